// round 2
// baseline (speedup 1.0000x reference)
#include <cuda_runtime.h>
#include <cuda_bf16.h>

#define T_OBS 16
#define T_PRED 25
#define NN 192
#define PP 36864
#define ENCH 64
#define EMBD 32
#define DECH 128
#define DYND 32
#define ENCD 176   // DYN + SOC

__device__ float g_Hn[(size_t)PP * ENCH];
__device__ float g_Hs[NN * ENCH];
__device__ float g_enc[NN * ENCD];

__device__ __forceinline__ float lrelu(float x) { return fmaxf(x, 0.1f * x); }
__device__ __forceinline__ float sigf(float x) { return __fdividef(1.f, 1.f + __expf(-x)); }
__device__ __forceinline__ float tanhf_(float x) { return __fdividef(2.f, 1.f + __expf(-2.f * x)) - 1.f; }

__device__ __forceinline__ unsigned long long pk2(float lo, float hi) {
    unsigned long long r;
    asm("mov.b64 %0,{%1,%2};" : "=l"(r) : "f"(lo), "f"(hi));
    return r;
}
__device__ __forceinline__ unsigned long long fma2(unsigned long long a, unsigned long long b,
                                                   unsigned long long c) {
    unsigned long long d;
    asm("fma.rn.f32x2 %0,%1,%2,%3;" : "=l"(d) : "l"(a), "l"(b), "l"(c));
    return d;
}
__device__ __forceinline__ float psum(unsigned long long v) {
    float a, b;
    asm("mov.b64 {%0,%1},%2;" : "=f"(a), "=f"(b) : "l"(v));
    return a + b;
}

// ============================================================================
// K1: encoder LSTMs. Blocks 0..143: neighbor rows (256/block). Block 144: ego.
// ============================================================================
#define K1_SMEM 230784

extern "C" __global__ void __launch_bounds__(256, 1)
k_encoder(const float* __restrict__ obs, const float* __restrict__ ngb,
          const float* __restrict__ Wip, const float* __restrict__ bip,
          const float* __restrict__ Wih, const float* __restrict__ Whh,
          const float* __restrict__ bih, const float* __restrict__ bhh) {
    extern __shared__ char smbase[];
    ulonglong2* WA = (ulonglong2*)smbase;                 // gates i,f  [48][64]
    ulonglong2* WB = WA + 48 * 64;                        // gates g,o
    float4* b4 = (float4*)(smbase + 98304);               // bias per unit
    float* wip_s = (float*)(smbase + 99328);
    float* bip_s = (float*)(smbase + 99584);
    float* htmp = (float*)(smbase + 99712);               // h [64][256]
    float* c_sh = (float*)(smbase + 165248);              // c [64][256]

    const int tid = threadIdx.x;

    // combined input vector k in [0,96): k<32 -> emb (Wih), k>=32 -> h (Whh)
    for (int idx = tid; idx < 48 * 64; idx += 256) {
        int kp = idx >> 6, j = idx & 63;
        int k0 = kp * 2;
        float v[8];
#pragma unroll
        for (int gg = 0; gg < 4; gg++) {
            int grow = j + gg * 64;
#pragma unroll
            for (int dk = 0; dk < 2; dk++) {
                int k = k0 + dk;
                v[gg * 2 + dk] = (k < EMBD) ? Wih[grow * EMBD + k] : Whh[grow * ENCH + (k - EMBD)];
            }
        }
        ulonglong2 a, b;
        a.x = pk2(v[0], v[1]); a.y = pk2(v[2], v[3]);
        b.x = pk2(v[4], v[5]); b.y = pk2(v[6], v[7]);
        WA[idx] = a;
        WB[idx] = b;
    }
    if (tid < 64) {
        b4[tid] = make_float4(bih[tid] + bhh[tid], bih[64 + tid] + bhh[64 + tid],
                              bih[128 + tid] + bhh[128 + tid], bih[192 + tid] + bhh[192 + tid]);
        wip_s[tid] = Wip[tid];
    }
    if (tid < 32) bip_s[tid] = bip[tid];
#pragma unroll 1
    for (int j = 0; j < 64; j++) {
        c_sh[j * 256 + tid] = 0.f;
        htmp[j * 256 + tid] = 0.f;
    }
    __syncthreads();

    const bool ego = (blockIdx.x == 144);
    const int nrows = ego ? NN : PP;
    const int row = ego ? tid : blockIdx.x * 256 + tid;
    const bool act = ego ? (tid < NN) : true;
    const float* src = ego ? obs : ngb;

    unsigned long long inp[48];
#pragma unroll
    for (int m = 0; m < 48; m++) inp[m] = 0ull;

#pragma unroll 1
    for (int t = 0; t < T_OBS; t++) {
        float x0 = 0.f, x1 = 0.f;
        if (act) {
            const float* p = src + ((size_t)t * nrows + row) * 2;
            x0 = p[0]; x1 = p[1];
        }
#pragma unroll
        for (int m = 0; m < 16; m++) {  // embedding
            float e0 = fmaf(wip_s[4 * m + 0], x0, fmaf(wip_s[4 * m + 1], x1, bip_s[2 * m]));
            float e1 = fmaf(wip_s[4 * m + 2], x0, fmaf(wip_s[4 * m + 3], x1, bip_s[2 * m + 1]));
            inp[m] = pk2(lrelu(e0), lrelu(e1));
        }
#pragma unroll 1
        for (int j = 0; j < 64; j++) {
            float4 bb = b4[j];
            unsigned long long ai = pk2(bb.x, 0.f), af = pk2(bb.y, 0.f);
            unsigned long long ag = pk2(bb.z, 0.f), ao = pk2(bb.w, 0.f);
#pragma unroll
            for (int kp = 0; kp < 48; kp++) {
                ulonglong2 wa = WA[kp * 64 + j];
                ulonglong2 wb = WB[kp * 64 + j];
                ai = fma2(wa.x, inp[kp], ai);
                af = fma2(wa.y, inp[kp], af);
                ag = fma2(wb.x, inp[kp], ag);
                ao = fma2(wb.y, inp[kp], ao);
            }
            float zi = psum(ai), zf = psum(af), zg = psum(ag), zo = psum(ao);
            float cold = c_sh[j * 256 + tid];
            float cn = sigf(zf) * cold + sigf(zi) * tanhf_(zg);
            c_sh[j * 256 + tid] = cn;
            htmp[j * 256 + tid] = sigf(zo) * tanhf_(cn);
        }
#pragma unroll
        for (int m = 0; m < 32; m++)  // repack h (same-thread smem, no sync needed)
            inp[16 + m] = pk2(htmp[(2 * m) * 256 + tid], htmp[(2 * m + 1) * 256 + tid]);
    }
    if (act) {
        float* dst = ego ? (g_Hs + row * ENCH) : (g_Hn + (size_t)row * ENCH);
#pragma unroll
        for (int j = 0; j < 64; j++) dst[j] = htmp[j * 256 + tid];
    }
}

// ============================================================================
// K2: per batch element b: gather -> conv1 -> conv2 -> maxpool + traj_enc
// ============================================================================
#define K2_SMEM (52736 * 4)

extern "C" __global__ void __launch_bounds__(256, 1)
k_social(const int* __restrict__ masks_idxs, const int* __restrict__ obs_traj_idxs,
         const float* __restrict__ Wdyn, const float* __restrict__ bdyn,
         const float* __restrict__ Wc1, const float* __restrict__ bc1,
         const float* __restrict__ Wc2, const float* __restrict__ bc2) {
    extern __shared__ float sm[];
    float* S = sm;            // [64 pos][64 ch]
    float* A = sm + 4096;     // [36 pos][64 ch]
    float* W1 = sm + 6400;    // [64 o][9 uv][64 i]
    float* W2 = sm + 43264;   // [16 o][9 uv][64 i]
    float* Bv = sm + 52480;   // [16 o][16 pos]
    const int b = blockIdx.x, tid = threadIdx.x;

    for (int idx = tid; idx < 36864; idx += 256) {
        int i = idx & 63, rest = idx >> 6, uv = rest % 9, o = rest / 9;
        W1[idx] = Wc1[(o * 64 + i) * 9 + uv];
    }
    for (int idx = tid; idx < 9216; idx += 256) {
        int i = idx & 63, rest = idx >> 6, uv = rest % 9, o = rest / 9;
        W2[idx] = Wc2[(o * 64 + i) * 9 + uv];
    }
    // S[(x*8+y)*64+i] = grid[b, h=y, w=x, ch=i]  (transpose (0,3,2,1) folded in)
    for (int idx = tid; idx < 4096; idx += 256) {
        int i = idx & 63, pos = idx >> 6, x = pos >> 3, y = pos & 7;
        int r = masks_idxs[b * 64 + y * 8 + x];
        S[idx] = g_Hn[(size_t)r * 64 + i];
    }
    __syncthreads();
    for (int idx = tid; idx < 2304; idx += 256) {  // conv1 -> [o][6][6]
        int o = idx / 36, p = idx - o * 36, x = p / 6, y = p - x * 6;
        float acc = bc1[o];
#pragma unroll
        for (int u = 0; u < 3; u++)
#pragma unroll
            for (int v = 0; v < 3; v++) {
                const float4* s4 = (const float4*)(S + ((x + u) * 8 + (y + v)) * 64);
                const float4* w4 = (const float4*)(W1 + (o * 9 + u * 3 + v) * 64);
#pragma unroll
                for (int q = 0; q < 16; q++) {
                    float4 sv = s4[q], wv = w4[q];
                    acc = fmaf(sv.x, wv.x, fmaf(sv.y, wv.y, fmaf(sv.z, wv.z, fmaf(sv.w, wv.w, acc))));
                }
            }
        A[p * 64 + o] = lrelu(acc);
    }
    __syncthreads();
    {   // conv2 -> [16 o][4][4], one task per thread
        int o = tid >> 4, p = tid & 15, x = p >> 2, y = p & 3;
        float acc = bc2[o];
#pragma unroll
        for (int u = 0; u < 3; u++)
#pragma unroll
            for (int v = 0; v < 3; v++) {
                const float4* a4 = (const float4*)(A + ((x + u) * 6 + (y + v)) * 64);
                const float4* w4 = (const float4*)(W2 + (o * 9 + u * 3 + v) * 64);
#pragma unroll
                for (int q = 0; q < 16; q++) {
                    float4 sv = a4[q], wv = w4[q];
                    acc = fmaf(sv.x, wv.x, fmaf(sv.y, wv.y, fmaf(sv.z, wv.z, fmaf(sv.w, wv.w, acc))));
                }
            }
        Bv[o * 16 + p] = lrelu(acc);
    }
    __syncthreads();
    if (tid < 144) {  // 2x2 maxpool stride 1 -> [16][3][3]
        int o = tid / 9, p = tid - o * 9, x = p / 3, y = p - x * 3;
        float m0 = fmaxf(Bv[o * 16 + x * 4 + y], Bv[o * 16 + x * 4 + y + 1]);
        float m1 = fmaxf(Bv[o * 16 + (x + 1) * 4 + y], Bv[o * 16 + (x + 1) * 4 + y + 1]);
        g_enc[b * ENCD + DYND + tid] = fmaxf(m0, m1);
    } else if (tid >= 160 && tid < 192) {  // traj_enc
        int d = tid - 160;
        int r = obs_traj_idxs[15 * NN + b];
        const float* hf = g_Hs + r * ENCH;
        float acc = bdyn[d];
#pragma unroll
        for (int k = 0; k < 64; k++) acc = fmaf(hf[k], Wdyn[d * 64 + k], acc);
        g_enc[b * ENCD + d] = lrelu(acc);
    }
}

// ============================================================================
// K3: decoder LSTM, 25 steps, 48 blocks x 4 rows; enc@Wih_d.T hoisted.
// ============================================================================
extern "C" __global__ void __launch_bounds__(256, 1)
k_decoder(const float* __restrict__ Wih_d, const float* __restrict__ Whh_d,
          const float* __restrict__ bih_d, const float* __restrict__ bhh_d,
          const float* __restrict__ Wop, const float* __restrict__ bop,
          float* __restrict__ out) {
    __shared__ __align__(16) float enc_s[4][ENCD];
    __shared__ __align__(16) float h_s[4][DECH];
    __shared__ __align__(16) float c_s[4][DECH];
    __shared__ __align__(16) float z_s[4][512];
    __shared__ float wop_s[5 * DECH];
    __shared__ float bop_s[8];
    const int tid = threadIdx.x;
    const int b0 = blockIdx.x * 4;

    for (int idx = tid; idx < 4 * ENCD; idx += 256)
        enc_s[idx / ENCD][idx % ENCD] = g_enc[b0 * ENCD + idx];
    for (int idx = tid; idx < 640; idx += 256) wop_s[idx] = Wop[idx];
    if (tid < 5) bop_s[tid] = bop[tid];
    for (int idx = tid; idx < 512; idx += 256) {
        h_s[idx >> 7][idx & 127] = 0.f;
        c_s[idx >> 7][idx & 127] = 0.f;
    }
    __syncthreads();

    float ez[8];
#pragma unroll
    for (int gg = 0; gg < 2; gg++) {
        int g = tid * 2 + gg;
        float bb = bih_d[g] + bhh_d[g];
        float a0 = bb, a1 = bb, a2 = bb, a3 = bb;
        for (int k = 0; k < ENCD; k++) {
            float w = Wih_d[g * ENCD + k];
            a0 = fmaf(w, enc_s[0][k], a0);
            a1 = fmaf(w, enc_s[1][k], a1);
            a2 = fmaf(w, enc_s[2][k], a2);
            a3 = fmaf(w, enc_s[3][k], a3);
        }
        ez[gg * 4 + 0] = a0; ez[gg * 4 + 1] = a1; ez[gg * 4 + 2] = a2; ez[gg * 4 + 3] = a3;
    }
    __syncthreads();

#pragma unroll 1
    for (int t = 0; t < T_PRED; t++) {
#pragma unroll
        for (int gg = 0; gg < 2; gg++) {
            int g = tid * 2 + gg;
            float a0 = ez[gg * 4], a1 = ez[gg * 4 + 1], a2 = ez[gg * 4 + 2], a3 = ez[gg * 4 + 3];
            const float4* wr = (const float4*)(Whh_d + g * DECH);
#pragma unroll
            for (int kq = 0; kq < 32; kq++) {
                float4 w = wr[kq];
                float4 h0 = ((const float4*)h_s[0])[kq];
                float4 h1 = ((const float4*)h_s[1])[kq];
                float4 h2 = ((const float4*)h_s[2])[kq];
                float4 h3 = ((const float4*)h_s[3])[kq];
                a0 = fmaf(w.x, h0.x, fmaf(w.y, h0.y, fmaf(w.z, h0.z, fmaf(w.w, h0.w, a0))));
                a1 = fmaf(w.x, h1.x, fmaf(w.y, h1.y, fmaf(w.z, h1.z, fmaf(w.w, h1.w, a1))));
                a2 = fmaf(w.x, h2.x, fmaf(w.y, h2.y, fmaf(w.z, h2.z, fmaf(w.w, h2.w, a2))));
                a3 = fmaf(w.x, h3.x, fmaf(w.y, h3.y, fmaf(w.z, h3.z, fmaf(w.w, h3.w, a3))));
            }
            z_s[0][g] = a0; z_s[1][g] = a1; z_s[2][g] = a2; z_s[3][g] = a3;
        }
        __syncthreads();
#pragma unroll
        for (int q = 0; q < 2; q++) {
            int task = tid + q * 256;
            int r = task >> 7, j = task & 127;
            float zi = z_s[r][j], zf = z_s[r][DECH + j];
            float zg = z_s[r][2 * DECH + j], zo = z_s[r][3 * DECH + j];
            float cn = sigf(zf) * c_s[r][j] + sigf(zi) * tanhf_(zg);
            c_s[r][j] = cn;
            h_s[r][j] = sigf(zo) * tanhf_(cn);
        }
        __syncthreads();
        if (tid < 20) {
            int r = tid / 5, oi = tid - r * 5;
            float acc = bop_s[oi];
#pragma unroll
            for (int k = 0; k < DECH; k++) acc = fmaf(h_s[r][k], wop_s[oi * DECH + k], acc);
            float val = (oi < 2) ? acc : ((oi < 4) ? __expf(acc) : tanhf_(acc));
            out[((size_t)t * NN + (b0 + r)) * 5 + oi] = val;
        }
        // next h_s write is fenced by next iteration's first __syncthreads
    }
}

extern "C" void kernel_launch(void* const* d_in, const int* in_sizes, int n_in,
                              void* d_out, int out_size) {
    const float* obs  = (const float*)d_in[0];
    const float* ngb  = (const float*)d_in[1];
    const int* masks_idxs    = (const int*)d_in[3];
    const int* obs_traj_idxs = (const int*)d_in[4];
    const float* Wip   = (const float*)d_in[7];
    const float* bip   = (const float*)d_in[8];
    const float* Wih_e = (const float*)d_in[9];
    const float* Whh_e = (const float*)d_in[10];
    const float* bih_e = (const float*)d_in[11];
    const float* bhh_e = (const float*)d_in[12];
    const float* Wdyn  = (const float*)d_in[13];
    const float* bdyn  = (const float*)d_in[14];
    const float* Wc1   = (const float*)d_in[15];
    const float* bc1   = (const float*)d_in[16];
    const float* Wc2   = (const float*)d_in[17];
    const float* bc2   = (const float*)d_in[18];
    const float* Wih_d = (const float*)d_in[19];
    const float* Whh_d = (const float*)d_in[20];
    const float* bih_d = (const float*)d_in[21];
    const float* bhh_d = (const float*)d_in[22];
    const float* Wop   = (const float*)d_in[23];
    const float* bop   = (const float*)d_in[24];

    cudaFuncSetAttribute(k_encoder, cudaFuncAttributeMaxDynamicSharedMemorySize, K1_SMEM);
    cudaFuncSetAttribute(k_social, cudaFuncAttributeMaxDynamicSharedMemorySize, K2_SMEM);

    k_encoder<<<145, 256, K1_SMEM>>>(obs, ngb, Wip, bip, Wih_e, Whh_e, bih_e, bhh_e);
    k_social<<<192, 256, K2_SMEM>>>(masks_idxs, obs_traj_idxs, Wdyn, bdyn, Wc1, bc1, Wc2, bc2);
    k_decoder<<<48, 256>>>(Wih_d, Whh_d, bih_d, bhh_d, Wop, bop, (float*)d_out);
}

// round 3
// speedup vs baseline: 2.0460x; 2.0460x over previous
#include <cuda_runtime.h>
#include <cuda_bf16.h>

#define T_OBS 16
#define T_PRED 25
#define NN 192
#define PP 36864
#define ENCH 64
#define DECH 128
#define DYND 32
#define ENCD 176   // DYN + SOC

typedef unsigned long long ull;

__device__ float g_Hn[(size_t)PP * ENCH];
__device__ float g_Hs[NN * ENCH];
__device__ float g_enc[NN * ENCD];

__device__ __forceinline__ float lrelu(float x) { return fmaxf(x, 0.1f * x); }
__device__ __forceinline__ float tanha(float x) {
    float y; asm("tanh.approx.f32 %0,%1;" : "=f"(y) : "f"(x)); return y;
}
__device__ __forceinline__ float sigf(float x) { return fmaf(tanha(0.5f * x), 0.5f, 0.5f); }

__device__ __forceinline__ ull pk2(float lo, float hi) {
    ull r; asm("mov.b64 %0,{%1,%2};" : "=l"(r) : "f"(lo), "f"(hi)); return r;
}
__device__ __forceinline__ ull fma2(ull a, ull b, ull c) {
    ull d; asm("fma.rn.f32x2 %0,%1,%2,%3;" : "=l"(d) : "l"(a), "l"(b), "l"(c)); return d;
}
__device__ __forceinline__ float psum(ull v) {
    float a, b; asm("mov.b64 {%0,%1},%2;" : "=f"(a), "=f"(b) : "l"(v)); return a + b;
}

// ============================================================================
// K1: encoder LSTMs, register-tiled. 290 blocks x 128 rows.
//  blocks 0..287: neighbor rows. 288/289: ego rows 0..127 / 128..191.
//  Thread (warp w, lane m): rows (w*2+i)*8..+7 (i=0,1), units 2m,2m+1.
//  Weights packed as f32x2 pairs, lane-contiguous (conflict-free LDS.128).
//  x/h inputs broadcast; h double-buffered; c in registers.
// ============================================================================
#define K1_SMEM 182912

#define GEMM_KP(xb, wb) do {                                                  \
    ulonglong2 x01 = *(const ulonglong2*)(xb);                                \
    ulonglong2 x23 = *(const ulonglong2*)((xb) + 2);                          \
    ulonglong2 x45 = *(const ulonglong2*)((xb) + 4);                          \
    ulonglong2 x67 = *(const ulonglong2*)((xb) + 6);                          \
    ulonglong2 w0 = (wb)[0];                                                  \
    ulonglong2 w1 = (wb)[32];                                                 \
    ull xs0 = x01.x, xs1 = x01.y, xs2 = x23.x, xs3 = x23.y;                   \
    ull xs4 = x45.x, xs5 = x45.y, xs6 = x67.x, xs7 = x67.y;                   \
    acc[0][0] = fma2(w0.x, xs0, acc[0][0]); acc[0][1] = fma2(w0.y, xs0, acc[0][1]); \
    acc[0][2] = fma2(w1.x, xs0, acc[0][2]); acc[0][3] = fma2(w1.y, xs0, acc[0][3]); \
    acc[1][0] = fma2(w0.x, xs1, acc[1][0]); acc[1][1] = fma2(w0.y, xs1, acc[1][1]); \
    acc[1][2] = fma2(w1.x, xs1, acc[1][2]); acc[1][3] = fma2(w1.y, xs1, acc[1][3]); \
    acc[2][0] = fma2(w0.x, xs2, acc[2][0]); acc[2][1] = fma2(w0.y, xs2, acc[2][1]); \
    acc[2][2] = fma2(w1.x, xs2, acc[2][2]); acc[2][3] = fma2(w1.y, xs2, acc[2][3]); \
    acc[3][0] = fma2(w0.x, xs3, acc[3][0]); acc[3][1] = fma2(w0.y, xs3, acc[3][1]); \
    acc[3][2] = fma2(w1.x, xs3, acc[3][2]); acc[3][3] = fma2(w1.y, xs3, acc[3][3]); \
    acc[4][0] = fma2(w0.x, xs4, acc[4][0]); acc[4][1] = fma2(w0.y, xs4, acc[4][1]); \
    acc[4][2] = fma2(w1.x, xs4, acc[4][2]); acc[4][3] = fma2(w1.y, xs4, acc[4][3]); \
    acc[5][0] = fma2(w0.x, xs5, acc[5][0]); acc[5][1] = fma2(w0.y, xs5, acc[5][1]); \
    acc[5][2] = fma2(w1.x, xs5, acc[5][2]); acc[5][3] = fma2(w1.y, xs5, acc[5][3]); \
    acc[6][0] = fma2(w0.x, xs6, acc[6][0]); acc[6][1] = fma2(w0.y, xs6, acc[6][1]); \
    acc[6][2] = fma2(w1.x, xs6, acc[6][2]); acc[6][3] = fma2(w1.y, xs6, acc[6][3]); \
    acc[7][0] = fma2(w0.x, xs7, acc[7][0]); acc[7][1] = fma2(w0.y, xs7, acc[7][1]); \
    acc[7][2] = fma2(w1.x, xs7, acc[7][2]); acc[7][3] = fma2(w1.y, xs7, acc[7][3]); \
} while (0)

extern "C" __global__ void __launch_bounds__(256, 1)
k_encoder(const float* __restrict__ obs, const float* __restrict__ ngb,
          const float* __restrict__ Wip, const float* __restrict__ bip,
          const float* __restrict__ Wih, const float* __restrict__ Whh,
          const float* __restrict__ bih, const float* __restrict__ bhh) {
    extern __shared__ char smb[];
    ulonglong2* WL = (ulonglong2*)smb;                // [48 kp][2 su][2 half][32 m]
    float4* b4 = (float4*)(smb + 98304);              // [64 units] (i,f,g,o)
    float* wip_s = (float*)(smb + 99328);             // [64]
    float* bip_s = (float*)(smb + 99584);             // [32]
    ull* Xemb = (ull*)(smb + 99712);                  // [16 kp][130]
    ull* Hbuf = Xemb + 16 * 130;                      // [2][32 kp][130]

    const int tid = threadIdx.x;
    const int m = tid & 31, wid = tid >> 5;

    // stage packed weights: WL[((kp*2+su)*2+half)*32+m]
    for (int idx = tid; idx < 6144; idx += 256) {
        int mm = idx & 31, half = (idx >> 5) & 1, su = (idx >> 6) & 1, kp = idx >> 7;
        int u = 2 * mm + su, k0 = 2 * kp;
        float v[4];
#pragma unroll
        for (int q = 0; q < 4; q++) {
            int g = 2 * half + (q >> 1);
            int k = k0 + (q & 1);
            int grow = g * 64 + u;
            v[q] = (k < 32) ? Wih[grow * 32 + k] : Whh[grow * 64 + (k - 32)];
        }
        ulonglong2 e; e.x = pk2(v[0], v[1]); e.y = pk2(v[2], v[3]);
        WL[idx] = e;
    }
    if (tid < 64) {
        b4[tid] = make_float4(bih[tid] + bhh[tid], bih[64 + tid] + bhh[64 + tid],
                              bih[128 + tid] + bhh[128 + tid], bih[192 + tid] + bhh[192 + tid]);
        wip_s[tid] = Wip[tid];
    }
    if (tid < 32) bip_s[tid] = bip[tid];
    for (int idx = tid; idx < 4160; idx += 256) Hbuf[idx] = 0ull;  // zero h buffer 0
    __syncthreads();

    const int bx = blockIdx.x;
    const bool ego = (bx >= 288);
    const int row0 = ego ? (bx - 288) * 128 : bx * 128;
    const int nr = ego ? NN : PP;
    const float* src = ego ? obs : ngb;

    float creg[32];
#pragma unroll
    for (int q = 0; q < 32; q++) creg[q] = 0.f;

    int p = 0;
#pragma unroll 1
    for (int t = 0; t < T_OBS; t++) {
        if (tid < 128) {  // embedding for this block's 128 rows
            int row = row0 + tid;
            float x0 = 0.f, x1 = 0.f;
            if (row < nr) {
                const float* px = src + ((size_t)t * nr + row) * 2;
                x0 = px[0]; x1 = px[1];
            }
#pragma unroll
            for (int mm = 0; mm < 16; mm++) {
                float e0 = fmaf(wip_s[4 * mm + 0], x0, fmaf(wip_s[4 * mm + 1], x1, bip_s[2 * mm + 0]));
                float e1 = fmaf(wip_s[4 * mm + 2], x0, fmaf(wip_s[4 * mm + 3], x1, bip_s[2 * mm + 1]));
                Xemb[mm * 130 + tid] = pk2(lrelu(e0), lrelu(e1));
            }
        }
        __syncthreads();
        const ull* Hr = Hbuf + p * 4160;
        ull* Hw = Hbuf + (p ^ 1) * 4160;
#pragma unroll
        for (int i = 0; i < 2; i++) {
            const int r0 = (wid * 2 + i) * 8;
            float hlo[8];
#pragma unroll
            for (int su = 0; su < 2; su++) {
                ull acc[8][4];
#pragma unroll
                for (int rr = 0; rr < 8; rr++)
#pragma unroll
                    for (int q = 0; q < 4; q++) acc[rr][q] = 0ull;
#pragma unroll 8
                for (int kp = 0; kp < 16; kp++) {  // embedding part
                    const ull* xb = Xemb + kp * 130 + r0;
                    const ulonglong2* wb = WL + (kp * 2 + su) * 64 + m;
                    GEMM_KP(xb, wb);
                }
#pragma unroll 8
                for (int kp = 0; kp < 32; kp++) {  // recurrent part
                    const ull* xb = Hr + kp * 130 + r0;
                    const ulonglong2* wb = WL + ((kp + 16) * 2 + su) * 64 + m;
                    GEMM_KP(xb, wb);
                }
                float4 bb = b4[2 * m + su];
#pragma unroll
                for (int rr = 0; rr < 8; rr++) {
                    float zi = psum(acc[rr][0]) + bb.x;
                    float zf = psum(acc[rr][1]) + bb.y;
                    float zg = psum(acc[rr][2]) + bb.z;
                    float zo = psum(acc[rr][3]) + bb.w;
                    int ci = (i * 2 + su) * 8 + rr;
                    float cn = fmaf(sigf(zf), creg[ci], sigf(zi) * tanha(zg));
                    creg[ci] = cn;
                    float h = sigf(zo) * tanha(cn);
                    if (su == 0) hlo[rr] = h;
                    else Hw[m * 130 + r0 + rr] = pk2(hlo[rr], h);
                }
            }
        }
        __syncthreads();
        p ^= 1;
    }
    // store final h (coalesced: lanes sweep unit-pairs)
    {
        const ull* Hf = Hbuf + p * 4160;
        ull* gH = ego ? (ull*)g_Hs : (ull*)g_Hn;
        for (int idx = tid; idx < 4096; idx += 256) {
            int mm = idx & 31, r = idx >> 5;
            int row = row0 + r;
            if (row < nr) gH[(size_t)row * 32 + mm] = Hf[mm * 130 + r];
        }
    }
}

// ============================================================================
// K2: per batch element b: gather -> conv1 -> conv2 -> maxpool + traj_enc
// ============================================================================
#define K2_SMEM (52736 * 4)

extern "C" __global__ void __launch_bounds__(256, 1)
k_social(const int* __restrict__ masks_idxs, const int* __restrict__ obs_traj_idxs,
         const float* __restrict__ Wdyn, const float* __restrict__ bdyn,
         const float* __restrict__ Wc1, const float* __restrict__ bc1,
         const float* __restrict__ Wc2, const float* __restrict__ bc2) {
    extern __shared__ float sm[];
    float* S = sm;            // [64 pos][64 ch]
    float* A = sm + 4096;     // [36 pos][64 ch]
    float* W1 = sm + 6400;    // [64 o][9 uv][64 i]
    float* W2 = sm + 43264;   // [16 o][9 uv][64 i]
    float* Bv = sm + 52480;   // [16 o][16 pos]
    const int b = blockIdx.x, tid = threadIdx.x;

    for (int idx = tid; idx < 36864; idx += 256) {
        int i = idx & 63, rest = idx >> 6, uv = rest % 9, o = rest / 9;
        W1[idx] = Wc1[(o * 64 + i) * 9 + uv];
    }
    for (int idx = tid; idx < 9216; idx += 256) {
        int i = idx & 63, rest = idx >> 6, uv = rest % 9, o = rest / 9;
        W2[idx] = Wc2[(o * 64 + i) * 9 + uv];
    }
    for (int idx = tid; idx < 4096; idx += 256) {
        int i = idx & 63, pos = idx >> 6, x = pos >> 3, y = pos & 7;
        int r = masks_idxs[b * 64 + y * 8 + x];
        S[idx] = g_Hn[(size_t)r * 64 + i];
    }
    __syncthreads();
    for (int idx = tid; idx < 2304; idx += 256) {  // conv1 -> [o][6][6]
        int o = idx / 36, p = idx - o * 36, x = p / 6, y = p - x * 6;
        float acc = bc1[o];
#pragma unroll
        for (int u = 0; u < 3; u++)
#pragma unroll
            for (int v = 0; v < 3; v++) {
                const float4* s4 = (const float4*)(S + ((x + u) * 8 + (y + v)) * 64);
                const float4* w4 = (const float4*)(W1 + (o * 9 + u * 3 + v) * 64);
#pragma unroll
                for (int q = 0; q < 16; q++) {
                    float4 sv = s4[q], wv = w4[q];
                    acc = fmaf(sv.x, wv.x, fmaf(sv.y, wv.y, fmaf(sv.z, wv.z, fmaf(sv.w, wv.w, acc))));
                }
            }
        A[p * 64 + o] = lrelu(acc);
    }
    __syncthreads();
    {   // conv2 -> [16 o][4][4]
        int o = tid >> 4, p = tid & 15, x = p >> 2, y = p & 3;
        float acc = bc2[o];
#pragma unroll
        for (int u = 0; u < 3; u++)
#pragma unroll
            for (int v = 0; v < 3; v++) {
                const float4* a4 = (const float4*)(A + ((x + u) * 6 + (y + v)) * 64);
                const float4* w4 = (const float4*)(W2 + (o * 9 + u * 3 + v) * 64);
#pragma unroll
                for (int q = 0; q < 16; q++) {
                    float4 sv = a4[q], wv = w4[q];
                    acc = fmaf(sv.x, wv.x, fmaf(sv.y, wv.y, fmaf(sv.z, wv.z, fmaf(sv.w, wv.w, acc))));
                }
            }
        Bv[o * 16 + p] = lrelu(acc);
    }
    __syncthreads();
    if (tid < 144) {  // 2x2 maxpool stride 1 -> [16][3][3]
        int o = tid / 9, p = tid - o * 9, x = p / 3, y = p - x * 3;
        float m0 = fmaxf(Bv[o * 16 + x * 4 + y], Bv[o * 16 + x * 4 + y + 1]);
        float m1 = fmaxf(Bv[o * 16 + (x + 1) * 4 + y], Bv[o * 16 + (x + 1) * 4 + y + 1]);
        g_enc[b * ENCD + DYND + tid] = fmaxf(m0, m1);
    } else if (tid >= 160 && tid < 192) {  // traj_enc
        int d = tid - 160;
        int r = obs_traj_idxs[15 * NN + b];
        const float* hf = g_Hs + r * ENCH;
        float acc = bdyn[d];
#pragma unroll
        for (int k = 0; k < 64; k++) acc = fmaf(hf[k], Wdyn[d * 64 + k], acc);
        g_enc[b * ENCD + d] = lrelu(acc);
    }
}

// ============================================================================
// K3: decoder LSTM, 25 steps, 48 blocks x 4 rows; packed f32x2 inner loop.
// ============================================================================
extern "C" __global__ void __launch_bounds__(256, 1)
k_decoder(const float* __restrict__ Wih_d, const float* __restrict__ Whh_d,
          const float* __restrict__ bih_d, const float* __restrict__ bhh_d,
          const float* __restrict__ Wop, const float* __restrict__ bop,
          float* __restrict__ out) {
    __shared__ __align__(16) float enc_s[4][ENCD];
    __shared__ __align__(16) float h_s[4][DECH];
    __shared__ __align__(16) float c_s[4][DECH];
    __shared__ __align__(16) float z_s[4][512];
    __shared__ float wop_s[5 * DECH];
    __shared__ float bop_s[8];
    const int tid = threadIdx.x;
    const int b0 = blockIdx.x * 4;

    for (int idx = tid; idx < 4 * ENCD; idx += 256)
        enc_s[idx / ENCD][idx % ENCD] = g_enc[b0 * ENCD + idx];
    for (int idx = tid; idx < 640; idx += 256) wop_s[idx] = Wop[idx];
    if (tid < 5) bop_s[tid] = bop[tid];
    for (int idx = tid; idx < 512; idx += 256) {
        h_s[idx >> 7][idx & 127] = 0.f;
        c_s[idx >> 7][idx & 127] = 0.f;
    }
    __syncthreads();

    float ez[8];
#pragma unroll
    for (int gg = 0; gg < 2; gg++) {
        int g = tid * 2 + gg;
        float bb = bih_d[g] + bhh_d[g];
        float a0 = bb, a1 = bb, a2 = bb, a3 = bb;
        for (int k = 0; k < ENCD; k++) {
            float w = Wih_d[g * ENCD + k];
            a0 = fmaf(w, enc_s[0][k], a0);
            a1 = fmaf(w, enc_s[1][k], a1);
            a2 = fmaf(w, enc_s[2][k], a2);
            a3 = fmaf(w, enc_s[3][k], a3);
        }
        ez[gg * 4 + 0] = a0; ez[gg * 4 + 1] = a1; ez[gg * 4 + 2] = a2; ez[gg * 4 + 3] = a3;
    }
    __syncthreads();

#pragma unroll 1
    for (int t = 0; t < T_PRED; t++) {
#pragma unroll
        for (int gg = 0; gg < 2; gg++) {
            int g = tid * 2 + gg;
            ull a0 = pk2(ez[gg * 4 + 0], 0.f), a1 = pk2(ez[gg * 4 + 1], 0.f);
            ull a2 = pk2(ez[gg * 4 + 2], 0.f), a3 = pk2(ez[gg * 4 + 3], 0.f);
            const ulonglong2* wr = (const ulonglong2*)(Whh_d + g * DECH);
            const ulonglong2* h0p = (const ulonglong2*)h_s[0];
            const ulonglong2* h1p = (const ulonglong2*)h_s[1];
            const ulonglong2* h2p = (const ulonglong2*)h_s[2];
            const ulonglong2* h3p = (const ulonglong2*)h_s[3];
#pragma unroll
            for (int kq = 0; kq < 32; kq++) {
                ulonglong2 w = wr[kq];
                ulonglong2 q0 = h0p[kq], q1 = h1p[kq], q2 = h2p[kq], q3 = h3p[kq];
                a0 = fma2(w.x, q0.x, a0); a0 = fma2(w.y, q0.y, a0);
                a1 = fma2(w.x, q1.x, a1); a1 = fma2(w.y, q1.y, a1);
                a2 = fma2(w.x, q2.x, a2); a2 = fma2(w.y, q2.y, a2);
                a3 = fma2(w.x, q3.x, a3); a3 = fma2(w.y, q3.y, a3);
            }
            z_s[0][g] = psum(a0); z_s[1][g] = psum(a1);
            z_s[2][g] = psum(a2); z_s[3][g] = psum(a3);
        }
        __syncthreads();
#pragma unroll
        for (int q = 0; q < 2; q++) {
            int task = tid + q * 256;
            int r = task >> 7, j = task & 127;
            float zi = z_s[r][j], zf = z_s[r][DECH + j];
            float zg = z_s[r][2 * DECH + j], zo = z_s[r][3 * DECH + j];
            float cn = fmaf(sigf(zf), c_s[r][j], sigf(zi) * tanha(zg));
            c_s[r][j] = cn;
            h_s[r][j] = sigf(zo) * tanha(cn);
        }
        __syncthreads();
        if (tid < 20) {
            int r = tid / 5, oi = tid - r * 5;
            float acc = bop_s[oi];
#pragma unroll
            for (int k = 0; k < DECH; k++) acc = fmaf(h_s[r][k], wop_s[oi * DECH + k], acc);
            float val = (oi < 2) ? acc : ((oi < 4) ? __expf(acc) : tanha(acc));
            out[((size_t)t * NN + (b0 + r)) * 5 + oi] = val;
        }
    }
}

extern "C" void kernel_launch(void* const* d_in, const int* in_sizes, int n_in,
                              void* d_out, int out_size) {
    const float* obs  = (const float*)d_in[0];
    const float* ngb  = (const float*)d_in[1];
    const int* masks_idxs    = (const int*)d_in[3];
    const int* obs_traj_idxs = (const int*)d_in[4];
    const float* Wip   = (const float*)d_in[7];
    const float* bip   = (const float*)d_in[8];
    const float* Wih_e = (const float*)d_in[9];
    const float* Whh_e = (const float*)d_in[10];
    const float* bih_e = (const float*)d_in[11];
    const float* bhh_e = (const float*)d_in[12];
    const float* Wdyn  = (const float*)d_in[13];
    const float* bdyn  = (const float*)d_in[14];
    const float* Wc1   = (const float*)d_in[15];
    const float* bc1   = (const float*)d_in[16];
    const float* Wc2   = (const float*)d_in[17];
    const float* bc2   = (const float*)d_in[18];
    const float* Wih_d = (const float*)d_in[19];
    const float* Whh_d = (const float*)d_in[20];
    const float* bih_d = (const float*)d_in[21];
    const float* bhh_d = (const float*)d_in[22];
    const float* Wop   = (const float*)d_in[23];
    const float* bop   = (const float*)d_in[24];

    cudaFuncSetAttribute(k_encoder, cudaFuncAttributeMaxDynamicSharedMemorySize, K1_SMEM);
    cudaFuncSetAttribute(k_social, cudaFuncAttributeMaxDynamicSharedMemorySize, K2_SMEM);

    k_encoder<<<290, 256, K1_SMEM>>>(obs, ngb, Wip, bip, Wih_e, Whh_e, bih_e, bhh_e);
    k_social<<<192, 256, K2_SMEM>>>(masks_idxs, obs_traj_idxs, Wdyn, bdyn, Wc1, bc1, Wc2, bc2);
    k_decoder<<<48, 256>>>(Wih_d, Whh_d, bih_d, bhh_d, Wop, bop, (float*)d_out);
}

// round 4
// speedup vs baseline: 2.6511x; 1.2958x over previous
#include <cuda_runtime.h>
#include <cuda_bf16.h>

#define T_OBS 16
#define T_PRED 25
#define NN 192
#define PP 36864
#define ENCH 64
#define DECH 128
#define DYND 32
#define ENCD 176   // DYN + SOC

typedef unsigned long long ull;

__device__ float g_Hn[(size_t)PP * ENCH];
__device__ float g_Hs[NN * ENCH];
__device__ float g_enc[NN * ENCD];

__device__ __forceinline__ float lrelu(float x) { return fmaxf(x, 0.1f * x); }
__device__ __forceinline__ float tanha(float x) {
    float y; asm("tanh.approx.f32 %0,%1;" : "=f"(y) : "f"(x)); return y;
}
__device__ __forceinline__ float sigf(float x) { return fmaf(tanha(0.5f * x), 0.5f, 0.5f); }

__device__ __forceinline__ ull pk2(float lo, float hi) {
    ull r; asm("mov.b64 %0,{%1,%2};" : "=l"(r) : "f"(lo), "f"(hi)); return r;
}
__device__ __forceinline__ ull fma2(ull a, ull b, ull c) {
    ull d; asm("fma.rn.f32x2 %0,%1,%2,%3;" : "=l"(d) : "l"(a), "l"(b), "l"(c)); return d;
}
__device__ __forceinline__ float psum(ull v) {
    float a, b; asm("mov.b64 {%0,%1},%2;" : "=f"(a), "=f"(b) : "l"(v)); return a + b;
}

// ============================================================================
// K1: encoder LSTMs, register-tiled (UNCHANGED from R3 — known good 606us).
// ============================================================================
#define K1_SMEM 182912

#define GEMM_KP(xb, wb) do {                                                  \
    ulonglong2 x01 = *(const ulonglong2*)(xb);                                \
    ulonglong2 x23 = *(const ulonglong2*)((xb) + 2);                          \
    ulonglong2 x45 = *(const ulonglong2*)((xb) + 4);                          \
    ulonglong2 x67 = *(const ulonglong2*)((xb) + 6);                          \
    ulonglong2 w0 = (wb)[0];                                                  \
    ulonglong2 w1 = (wb)[32];                                                 \
    ull xs0 = x01.x, xs1 = x01.y, xs2 = x23.x, xs3 = x23.y;                   \
    ull xs4 = x45.x, xs5 = x45.y, xs6 = x67.x, xs7 = x67.y;                   \
    acc[0][0] = fma2(w0.x, xs0, acc[0][0]); acc[0][1] = fma2(w0.y, xs0, acc[0][1]); \
    acc[0][2] = fma2(w1.x, xs0, acc[0][2]); acc[0][3] = fma2(w1.y, xs0, acc[0][3]); \
    acc[1][0] = fma2(w0.x, xs1, acc[1][0]); acc[1][1] = fma2(w0.y, xs1, acc[1][1]); \
    acc[1][2] = fma2(w1.x, xs1, acc[1][2]); acc[1][3] = fma2(w1.y, xs1, acc[1][3]); \
    acc[2][0] = fma2(w0.x, xs2, acc[2][0]); acc[2][1] = fma2(w0.y, xs2, acc[2][1]); \
    acc[2][2] = fma2(w1.x, xs2, acc[2][2]); acc[2][3] = fma2(w1.y, xs2, acc[2][3]); \
    acc[3][0] = fma2(w0.x, xs3, acc[3][0]); acc[3][1] = fma2(w0.y, xs3, acc[3][1]); \
    acc[3][2] = fma2(w1.x, xs3, acc[3][2]); acc[3][3] = fma2(w1.y, xs3, acc[3][3]); \
    acc[4][0] = fma2(w0.x, xs4, acc[4][0]); acc[4][1] = fma2(w0.y, xs4, acc[4][1]); \
    acc[4][2] = fma2(w1.x, xs4, acc[4][2]); acc[4][3] = fma2(w1.y, xs4, acc[4][3]); \
    acc[5][0] = fma2(w0.x, xs5, acc[5][0]); acc[5][1] = fma2(w0.y, xs5, acc[5][1]); \
    acc[5][2] = fma2(w1.x, xs5, acc[5][2]); acc[5][3] = fma2(w1.y, xs5, acc[5][3]); \
    acc[6][0] = fma2(w0.x, xs6, acc[6][0]); acc[6][1] = fma2(w0.y, xs6, acc[6][1]); \
    acc[6][2] = fma2(w1.x, xs6, acc[6][2]); acc[6][3] = fma2(w1.y, xs6, acc[6][3]); \
    acc[7][0] = fma2(w0.x, xs7, acc[7][0]); acc[7][1] = fma2(w0.y, xs7, acc[7][1]); \
    acc[7][2] = fma2(w1.x, xs7, acc[7][2]); acc[7][3] = fma2(w1.y, xs7, acc[7][3]); \
} while (0)

extern "C" __global__ void __launch_bounds__(256, 1)
k_encoder(const float* __restrict__ obs, const float* __restrict__ ngb,
          const float* __restrict__ Wip, const float* __restrict__ bip,
          const float* __restrict__ Wih, const float* __restrict__ Whh,
          const float* __restrict__ bih, const float* __restrict__ bhh) {
    extern __shared__ char smb[];
    ulonglong2* WL = (ulonglong2*)smb;                // [48 kp][2 su][2 half][32 m]
    float4* b4 = (float4*)(smb + 98304);
    float* wip_s = (float*)(smb + 99328);
    float* bip_s = (float*)(smb + 99584);
    ull* Xemb = (ull*)(smb + 99712);                  // [16 kp][130]
    ull* Hbuf = Xemb + 16 * 130;                      // [2][32 kp][130]

    const int tid = threadIdx.x;
    const int m = tid & 31, wid = tid >> 5;

    for (int idx = tid; idx < 6144; idx += 256) {
        int mm = idx & 31, half = (idx >> 5) & 1, su = (idx >> 6) & 1, kp = idx >> 7;
        int u = 2 * mm + su, k0 = 2 * kp;
        float v[4];
#pragma unroll
        for (int q = 0; q < 4; q++) {
            int g = 2 * half + (q >> 1);
            int k = k0 + (q & 1);
            int grow = g * 64 + u;
            v[q] = (k < 32) ? Wih[grow * 32 + k] : Whh[grow * 64 + (k - 32)];
        }
        ulonglong2 e; e.x = pk2(v[0], v[1]); e.y = pk2(v[2], v[3]);
        WL[idx] = e;
    }
    if (tid < 64) {
        b4[tid] = make_float4(bih[tid] + bhh[tid], bih[64 + tid] + bhh[64 + tid],
                              bih[128 + tid] + bhh[128 + tid], bih[192 + tid] + bhh[192 + tid]);
        wip_s[tid] = Wip[tid];
    }
    if (tid < 32) bip_s[tid] = bip[tid];
    for (int idx = tid; idx < 4160; idx += 256) Hbuf[idx] = 0ull;
    __syncthreads();

    const int bx = blockIdx.x;
    const bool ego = (bx >= 288);
    const int row0 = ego ? (bx - 288) * 128 : bx * 128;
    const int nr = ego ? NN : PP;
    const float* src = ego ? obs : ngb;

    float creg[32];
#pragma unroll
    for (int q = 0; q < 32; q++) creg[q] = 0.f;

    int p = 0;
#pragma unroll 1
    for (int t = 0; t < T_OBS; t++) {
        if (tid < 128) {
            int row = row0 + tid;
            float x0 = 0.f, x1 = 0.f;
            if (row < nr) {
                const float* px = src + ((size_t)t * nr + row) * 2;
                x0 = px[0]; x1 = px[1];
            }
#pragma unroll
            for (int mm = 0; mm < 16; mm++) {
                float e0 = fmaf(wip_s[4 * mm + 0], x0, fmaf(wip_s[4 * mm + 1], x1, bip_s[2 * mm + 0]));
                float e1 = fmaf(wip_s[4 * mm + 2], x0, fmaf(wip_s[4 * mm + 3], x1, bip_s[2 * mm + 1]));
                Xemb[mm * 130 + tid] = pk2(lrelu(e0), lrelu(e1));
            }
        }
        __syncthreads();
        const ull* Hr = Hbuf + p * 4160;
        ull* Hw = Hbuf + (p ^ 1) * 4160;
#pragma unroll
        for (int i = 0; i < 2; i++) {
            const int r0 = (wid * 2 + i) * 8;
            float hlo[8];
#pragma unroll
            for (int su = 0; su < 2; su++) {
                ull acc[8][4];
#pragma unroll
                for (int rr = 0; rr < 8; rr++)
#pragma unroll
                    for (int q = 0; q < 4; q++) acc[rr][q] = 0ull;
#pragma unroll 8
                for (int kp = 0; kp < 16; kp++) {
                    const ull* xb = Xemb + kp * 130 + r0;
                    const ulonglong2* wb = WL + (kp * 2 + su) * 64 + m;
                    GEMM_KP(xb, wb);
                }
#pragma unroll 8
                for (int kp = 0; kp < 32; kp++) {
                    const ull* xb = Hr + kp * 130 + r0;
                    const ulonglong2* wb = WL + ((kp + 16) * 2 + su) * 64 + m;
                    GEMM_KP(xb, wb);
                }
                float4 bb = b4[2 * m + su];
#pragma unroll
                for (int rr = 0; rr < 8; rr++) {
                    float zi = psum(acc[rr][0]) + bb.x;
                    float zf = psum(acc[rr][1]) + bb.y;
                    float zg = psum(acc[rr][2]) + bb.z;
                    float zo = psum(acc[rr][3]) + bb.w;
                    int ci = (i * 2 + su) * 8 + rr;
                    float cn = fmaf(sigf(zf), creg[ci], sigf(zi) * tanha(zg));
                    creg[ci] = cn;
                    float h = sigf(zo) * tanha(cn);
                    if (su == 0) hlo[rr] = h;
                    else Hw[m * 130 + r0 + rr] = pk2(hlo[rr], h);
                }
            }
        }
        __syncthreads();
        p ^= 1;
    }
    {
        const ull* Hf = Hbuf + p * 4160;
        ull* gH = ego ? (ull*)g_Hs : (ull*)g_Hn;
        for (int idx = tid; idx < 4096; idx += 256) {
            int mm = idx & 31, r = idx >> 5;
            int row = row0 + r;
            if (row < nr) gH[(size_t)row * 32 + mm] = Hf[mm * 130 + r];
        }
    }
}

// ============================================================================
// K2: social pipeline. REWORKED: row stride 68 (bank-conflict-free LDS.128),
// coalesced weight staging (linear gmem reads, smem scatter writes).
// smem floats: S 64*68=4352 | A 36*68=2448 | W1 36864 | W2 9216 | Bv 256
// ============================================================================
#define SROW 68
#define K2_SMEM (53136 * 4)

extern "C" __global__ void __launch_bounds__(256, 1)
k_social(const int* __restrict__ masks_idxs, const int* __restrict__ obs_traj_idxs,
         const float* __restrict__ Wdyn, const float* __restrict__ bdyn,
         const float* __restrict__ Wc1, const float* __restrict__ bc1,
         const float* __restrict__ Wc2, const float* __restrict__ bc2) {
    extern __shared__ float sm[];
    float* S = sm;             // [64 pos][68]
    float* A = sm + 4352;      // [36 pos][68]
    float* W1 = sm + 6800;     // [64 o][9 uv][64 i]
    float* W2 = sm + 43664;    // [16 o][9 uv][64 i]
    float* Bv = sm + 52880;    // [16 o][16 pos]
    const int b = blockIdx.x, tid = threadIdx.x;

    // coalesced gmem reads, scattered smem writes
    for (int g = tid; g < 36864; g += 256) {
        int o = g / 576, r = g - o * 576, i = r / 9, uv = r - i * 9;
        W1[(o * 9 + uv) * 64 + i] = Wc1[g];
    }
    for (int g = tid; g < 9216; g += 256) {
        int o = g / 576, r = g - o * 576, i = r / 9, uv = r - i * 9;
        W2[(o * 9 + uv) * 64 + i] = Wc2[g];
    }
    // S[(x*8+y)*SROW+i] = grid[b, h=y, w=x, ch=i]
    for (int idx = tid; idx < 4096; idx += 256) {
        int i = idx & 63, pos = idx >> 6, x = pos >> 3, y = pos & 7;
        int r = masks_idxs[b * 64 + y * 8 + x];
        S[pos * SROW + i] = g_Hn[(size_t)r * 64 + i];
    }
    __syncthreads();
    for (int idx = tid; idx < 2304; idx += 256) {  // conv1 -> [o][6][6]
        int o = idx / 36, p = idx - o * 36, x = p / 6, y = p - x * 6;
        float acc = bc1[o];
#pragma unroll
        for (int u = 0; u < 3; u++)
#pragma unroll
            for (int v = 0; v < 3; v++) {
                const float4* s4 = (const float4*)(S + ((x + u) * 8 + (y + v)) * SROW);
                const float4* w4 = (const float4*)(W1 + (o * 9 + u * 3 + v) * 64);
#pragma unroll
                for (int q = 0; q < 16; q++) {
                    float4 sv = s4[q], wv = w4[q];
                    acc = fmaf(sv.x, wv.x, fmaf(sv.y, wv.y, fmaf(sv.z, wv.z, fmaf(sv.w, wv.w, acc))));
                }
            }
        A[p * SROW + o] = lrelu(acc);
    }
    __syncthreads();
    {   // conv2 -> [16 o][4][4]
        int o = tid >> 4, p = tid & 15, x = p >> 2, y = p & 3;
        float acc = bc2[o];
#pragma unroll
        for (int u = 0; u < 3; u++)
#pragma unroll
            for (int v = 0; v < 3; v++) {
                const float4* a4 = (const float4*)(A + ((x + u) * 6 + (y + v)) * SROW);
                const float4* w4 = (const float4*)(W2 + (o * 9 + u * 3 + v) * 64);
#pragma unroll
                for (int q = 0; q < 16; q++) {
                    float4 sv = a4[q], wv = w4[q];
                    acc = fmaf(sv.x, wv.x, fmaf(sv.y, wv.y, fmaf(sv.z, wv.z, fmaf(sv.w, wv.w, acc))));
                }
            }
        Bv[o * 16 + p] = lrelu(acc);
    }
    __syncthreads();
    if (tid < 144) {  // 2x2 maxpool stride 1 -> [16][3][3]
        int o = tid / 9, p = tid - o * 9, x = p / 3, y = p - x * 3;
        float m0 = fmaxf(Bv[o * 16 + x * 4 + y], Bv[o * 16 + x * 4 + y + 1]);
        float m1 = fmaxf(Bv[o * 16 + (x + 1) * 4 + y], Bv[o * 16 + (x + 1) * 4 + y + 1]);
        g_enc[b * ENCD + DYND + tid] = fmaxf(m0, m1);
    } else if (tid >= 160 && tid < 192) {  // traj_enc
        int d = tid - 160;
        int r = obs_traj_idxs[15 * NN + b];
        const float* hf = g_Hs + r * ENCH;
        float acc = bdyn[d];
#pragma unroll
        for (int k = 0; k < 64; k++) acc = fmaf(hf[k], Wdyn[d * 64 + k], acc);
        g_enc[b * ENCD + d] = lrelu(acc);
    }
}

// ============================================================================
// K3: decoder LSTM (unchanged).
// ============================================================================
extern "C" __global__ void __launch_bounds__(256, 1)
k_decoder(const float* __restrict__ Wih_d, const float* __restrict__ Whh_d,
          const float* __restrict__ bih_d, const float* __restrict__ bhh_d,
          const float* __restrict__ Wop, const float* __restrict__ bop,
          float* __restrict__ out) {
    __shared__ __align__(16) float enc_s[4][ENCD];
    __shared__ __align__(16) float h_s[4][DECH];
    __shared__ __align__(16) float c_s[4][DECH];
    __shared__ __align__(16) float z_s[4][512];
    __shared__ float wop_s[5 * DECH];
    __shared__ float bop_s[8];
    const int tid = threadIdx.x;
    const int b0 = blockIdx.x * 4;

    for (int idx = tid; idx < 4 * ENCD; idx += 256)
        enc_s[idx / ENCD][idx % ENCD] = g_enc[b0 * ENCD + idx];
    for (int idx = tid; idx < 640; idx += 256) wop_s[idx] = Wop[idx];
    if (tid < 5) bop_s[tid] = bop[tid];
    for (int idx = tid; idx < 512; idx += 256) {
        h_s[idx >> 7][idx & 127] = 0.f;
        c_s[idx >> 7][idx & 127] = 0.f;
    }
    __syncthreads();

    float ez[8];
#pragma unroll
    for (int gg = 0; gg < 2; gg++) {
        int g = tid * 2 + gg;
        float bb = bih_d[g] + bhh_d[g];
        float a0 = bb, a1 = bb, a2 = bb, a3 = bb;
        for (int k = 0; k < ENCD; k++) {
            float w = Wih_d[g * ENCD + k];
            a0 = fmaf(w, enc_s[0][k], a0);
            a1 = fmaf(w, enc_s[1][k], a1);
            a2 = fmaf(w, enc_s[2][k], a2);
            a3 = fmaf(w, enc_s[3][k], a3);
        }
        ez[gg * 4 + 0] = a0; ez[gg * 4 + 1] = a1; ez[gg * 4 + 2] = a2; ez[gg * 4 + 3] = a3;
    }
    __syncthreads();

#pragma unroll 1
    for (int t = 0; t < T_PRED; t++) {
#pragma unroll
        for (int gg = 0; gg < 2; gg++) {
            int g = tid * 2 + gg;
            ull a0 = pk2(ez[gg * 4 + 0], 0.f), a1 = pk2(ez[gg * 4 + 1], 0.f);
            ull a2 = pk2(ez[gg * 4 + 2], 0.f), a3 = pk2(ez[gg * 4 + 3], 0.f);
            const ulonglong2* wr = (const ulonglong2*)(Whh_d + g * DECH);
            const ulonglong2* h0p = (const ulonglong2*)h_s[0];
            const ulonglong2* h1p = (const ulonglong2*)h_s[1];
            const ulonglong2* h2p = (const ulonglong2*)h_s[2];
            const ulonglong2* h3p = (const ulonglong2*)h_s[3];
#pragma unroll
            for (int kq = 0; kq < 32; kq++) {
                ulonglong2 w = wr[kq];
                ulonglong2 q0 = h0p[kq], q1 = h1p[kq], q2 = h2p[kq], q3 = h3p[kq];
                a0 = fma2(w.x, q0.x, a0); a0 = fma2(w.y, q0.y, a0);
                a1 = fma2(w.x, q1.x, a1); a1 = fma2(w.y, q1.y, a1);
                a2 = fma2(w.x, q2.x, a2); a2 = fma2(w.y, q2.y, a2);
                a3 = fma2(w.x, q3.x, a3); a3 = fma2(w.y, q3.y, a3);
            }
            z_s[0][g] = psum(a0); z_s[1][g] = psum(a1);
            z_s[2][g] = psum(a2); z_s[3][g] = psum(a3);
        }
        __syncthreads();
#pragma unroll
        for (int q = 0; q < 2; q++) {
            int task = tid + q * 256;
            int r = task >> 7, j = task & 127;
            float zi = z_s[r][j], zf = z_s[r][DECH + j];
            float zg = z_s[r][2 * DECH + j], zo = z_s[r][3 * DECH + j];
            float cn = fmaf(sigf(zf), c_s[r][j], sigf(zi) * tanha(zg));
            c_s[r][j] = cn;
            h_s[r][j] = sigf(zo) * tanha(cn);
        }
        __syncthreads();
        if (tid < 20) {
            int r = tid / 5, oi = tid - r * 5;
            float acc = bop_s[oi];
#pragma unroll
            for (int k = 0; k < DECH; k++) acc = fmaf(h_s[r][k], wop_s[oi * DECH + k], acc);
            float val = (oi < 2) ? acc : ((oi < 4) ? __expf(acc) : tanha(acc));
            out[((size_t)t * NN + (b0 + r)) * 5 + oi] = val;
        }
    }
}

extern "C" void kernel_launch(void* const* d_in, const int* in_sizes, int n_in,
                              void* d_out, int out_size) {
    const float* obs  = (const float*)d_in[0];
    const float* ngb  = (const float*)d_in[1];
    const int* masks_idxs    = (const int*)d_in[3];
    const int* obs_traj_idxs = (const int*)d_in[4];
    const float* Wip   = (const float*)d_in[7];
    const float* bip   = (const float*)d_in[8];
    const float* Wih_e = (const float*)d_in[9];
    const float* Whh_e = (const float*)d_in[10];
    const float* bih_e = (const float*)d_in[11];
    const float* bhh_e = (const float*)d_in[12];
    const float* Wdyn  = (const float*)d_in[13];
    const float* bdyn  = (const float*)d_in[14];
    const float* Wc1   = (const float*)d_in[15];
    const float* bc1   = (const float*)d_in[16];
    const float* Wc2   = (const float*)d_in[17];
    const float* bc2   = (const float*)d_in[18];
    const float* Wih_d = (const float*)d_in[19];
    const float* Whh_d = (const float*)d_in[20];
    const float* bih_d = (const float*)d_in[21];
    const float* bhh_d = (const float*)d_in[22];
    const float* Wop   = (const float*)d_in[23];
    const float* bop   = (const float*)d_in[24];

    cudaFuncSetAttribute(k_encoder, cudaFuncAttributeMaxDynamicSharedMemorySize, K1_SMEM);
    cudaFuncSetAttribute(k_social, cudaFuncAttributeMaxDynamicSharedMemorySize, K2_SMEM);

    k_encoder<<<290, 256, K1_SMEM>>>(obs, ngb, Wip, bip, Wih_e, Whh_e, bih_e, bhh_e);
    k_social<<<192, 256, K2_SMEM>>>(masks_idxs, obs_traj_idxs, Wdyn, bdyn, Wc1, bc1, Wc2, bc2);
    k_decoder<<<48, 256>>>(Wih_d, Whh_d, bih_d, bhh_d, Wop, bop, (float*)d_out);
}

// round 7
// speedup vs baseline: 2.8069x; 1.0588x over previous
#include <cuda_runtime.h>
#include <cuda_bf16.h>

#define T_OBS 16
#define T_PRED 25
#define NN 192
#define PP 36864
#define ENCH 64
#define DECH 128
#define DYND 32
#define ENCD 176   // DYN + SOC

typedef unsigned long long ull;

__device__ float g_Hn[(size_t)PP * ENCH];
__device__ float g_Hs[NN * ENCH];
__device__ float g_enc[NN * ENCD];
__device__ float g_Whh4[32 * 512 * 4];   // [k4][g][4]

__device__ __forceinline__ float lrelu(float x) { return fmaxf(x, 0.1f * x); }
__device__ __forceinline__ float tanha(float x) {
    float y; asm("tanh.approx.f32 %0,%1;" : "=f"(y) : "f"(x)); return y;
}
__device__ __forceinline__ float sigf(float x) { return fmaf(tanha(0.5f * x), 0.5f, 0.5f); }

__device__ __forceinline__ ull pk2(float lo, float hi) {
    ull r; asm("mov.b64 %0,{%1,%2};" : "=l"(r) : "f"(lo), "f"(hi)); return r;
}
__device__ __forceinline__ ull fma2(ull a, ull b, ull c) {
    ull d; asm("fma.rn.f32x2 %0,%1,%2,%3;" : "=l"(d) : "l"(a), "l"(b), "l"(c)); return d;
}
__device__ __forceinline__ float psum(ull v) {
    float a, b; asm("mov.b64 {%0,%1},%2;" : "=f"(a), "=f"(b) : "l"(v)); return a + b;
}

// ============================================================================
// K1: encoder LSTMs, register-tiled FFMA2 (R4 version — known good 607us).
// ============================================================================
#define K1_SMEM 182912

#define GEMM_KP(xb, wb) do {                                                  \
    ulonglong2 x01 = *(const ulonglong2*)(xb);                                \
    ulonglong2 x23 = *(const ulonglong2*)((xb) + 2);                          \
    ulonglong2 x45 = *(const ulonglong2*)((xb) + 4);                          \
    ulonglong2 x67 = *(const ulonglong2*)((xb) + 6);                          \
    ulonglong2 w0 = (wb)[0];                                                  \
    ulonglong2 w1 = (wb)[32];                                                 \
    ull xs0 = x01.x, xs1 = x01.y, xs2 = x23.x, xs3 = x23.y;                   \
    ull xs4 = x45.x, xs5 = x45.y, xs6 = x67.x, xs7 = x67.y;                   \
    acc[0][0] = fma2(w0.x, xs0, acc[0][0]); acc[0][1] = fma2(w0.y, xs0, acc[0][1]); \
    acc[0][2] = fma2(w1.x, xs0, acc[0][2]); acc[0][3] = fma2(w1.y, xs0, acc[0][3]); \
    acc[1][0] = fma2(w0.x, xs1, acc[1][0]); acc[1][1] = fma2(w0.y, xs1, acc[1][1]); \
    acc[1][2] = fma2(w1.x, xs1, acc[1][2]); acc[1][3] = fma2(w1.y, xs1, acc[1][3]); \
    acc[2][0] = fma2(w0.x, xs2, acc[2][0]); acc[2][1] = fma2(w0.y, xs2, acc[2][1]); \
    acc[2][2] = fma2(w1.x, xs2, acc[2][2]); acc[2][3] = fma2(w1.y, xs2, acc[2][3]); \
    acc[3][0] = fma2(w0.x, xs3, acc[3][0]); acc[3][1] = fma2(w0.y, xs3, acc[3][1]); \
    acc[3][2] = fma2(w1.x, xs3, acc[3][2]); acc[3][3] = fma2(w1.y, xs3, acc[3][3]); \
    acc[4][0] = fma2(w0.x, xs4, acc[4][0]); acc[4][1] = fma2(w0.y, xs4, acc[4][1]); \
    acc[4][2] = fma2(w1.x, xs4, acc[4][2]); acc[4][3] = fma2(w1.y, xs4, acc[4][3]); \
    acc[5][0] = fma2(w0.x, xs5, acc[5][0]); acc[5][1] = fma2(w0.y, xs5, acc[5][1]); \
    acc[5][2] = fma2(w1.x, xs5, acc[5][2]); acc[5][3] = fma2(w1.y, xs5, acc[5][3]); \
    acc[6][0] = fma2(w0.x, xs6, acc[6][0]); acc[6][1] = fma2(w0.y, xs6, acc[6][1]); \
    acc[6][2] = fma2(w1.x, xs6, acc[6][2]); acc[6][3] = fma2(w1.y, xs6, acc[6][3]); \
    acc[7][0] = fma2(w0.x, xs7, acc[7][0]); acc[7][1] = fma2(w0.y, xs7, acc[7][1]); \
    acc[7][2] = fma2(w1.x, xs7, acc[7][2]); acc[7][3] = fma2(w1.y, xs7, acc[7][3]); \
} while (0)

extern "C" __global__ void __launch_bounds__(256, 1)
k_encoder(const float* __restrict__ obs, const float* __restrict__ ngb,
          const float* __restrict__ Wip, const float* __restrict__ bip,
          const float* __restrict__ Wih, const float* __restrict__ Whh,
          const float* __restrict__ bih, const float* __restrict__ bhh) {
    extern __shared__ char smb[];
    ulonglong2* WL = (ulonglong2*)smb;
    float4* b4 = (float4*)(smb + 98304);
    float* wip_s = (float*)(smb + 99328);
    float* bip_s = (float*)(smb + 99584);
    ull* Xemb = (ull*)(smb + 99712);
    ull* Hbuf = Xemb + 16 * 130;

    const int tid = threadIdx.x;
    const int m = tid & 31, wid = tid >> 5;

    for (int idx = tid; idx < 6144; idx += 256) {
        int mm = idx & 31, half = (idx >> 5) & 1, su = (idx >> 6) & 1, kp = idx >> 7;
        int u = 2 * mm + su, k0 = 2 * kp;
        float v[4];
#pragma unroll
        for (int q = 0; q < 4; q++) {
            int g = 2 * half + (q >> 1);
            int k = k0 + (q & 1);
            int grow = g * 64 + u;
            v[q] = (k < 32) ? Wih[grow * 32 + k] : Whh[grow * 64 + (k - 32)];
        }
        ulonglong2 e; e.x = pk2(v[0], v[1]); e.y = pk2(v[2], v[3]);
        WL[idx] = e;
    }
    if (tid < 64) {
        b4[tid] = make_float4(bih[tid] + bhh[tid], bih[64 + tid] + bhh[64 + tid],
                              bih[128 + tid] + bhh[128 + tid], bih[192 + tid] + bhh[192 + tid]);
        wip_s[tid] = Wip[tid];
    }
    if (tid < 32) bip_s[tid] = bip[tid];
    for (int idx = tid; idx < 4160; idx += 256) Hbuf[idx] = 0ull;
    __syncthreads();

    const int bx = blockIdx.x;
    const bool ego = (bx >= 288);
    const int row0 = ego ? (bx - 288) * 128 : bx * 128;
    const int nr = ego ? NN : PP;
    const float* src = ego ? obs : ngb;

    float creg[32];
#pragma unroll
    for (int q = 0; q < 32; q++) creg[q] = 0.f;

    int p = 0;
#pragma unroll 1
    for (int t = 0; t < T_OBS; t++) {
        if (tid < 128) {
            int row = row0 + tid;
            float x0 = 0.f, x1 = 0.f;
            if (row < nr) {
                const float* px = src + ((size_t)t * nr + row) * 2;
                x0 = px[0]; x1 = px[1];
            }
#pragma unroll
            for (int mm = 0; mm < 16; mm++) {
                float e0 = fmaf(wip_s[4 * mm + 0], x0, fmaf(wip_s[4 * mm + 1], x1, bip_s[2 * mm + 0]));
                float e1 = fmaf(wip_s[4 * mm + 2], x0, fmaf(wip_s[4 * mm + 3], x1, bip_s[2 * mm + 1]));
                Xemb[mm * 130 + tid] = pk2(lrelu(e0), lrelu(e1));
            }
        }
        __syncthreads();
        const ull* Hr = Hbuf + p * 4160;
        ull* Hw = Hbuf + (p ^ 1) * 4160;
#pragma unroll
        for (int i = 0; i < 2; i++) {
            const int r0 = (wid * 2 + i) * 8;
            float hlo[8];
#pragma unroll
            for (int su = 0; su < 2; su++) {
                ull acc[8][4];
#pragma unroll
                for (int rr = 0; rr < 8; rr++)
#pragma unroll
                    for (int q = 0; q < 4; q++) acc[rr][q] = 0ull;
#pragma unroll 8
                for (int kp = 0; kp < 16; kp++) {
                    const ull* xb = Xemb + kp * 130 + r0;
                    const ulonglong2* wb = WL + (kp * 2 + su) * 64 + m;
                    GEMM_KP(xb, wb);
                }
#pragma unroll 8
                for (int kp = 0; kp < 32; kp++) {
                    const ull* xb = Hr + kp * 130 + r0;
                    const ulonglong2* wb = WL + ((kp + 16) * 2 + su) * 64 + m;
                    GEMM_KP(xb, wb);
                }
                float4 bb = b4[2 * m + su];
#pragma unroll
                for (int rr = 0; rr < 8; rr++) {
                    float zi = psum(acc[rr][0]) + bb.x;
                    float zf = psum(acc[rr][1]) + bb.y;
                    float zg = psum(acc[rr][2]) + bb.z;
                    float zo = psum(acc[rr][3]) + bb.w;
                    int ci = (i * 2 + su) * 8 + rr;
                    float cn = fmaf(sigf(zf), creg[ci], sigf(zi) * tanha(zg));
                    creg[ci] = cn;
                    float h = sigf(zo) * tanha(cn);
                    if (su == 0) hlo[rr] = h;
                    else Hw[m * 130 + r0 + rr] = pk2(hlo[rr], h);
                }
            }
        }
        __syncthreads();
        p ^= 1;
    }
    {
        const ull* Hf = Hbuf + p * 4160;
        ull* gH = ego ? (ull*)g_Hs : (ull*)g_Hn;
        for (int idx = tid; idx < 4096; idx += 256) {
            int mm = idx & 31, r = idx >> 5;
            int row = row0 + r;
            if (row < nr) gH[(size_t)row * 32 + mm] = Hf[mm * 130 + r];
        }
    }
}

// ============================================================================
// K2: social pipeline. Warp-uniform o, padded weight rows (stride 68),
// packed fma2 inner loops.
// floats: S@0 (4352) | A@4352 (2448) | W1@6800 (39168) | W2@45968 (9792) | Bv@55760
// ============================================================================
#define SROW 68
#define K2_SMEM (56016 * 4)

extern "C" __global__ void __launch_bounds__(256, 1)
k_social(const int* __restrict__ masks_idxs, const int* __restrict__ obs_traj_idxs,
         const float* __restrict__ Wdyn, const float* __restrict__ bdyn,
         const float* __restrict__ Wc1, const float* __restrict__ bc1,
         const float* __restrict__ Wc2, const float* __restrict__ bc2) {
    extern __shared__ float sm[];
    float* S = sm;
    float* A = sm + 4352;
    float* W1 = sm + 6800;
    float* W2 = sm + 45968;
    float* Bv = sm + 55760;
    const int b = blockIdx.x, tid = threadIdx.x;
    const int lane = tid & 31, wrp = tid >> 5;

    // coalesced gmem reads; padded-row smem writes (bank stride 4 per uv)
    for (int g = tid; g < 36864; g += 256) {
        int o = g / 576, r = g - o * 576, i = r / 9, uv = r - i * 9;
        W1[(o * 9 + uv) * SROW + i] = Wc1[g];
    }
    for (int g = tid; g < 9216; g += 256) {
        int o = g / 576, r = g - o * 576, i = r / 9, uv = r - i * 9;
        W2[(o * 9 + uv) * SROW + i] = Wc2[g];
    }
    for (int idx = tid; idx < 4096; idx += 256) {
        int i = idx & 63, pos = idx >> 6, x = pos >> 3, y = pos & 7;
        int r = masks_idxs[b * 64 + y * 8 + x];
        S[pos * SROW + i] = g_Hn[(size_t)r * 64 + i];
    }
    __syncthreads();
    // conv1: warp-uniform o; lanes sweep 36 positions
#pragma unroll 1
    for (int rep = 0; rep < 8; rep++) {
        int o = wrp * 8 + rep;
        float bb = bc1[o];
        for (int pp = lane; pp < 36; pp += 32) {
            int x = pp / 6, y = pp - x * 6;
            ull acc = pk2(bb, 0.f);
#pragma unroll
            for (int u = 0; u < 3; u++)
#pragma unroll
                for (int v = 0; v < 3; v++) {
                    const ulonglong2* s2 = (const ulonglong2*)(S + ((x + u) * 8 + (y + v)) * SROW);
                    const ulonglong2* w2 = (const ulonglong2*)(W1 + (o * 9 + u * 3 + v) * SROW);
#pragma unroll
                    for (int q = 0; q < 16; q++) {
                        ulonglong2 sv = s2[q], wv = w2[q];
                        acc = fma2(sv.x, wv.x, acc);
                        acc = fma2(sv.y, wv.y, acc);
                    }
                }
            A[pp * SROW + o] = lrelu(psum(acc));
        }
    }
    __syncthreads();
    {   // conv2: 256 outputs, half-warp-uniform o
        int o = tid >> 4, pp = tid & 15, x = pp >> 2, y = pp & 3;
        ull acc = pk2(bc2[o], 0.f);
#pragma unroll
        for (int u = 0; u < 3; u++)
#pragma unroll
            for (int v = 0; v < 3; v++) {
                const ulonglong2* a2 = (const ulonglong2*)(A + ((x + u) * 6 + (y + v)) * SROW);
                const ulonglong2* w2 = (const ulonglong2*)(W2 + (o * 9 + u * 3 + v) * SROW);
#pragma unroll
                for (int q = 0; q < 16; q++) {
                    ulonglong2 av = a2[q], wv = w2[q];
                    acc = fma2(av.x, wv.x, acc);
                    acc = fma2(av.y, wv.y, acc);
                }
            }
        Bv[o * 16 + pp] = lrelu(psum(acc));
    }
    __syncthreads();
    if (tid < 144) {  // 2x2 maxpool stride 1 -> [16][3][3]
        int o = tid / 9, pp = tid - o * 9, x = pp / 3, y = pp - x * 3;
        float m0 = fmaxf(Bv[o * 16 + x * 4 + y], Bv[o * 16 + x * 4 + y + 1]);
        float m1 = fmaxf(Bv[o * 16 + (x + 1) * 4 + y], Bv[o * 16 + (x + 1) * 4 + y + 1]);
        g_enc[b * ENCD + DYND + tid] = fmaxf(m0, m1);
    } else if (tid >= 160 && tid < 192) {  // traj_enc
        int d = tid - 160;
        int r = obs_traj_idxs[15 * NN + b];
        const float* hf = g_Hs + r * ENCH;
        float acc = bdyn[d];
#pragma unroll
        for (int k = 0; k < 64; k++) acc = fmaf(hf[k], Wdyn[d * 64 + k], acc);
        g_enc[b * ENCD + d] = lrelu(acc);
    }
}

// ============================================================================
// K_prep: transpose Whh_d -> g_Whh4[k4][g][4] for coalesced decoder loads.
// ============================================================================
extern "C" __global__ void k_prep(const float* __restrict__ Whh_d) {
    int idx = blockIdx.x * 256 + threadIdx.x;   // 65536 total
    int g = idx >> 7, k = idx & 127;
    g_Whh4[(k >> 2) * 2048 + g * 4 + (k & 3)] = Whh_d[idx];
}

// ============================================================================
// K3: decoder LSTM, 48 blocks x 4 rows, 512 threads (1 gate/thread),
// coalesced transposed weight streaming.
// ============================================================================
extern "C" __global__ void __launch_bounds__(512, 1)
k_decoder(const float* __restrict__ Wih_d, const float* __restrict__ bih_d,
          const float* __restrict__ bhh_d,
          const float* __restrict__ Wop, const float* __restrict__ bop,
          float* __restrict__ out) {
    __shared__ __align__(16) float enc_s[4][ENCD];
    __shared__ __align__(16) float h_s[4][DECH];
    __shared__ __align__(16) float c_s[4][DECH];
    __shared__ __align__(16) float z_s[4][512];
    __shared__ float wop_s[5 * DECH];
    __shared__ float bop_s[8];
    const int tid = threadIdx.x;
    const int b0 = blockIdx.x * 4;

    for (int idx = tid; idx < 4 * ENCD; idx += 512)
        enc_s[idx / ENCD][idx % ENCD] = g_enc[b0 * ENCD + idx];
    for (int idx = tid; idx < 640; idx += 512) wop_s[idx] = Wop[idx];
    if (tid < 5) bop_s[tid] = bop[tid];
    if (tid < 512) {
        h_s[tid >> 7][tid & 127] = 0.f;
        c_s[tid >> 7][tid & 127] = 0.f;
    }
    __syncthreads();

    // per-gate enc projection (hoisted out of step loop)
    const int g = tid;
    float ez[4];
    {
        float bb = bih_d[g] + bhh_d[g];
        ez[0] = bb; ez[1] = bb; ez[2] = bb; ez[3] = bb;
        const float4* wr = (const float4*)(Wih_d + g * ENCD);
#pragma unroll 4
        for (int k4 = 0; k4 < 44; k4++) {
            float4 w = wr[k4];
#pragma unroll
            for (int r = 0; r < 4; r++)
                ez[r] = fmaf(w.x, enc_s[r][4 * k4 + 0],
                        fmaf(w.y, enc_s[r][4 * k4 + 1],
                        fmaf(w.z, enc_s[r][4 * k4 + 2],
                        fmaf(w.w, enc_s[r][4 * k4 + 3], ez[r]))));
        }
    }
    __syncthreads();

#pragma unroll 1
    for (int t = 0; t < T_PRED; t++) {
        {
            ull a0 = pk2(ez[0], 0.f), a1 = pk2(ez[1], 0.f);
            ull a2 = pk2(ez[2], 0.f), a3 = pk2(ez[3], 0.f);
            const ulonglong2* h0p = (const ulonglong2*)h_s[0];
            const ulonglong2* h1p = (const ulonglong2*)h_s[1];
            const ulonglong2* h2p = (const ulonglong2*)h_s[2];
            const ulonglong2* h3p = (const ulonglong2*)h_s[3];
#pragma unroll
            for (int k4 = 0; k4 < 32; k4++) {
                ulonglong2 w = *(const ulonglong2*)(g_Whh4 + k4 * 2048 + g * 4);
                ulonglong2 q0 = h0p[k4], q1 = h1p[k4], q2 = h2p[k4], q3 = h3p[k4];
                a0 = fma2(w.x, q0.x, a0); a0 = fma2(w.y, q0.y, a0);
                a1 = fma2(w.x, q1.x, a1); a1 = fma2(w.y, q1.y, a1);
                a2 = fma2(w.x, q2.x, a2); a2 = fma2(w.y, q2.y, a2);
                a3 = fma2(w.x, q3.x, a3); a3 = fma2(w.y, q3.y, a3);
            }
            z_s[0][g] = psum(a0); z_s[1][g] = psum(a1);
            z_s[2][g] = psum(a2); z_s[3][g] = psum(a3);
        }
        __syncthreads();
        {
            int r = tid >> 7, j = tid & 127;
            float zi = z_s[r][j], zf = z_s[r][DECH + j];
            float zg = z_s[r][2 * DECH + j], zo = z_s[r][3 * DECH + j];
            float cn = fmaf(sigf(zf), c_s[r][j], sigf(zi) * tanha(zg));
            c_s[r][j] = cn;
            h_s[r][j] = sigf(zo) * tanha(cn);
        }
        __syncthreads();
        if (tid < 20) {
            int r = tid / 5, oi = tid - r * 5;
            float acc = bop_s[oi];
#pragma unroll
            for (int k = 0; k < DECH; k++) acc = fmaf(h_s[r][k], wop_s[oi * DECH + k], acc);
            float val = (oi < 2) ? acc : ((oi < 4) ? __expf(acc) : tanha(acc));
            out[((size_t)t * NN + (b0 + r)) * 5 + oi] = val;
        }
        // next h_s write is fenced by next iteration's first __syncthreads
    }
}

extern "C" void kernel_launch(void* const* d_in, const int* in_sizes, int n_in,
                              void* d_out, int out_size) {
    const float* obs  = (const float*)d_in[0];
    const float* ngb  = (const float*)d_in[1];
    const int* masks_idxs    = (const int*)d_in[3];
    const int* obs_traj_idxs = (const int*)d_in[4];
    const float* Wip   = (const float*)d_in[7];
    const float* bip   = (const float*)d_in[8];
    const float* Wih_e = (const float*)d_in[9];
    const float* Whh_e = (const float*)d_in[10];
    const float* bih_e = (const float*)d_in[11];
    const float* bhh_e = (const float*)d_in[12];
    const float* Wdyn  = (const float*)d_in[13];
    const float* bdyn  = (const float*)d_in[14];
    const float* Wc1   = (const float*)d_in[15];
    const float* bc1   = (const float*)d_in[16];
    const float* Wc2   = (const float*)d_in[17];
    const float* bc2   = (const float*)d_in[18];
    const float* Wih_d = (const float*)d_in[19];
    const float* Whh_d = (const float*)d_in[20];
    const float* bih_d = (const float*)d_in[21];
    const float* bhh_d = (const float*)d_in[22];
    const float* Wop   = (const float*)d_in[23];
    const float* bop   = (const float*)d_in[24];

    cudaFuncSetAttribute(k_encoder, cudaFuncAttributeMaxDynamicSharedMemorySize, K1_SMEM);
    cudaFuncSetAttribute(k_social, cudaFuncAttributeMaxDynamicSharedMemorySize, K2_SMEM);

    k_prep<<<256, 256>>>(Whh_d);
    k_encoder<<<290, 256, K1_SMEM>>>(obs, ngb, Wip, bip, Wih_e, Whh_e, bih_e, bhh_e);
    k_social<<<192, 256, K2_SMEM>>>(masks_idxs, obs_traj_idxs, Wdyn, bdyn, Wc1, bc1, Wc2, bc2);
    k_decoder<<<48, 512>>>(Wih_d, bih_d, bhh_d, Wop, bop, (float*)d_out);
}

// round 9
// speedup vs baseline: 3.0373x; 1.0821x over previous
#include <cuda_runtime.h>
#include <cuda_bf16.h>

#define T_OBS 16
#define T_PRED 25
#define NN 192
#define PP 36864
#define ENCH 64
#define DECH 128
#define DYND 32
#define ENCD 176   // DYN + SOC

typedef unsigned long long ull;

__device__ float g_Hn[(size_t)PP * ENCH];
__device__ float g_Hs[NN * ENCH];
__device__ float g_enc[NN * ENCD];
__device__ float g_Whh4[32 * 512 * 4];   // [k4][g][4]

__device__ __forceinline__ float lrelu(float x) { return fmaxf(x, 0.1f * x); }
__device__ __forceinline__ float tanha(float x) {
    float y; asm("tanh.approx.f32 %0,%1;" : "=f"(y) : "f"(x)); return y;
}
__device__ __forceinline__ float sigf(float x) { return fmaf(tanha(0.5f * x), 0.5f, 0.5f); }

__device__ __forceinline__ ull pk2(float lo, float hi) {
    ull r; asm("mov.b64 %0,{%1,%2};" : "=l"(r) : "f"(lo), "f"(hi)); return r;
}
__device__ __forceinline__ ull fma2(ull a, ull b, ull c) {
    ull d; asm("fma.rn.f32x2 %0,%1,%2,%3;" : "=l"(d) : "l"(a), "l"(b), "l"(c)); return d;
}
__device__ __forceinline__ float psum(ull v) {
    float a, b; asm("mov.b64 {%0,%1},%2;" : "=f"(a), "=f"(b) : "l"(v)); return a + b;
}

// ============================================================================
// K1: encoder LSTMs, register-tiled FFMA2 (unchanged — known good 607us).
// ============================================================================
#define K1_SMEM 182912

#define GEMM_KP(xb, wb) do {                                                  \
    ulonglong2 x01 = *(const ulonglong2*)(xb);                                \
    ulonglong2 x23 = *(const ulonglong2*)((xb) + 2);                          \
    ulonglong2 x45 = *(const ulonglong2*)((xb) + 4);                          \
    ulonglong2 x67 = *(const ulonglong2*)((xb) + 6);                          \
    ulonglong2 w0 = (wb)[0];                                                  \
    ulonglong2 w1 = (wb)[32];                                                 \
    ull xs0 = x01.x, xs1 = x01.y, xs2 = x23.x, xs3 = x23.y;                   \
    ull xs4 = x45.x, xs5 = x45.y, xs6 = x67.x, xs7 = x67.y;                   \
    acc[0][0] = fma2(w0.x, xs0, acc[0][0]); acc[0][1] = fma2(w0.y, xs0, acc[0][1]); \
    acc[0][2] = fma2(w1.x, xs0, acc[0][2]); acc[0][3] = fma2(w1.y, xs0, acc[0][3]); \
    acc[1][0] = fma2(w0.x, xs1, acc[1][0]); acc[1][1] = fma2(w0.y, xs1, acc[1][1]); \
    acc[1][2] = fma2(w1.x, xs1, acc[1][2]); acc[1][3] = fma2(w1.y, xs1, acc[1][3]); \
    acc[2][0] = fma2(w0.x, xs2, acc[2][0]); acc[2][1] = fma2(w0.y, xs2, acc[2][1]); \
    acc[2][2] = fma2(w1.x, xs2, acc[2][2]); acc[2][3] = fma2(w1.y, xs2, acc[2][3]); \
    acc[3][0] = fma2(w0.x, xs3, acc[3][0]); acc[3][1] = fma2(w0.y, xs3, acc[3][1]); \
    acc[3][2] = fma2(w1.x, xs3, acc[3][2]); acc[3][3] = fma2(w1.y, xs3, acc[3][3]); \
    acc[4][0] = fma2(w0.x, xs4, acc[4][0]); acc[4][1] = fma2(w0.y, xs4, acc[4][1]); \
    acc[4][2] = fma2(w1.x, xs4, acc[4][2]); acc[4][3] = fma2(w1.y, xs4, acc[4][3]); \
    acc[5][0] = fma2(w0.x, xs5, acc[5][0]); acc[5][1] = fma2(w0.y, xs5, acc[5][1]); \
    acc[5][2] = fma2(w1.x, xs5, acc[5][2]); acc[5][3] = fma2(w1.y, xs5, acc[5][3]); \
    acc[6][0] = fma2(w0.x, xs6, acc[6][0]); acc[6][1] = fma2(w0.y, xs6, acc[6][1]); \
    acc[6][2] = fma2(w1.x, xs6, acc[6][2]); acc[6][3] = fma2(w1.y, xs6, acc[6][3]); \
    acc[7][0] = fma2(w0.x, xs7, acc[7][0]); acc[7][1] = fma2(w0.y, xs7, acc[7][1]); \
    acc[7][2] = fma2(w1.x, xs7, acc[7][2]); acc[7][3] = fma2(w1.y, xs7, acc[7][3]); \
} while (0)

extern "C" __global__ void __launch_bounds__(256, 1)
k_encoder(const float* __restrict__ obs, const float* __restrict__ ngb,
          const float* __restrict__ Wip, const float* __restrict__ bip,
          const float* __restrict__ Wih, const float* __restrict__ Whh,
          const float* __restrict__ bih, const float* __restrict__ bhh) {
    extern __shared__ char smb[];
    ulonglong2* WL = (ulonglong2*)smb;
    float4* b4 = (float4*)(smb + 98304);
    float* wip_s = (float*)(smb + 99328);
    float* bip_s = (float*)(smb + 99584);
    ull* Xemb = (ull*)(smb + 99712);
    ull* Hbuf = Xemb + 16 * 130;

    const int tid = threadIdx.x;
    const int m = tid & 31, wid = tid >> 5;

    for (int idx = tid; idx < 6144; idx += 256) {
        int mm = idx & 31, half = (idx >> 5) & 1, su = (idx >> 6) & 1, kp = idx >> 7;
        int u = 2 * mm + su, k0 = 2 * kp;
        float v[4];
#pragma unroll
        for (int q = 0; q < 4; q++) {
            int g = 2 * half + (q >> 1);
            int k = k0 + (q & 1);
            int grow = g * 64 + u;
            v[q] = (k < 32) ? Wih[grow * 32 + k] : Whh[grow * 64 + (k - 32)];
        }
        ulonglong2 e; e.x = pk2(v[0], v[1]); e.y = pk2(v[2], v[3]);
        WL[idx] = e;
    }
    if (tid < 64) {
        b4[tid] = make_float4(bih[tid] + bhh[tid], bih[64 + tid] + bhh[64 + tid],
                              bih[128 + tid] + bhh[128 + tid], bih[192 + tid] + bhh[192 + tid]);
        wip_s[tid] = Wip[tid];
    }
    if (tid < 32) bip_s[tid] = bip[tid];
    for (int idx = tid; idx < 4160; idx += 256) Hbuf[idx] = 0ull;
    __syncthreads();

    const int bx = blockIdx.x;
    const bool ego = (bx >= 288);
    const int row0 = ego ? (bx - 288) * 128 : bx * 128;
    const int nr = ego ? NN : PP;
    const float* src = ego ? obs : ngb;

    float creg[32];
#pragma unroll
    for (int q = 0; q < 32; q++) creg[q] = 0.f;

    int p = 0;
#pragma unroll 1
    for (int t = 0; t < T_OBS; t++) {
        if (tid < 128) {
            int row = row0 + tid;
            float x0 = 0.f, x1 = 0.f;
            if (row < nr) {
                const float* px = src + ((size_t)t * nr + row) * 2;
                x0 = px[0]; x1 = px[1];
            }
#pragma unroll
            for (int mm = 0; mm < 16; mm++) {
                float e0 = fmaf(wip_s[4 * mm + 0], x0, fmaf(wip_s[4 * mm + 1], x1, bip_s[2 * mm + 0]));
                float e1 = fmaf(wip_s[4 * mm + 2], x0, fmaf(wip_s[4 * mm + 3], x1, bip_s[2 * mm + 1]));
                Xemb[mm * 130 + tid] = pk2(lrelu(e0), lrelu(e1));
            }
        }
        __syncthreads();
        const ull* Hr = Hbuf + p * 4160;
        ull* Hw = Hbuf + (p ^ 1) * 4160;
#pragma unroll
        for (int i = 0; i < 2; i++) {
            const int r0 = (wid * 2 + i) * 8;
            float hlo[8];
#pragma unroll
            for (int su = 0; su < 2; su++) {
                ull acc[8][4];
#pragma unroll
                for (int rr = 0; rr < 8; rr++)
#pragma unroll
                    for (int q = 0; q < 4; q++) acc[rr][q] = 0ull;
#pragma unroll 8
                for (int kp = 0; kp < 16; kp++) {
                    const ull* xb = Xemb + kp * 130 + r0;
                    const ulonglong2* wb = WL + (kp * 2 + su) * 64 + m;
                    GEMM_KP(xb, wb);
                }
#pragma unroll 8
                for (int kp = 0; kp < 32; kp++) {
                    const ull* xb = Hr + kp * 130 + r0;
                    const ulonglong2* wb = WL + ((kp + 16) * 2 + su) * 64 + m;
                    GEMM_KP(xb, wb);
                }
                float4 bb = b4[2 * m + su];
#pragma unroll
                for (int rr = 0; rr < 8; rr++) {
                    float zi = psum(acc[rr][0]) + bb.x;
                    float zf = psum(acc[rr][1]) + bb.y;
                    float zg = psum(acc[rr][2]) + bb.z;
                    float zo = psum(acc[rr][3]) + bb.w;
                    int ci = (i * 2 + su) * 8 + rr;
                    float cn = fmaf(sigf(zf), creg[ci], sigf(zi) * tanha(zg));
                    creg[ci] = cn;
                    float h = sigf(zo) * tanha(cn);
                    if (su == 0) hlo[rr] = h;
                    else Hw[m * 130 + r0 + rr] = pk2(hlo[rr], h);
                }
            }
        }
        __syncthreads();
        p ^= 1;
    }
    {
        const ull* Hf = Hbuf + p * 4160;
        ull* gH = ego ? (ull*)g_Hs : (ull*)g_Hn;
        for (int idx = tid; idx < 4096; idx += 256) {
            int mm = idx & 31, r = idx >> 5;
            int row = row0 + r;
            if (row < nr) gH[(size_t)row * 32 + mm] = Hf[mm * 130 + r];
        }
    }
}

// ============================================================================
// K2: social pipeline. conv1 repacked: 8 full warp-iters + 1 combined
// leftover iter (no 4/32-lane waste).
// ============================================================================
#define SROW 68
#define K2_SMEM (56016 * 4)

__device__ __forceinline__ float conv1_at(const float* S, const float* W1,
                                          int o, int x, int y, float bb) {
    ull acc = pk2(bb, 0.f);
#pragma unroll
    for (int u = 0; u < 3; u++)
#pragma unroll
        for (int v = 0; v < 3; v++) {
            const ulonglong2* s2 = (const ulonglong2*)(S + ((x + u) * 8 + (y + v)) * SROW);
            const ulonglong2* w2 = (const ulonglong2*)(W1 + (o * 9 + u * 3 + v) * SROW);
#pragma unroll
            for (int q = 0; q < 16; q++) {
                ulonglong2 sv = s2[q], wv = w2[q];
                acc = fma2(sv.x, wv.x, acc);
                acc = fma2(sv.y, wv.y, acc);
            }
        }
    return lrelu(psum(acc));
}

extern "C" __global__ void __launch_bounds__(256, 1)
k_social(const int* __restrict__ masks_idxs, const int* __restrict__ obs_traj_idxs,
         const float* __restrict__ Wdyn, const float* __restrict__ bdyn,
         const float* __restrict__ Wc1, const float* __restrict__ bc1,
         const float* __restrict__ Wc2, const float* __restrict__ bc2) {
    extern __shared__ float sm[];
    float* S = sm;
    float* A = sm + 4352;
    float* W1 = sm + 6800;
    float* W2 = sm + 45968;
    float* Bv = sm + 55760;
    const int b = blockIdx.x, tid = threadIdx.x;
    const int lane = tid & 31, wrp = tid >> 5;

    for (int g = tid; g < 36864; g += 256) {
        int o = g / 576, r = g - o * 576, i = r / 9, uv = r - i * 9;
        W1[(o * 9 + uv) * SROW + i] = Wc1[g];
    }
    for (int g = tid; g < 9216; g += 256) {
        int o = g / 576, r = g - o * 576, i = r / 9, uv = r - i * 9;
        W2[(o * 9 + uv) * SROW + i] = Wc2[g];
    }
    for (int idx = tid; idx < 4096; idx += 256) {
        int i = idx & 63, pos = idx >> 6, x = pos >> 3, y = pos & 7;
        int r = masks_idxs[b * 64 + y * 8 + x];
        S[pos * SROW + i] = g_Hn[(size_t)r * 64 + i];
    }
    __syncthreads();
    // conv1: 8 full iters (warp-uniform o, pp=lane) + 1 combined leftover iter
#pragma unroll 1
    for (int rep = 0; rep < 8; rep++) {
        int o = wrp * 8 + rep;
        int x = lane / 6, y = lane - x * 6;
        A[lane * SROW + o] = conv1_at(S, W1, o, x, y, bc1[o]);
    }
    {
        int o = wrp * 8 + (lane >> 2);
        int pp = 32 + (lane & 3);
        int x = 5, y = pp - 30;
        A[pp * SROW + o] = conv1_at(S, W1, o, x, y, bc1[o]);
    }
    __syncthreads();
    {   // conv2: 256 outputs, half-warp-uniform o
        int o = tid >> 4, pp = tid & 15, x = pp >> 2, y = pp & 3;
        ull acc = pk2(bc2[o], 0.f);
#pragma unroll
        for (int u = 0; u < 3; u++)
#pragma unroll
            for (int v = 0; v < 3; v++) {
                const ulonglong2* a2 = (const ulonglong2*)(A + ((x + u) * 6 + (y + v)) * SROW);
                const ulonglong2* w2 = (const ulonglong2*)(W2 + (o * 9 + u * 3 + v) * SROW);
#pragma unroll
                for (int q = 0; q < 16; q++) {
                    ulonglong2 av = a2[q], wv = w2[q];
                    acc = fma2(av.x, wv.x, acc);
                    acc = fma2(av.y, wv.y, acc);
                }
            }
        Bv[o * 16 + pp] = lrelu(psum(acc));
    }
    __syncthreads();
    if (tid < 144) {
        int o = tid / 9, pp = tid - o * 9, x = pp / 3, y = pp - x * 3;
        float m0 = fmaxf(Bv[o * 16 + x * 4 + y], Bv[o * 16 + x * 4 + y + 1]);
        float m1 = fmaxf(Bv[o * 16 + (x + 1) * 4 + y], Bv[o * 16 + (x + 1) * 4 + y + 1]);
        g_enc[b * ENCD + DYND + tid] = fmaxf(m0, m1);
    } else if (tid >= 160 && tid < 192) {
        int d = tid - 160;
        int r = obs_traj_idxs[15 * NN + b];
        const float* hf = g_Hs + r * ENCH;
        float acc = bdyn[d];
#pragma unroll
        for (int k = 0; k < 64; k++) acc = fmaf(hf[k], Wdyn[d * 64 + k], acc);
        g_enc[b * ENCD + d] = lrelu(acc);
    }
}

// ============================================================================
// K_prep: transpose Whh_d -> g_Whh4[k4][g][4].
// ============================================================================
extern "C" __global__ void k_prep(const float* __restrict__ Whh_d) {
    int idx = blockIdx.x * 256 + threadIdx.x;   // 65536 total
    int g = idx >> 7, k = idx & 127;
    g_Whh4[(k >> 2) * 2048 + g * 4 + (k & 3)] = Whh_d[idx];
}

// ============================================================================
// K3: decoder LSTM. 96 blocks x 2 rows, 512 threads (1 gate/thread).
// Weights resident: k4 0..23 in smem (staged once), k4 24..31 in registers.
// Zero global loads inside the step loop.
// smem floats: W 49152 | enc 352 | h 256 | c 256 | z 1024 | wop 640 | bop 8
// ============================================================================
#define D_W 0
#define D_ENC 49152
#define D_H 49504
#define D_C 49760
#define D_Z 50016
#define D_WOP 51040
#define D_BOP 51680
#define K3_SMEM (51688 * 4)

extern "C" __global__ void __launch_bounds__(512, 1)
k_decoder(const float* __restrict__ Wih_d, const float* __restrict__ bih_d,
          const float* __restrict__ bhh_d,
          const float* __restrict__ Wop, const float* __restrict__ bop,
          float* __restrict__ out) {
    extern __shared__ float dsm[];
    float* enc_s = dsm + D_ENC;     // [2][176]
    float* h_s = dsm + D_H;         // [2][128]
    float* c_s = dsm + D_C;         // [2][128]
    float* z_s = dsm + D_Z;         // [2][512]
    float* wop_s = dsm + D_WOP;
    float* bop_s = dsm + D_BOP;
    const int tid = threadIdx.x;
    const int b0 = blockIdx.x * 2;
    const int g = tid;

    // stage smem weights (g_Whh4 first 24 k4 is layout-identical -> linear copy)
    {
        const float4* src4 = (const float4*)g_Whh4;
        float4* dst4 = (float4*)(dsm + D_W);
        for (int i = tid; i < 12288; i += 512) dst4[i] = src4[i];
    }
    for (int idx = tid; idx < 2 * ENCD; idx += 512)
        enc_s[idx] = g_enc[b0 * ENCD + idx];
    for (int idx = tid; idx < 640; idx += 512) wop_s[idx] = Wop[idx];
    if (tid < 5) bop_s[tid] = bop[tid];
    if (tid < 256) { h_s[tid] = 0.f; c_s[tid] = 0.f; }

    // register-resident weights for k4 24..31
    ulonglong2 wst[8];
#pragma unroll
    for (int k = 0; k < 8; k++)
        wst[k] = *(const ulonglong2*)(g_Whh4 + (24 + k) * 2048 + g * 4);

    __syncthreads();

    // per-gate enc projection (hoisted; 2 rows)
    float ez0, ez1;
    {
        float bb = bih_d[g] + bhh_d[g];
        ez0 = bb; ez1 = bb;
        const float4* wr = (const float4*)(Wih_d + g * ENCD);
#pragma unroll 4
        for (int k4 = 0; k4 < 44; k4++) {
            float4 w = wr[k4];
            ez0 = fmaf(w.x, enc_s[4 * k4 + 0], fmaf(w.y, enc_s[4 * k4 + 1],
                  fmaf(w.z, enc_s[4 * k4 + 2], fmaf(w.w, enc_s[4 * k4 + 3], ez0))));
            ez1 = fmaf(w.x, enc_s[ENCD + 4 * k4 + 0], fmaf(w.y, enc_s[ENCD + 4 * k4 + 1],
                  fmaf(w.z, enc_s[ENCD + 4 * k4 + 2], fmaf(w.w, enc_s[ENCD + 4 * k4 + 3], ez1))));
        }
    }
    __syncthreads();

#pragma unroll 1
    for (int t = 0; t < T_PRED; t++) {
        {
            ull a0 = pk2(ez0, 0.f), a1 = pk2(ez1, 0.f);
            const ulonglong2* wsm = (const ulonglong2*)(dsm + D_W) + g;
            const ulonglong2* h0p = (const ulonglong2*)h_s;
            const ulonglong2* h1p = (const ulonglong2*)(h_s + DECH);
#pragma unroll
            for (int k4 = 0; k4 < 24; k4++) {
                ulonglong2 w = wsm[k4 * 512];
                ulonglong2 q0 = h0p[k4], q1 = h1p[k4];
                a0 = fma2(w.x, q0.x, a0); a0 = fma2(w.y, q0.y, a0);
                a1 = fma2(w.x, q1.x, a1); a1 = fma2(w.y, q1.y, a1);
            }
#pragma unroll
            for (int k = 0; k < 8; k++) {
                ulonglong2 w = wst[k];
                ulonglong2 q0 = h0p[24 + k], q1 = h1p[24 + k];
                a0 = fma2(w.x, q0.x, a0); a0 = fma2(w.y, q0.y, a0);
                a1 = fma2(w.x, q1.x, a1); a1 = fma2(w.y, q1.y, a1);
            }
            z_s[g] = psum(a0);
            z_s[512 + g] = psum(a1);
        }
        __syncthreads();
        if (tid < 256) {
            int r = tid >> 7, j = tid & 127;
            const float* zr = z_s + r * 512;
            float zi = zr[j], zf = zr[DECH + j];
            float zg = zr[2 * DECH + j], zo = zr[3 * DECH + j];
            float cn = fmaf(sigf(zf), c_s[r * DECH + j], sigf(zi) * tanha(zg));
            c_s[r * DECH + j] = cn;
            h_s[r * DECH + j] = sigf(zo) * tanha(cn);
        }
        __syncthreads();
        if (tid < 10) {
            int r = tid / 5, oi = tid - r * 5;
            float acc = bop_s[oi];
#pragma unroll
            for (int k = 0; k < DECH; k++) acc = fmaf(h_s[r * DECH + k], wop_s[oi * DECH + k], acc);
            float val = (oi < 2) ? acc : ((oi < 4) ? __expf(acc) : tanha(acc));
            out[((size_t)t * NN + (b0 + r)) * 5 + oi] = val;
        }
        // next h_s write is fenced by the next iteration's first __syncthreads
    }
}

extern "C" void kernel_launch(void* const* d_in, const int* in_sizes, int n_in,
                              void* d_out, int out_size) {
    const float* obs  = (const float*)d_in[0];
    const float* ngb  = (const float*)d_in[1];
    const int* masks_idxs    = (const int*)d_in[3];
    const int* obs_traj_idxs = (const int*)d_in[4];
    const float* Wip   = (const float*)d_in[7];
    const float* bip   = (const float*)d_in[8];
    const float* Wih_e = (const float*)d_in[9];
    const float* Whh_e = (const float*)d_in[10];
    const float* bih_e = (const float*)d_in[11];
    const float* bhh_e = (const float*)d_in[12];
    const float* Wdyn  = (const float*)d_in[13];
    const float* bdyn  = (const float*)d_in[14];
    const float* Wc1   = (const float*)d_in[15];
    const float* bc1   = (const float*)d_in[16];
    const float* Wc2   = (const float*)d_in[17];
    const float* bc2   = (const float*)d_in[18];
    const float* Wih_d = (const float*)d_in[19];
    const float* Whh_d = (const float*)d_in[20];
    const float* bih_d = (const float*)d_in[21];
    const float* bhh_d = (const float*)d_in[22];
    const float* Wop   = (const float*)d_in[23];
    const float* bop   = (const float*)d_in[24];

    cudaFuncSetAttribute(k_encoder, cudaFuncAttributeMaxDynamicSharedMemorySize, K1_SMEM);
    cudaFuncSetAttribute(k_social, cudaFuncAttributeMaxDynamicSharedMemorySize, K2_SMEM);
    cudaFuncSetAttribute(k_decoder, cudaFuncAttributeMaxDynamicSharedMemorySize, K3_SMEM);

    k_prep<<<256, 256>>>(Whh_d);
    k_encoder<<<290, 256, K1_SMEM>>>(obs, ngb, Wip, bip, Wih_e, Whh_e, bih_e, bhh_e);
    k_social<<<192, 256, K2_SMEM>>>(masks_idxs, obs_traj_idxs, Wdyn, bdyn, Wc1, bc1, Wc2, bc2);
    k_decoder<<<96, 512, K3_SMEM>>>(Wih_d, bih_d, bhh_d, Wop, bop, (float*)d_out);
}

// round 10
// speedup vs baseline: 3.3745x; 1.1110x over previous
#include <cuda_runtime.h>
#include <cuda_bf16.h>

#define T_OBS 16
#define T_PRED 25
#define NN 192
#define PP 36864
#define ENCH 64
#define DECH 128
#define DYND 32
#define ENCD 176   // DYN + SOC

typedef unsigned long long ull;

__device__ float g_Hn[(size_t)PP * ENCH];
__device__ float g_Hs[NN * ENCH];
__device__ float g_enc[NN * ENCD];
__device__ float g_Whh4[32 * 512 * 4];   // [k4][u*4+q][4]
__device__ float g_W1t[36864];           // [uv][i2][64 o] ull-packed
__device__ float g_W2t[9216];            // [uv][i2][16 o] ull-packed

__device__ __forceinline__ float lrelu(float x) { return fmaxf(x, 0.1f * x); }
__device__ __forceinline__ float tanha(float x) {
    float y; asm("tanh.approx.f32 %0,%1;" : "=f"(y) : "f"(x)); return y;
}
__device__ __forceinline__ float sigf(float x) { return fmaf(tanha(0.5f * x), 0.5f, 0.5f); }

__device__ __forceinline__ ull pk2(float lo, float hi) {
    ull r; asm("mov.b64 %0,{%1,%2};" : "=l"(r) : "f"(lo), "f"(hi)); return r;
}
__device__ __forceinline__ ull fma2(ull a, ull b, ull c) {
    ull d; asm("fma.rn.f32x2 %0,%1,%2,%3;" : "=l"(d) : "l"(a), "l"(b), "l"(c)); return d;
}
__device__ __forceinline__ float psum(ull v) {
    float a, b; asm("mov.b64 {%0,%1},%2;" : "=f"(a), "=f"(b) : "l"(v)); return a + b;
}

// ============================================================================
// K1: encoder LSTMs, register-tiled FFMA2 (unchanged — known good 607us).
// ============================================================================
#define K1_SMEM 182912

#define GEMM_KP(xb, wb) do {                                                  \
    ulonglong2 x01 = *(const ulonglong2*)(xb);                                \
    ulonglong2 x23 = *(const ulonglong2*)((xb) + 2);                          \
    ulonglong2 x45 = *(const ulonglong2*)((xb) + 4);                          \
    ulonglong2 x67 = *(const ulonglong2*)((xb) + 6);                          \
    ulonglong2 w0 = (wb)[0];                                                  \
    ulonglong2 w1 = (wb)[32];                                                 \
    ull xs0 = x01.x, xs1 = x01.y, xs2 = x23.x, xs3 = x23.y;                   \
    ull xs4 = x45.x, xs5 = x45.y, xs6 = x67.x, xs7 = x67.y;                   \
    acc[0][0] = fma2(w0.x, xs0, acc[0][0]); acc[0][1] = fma2(w0.y, xs0, acc[0][1]); \
    acc[0][2] = fma2(w1.x, xs0, acc[0][2]); acc[0][3] = fma2(w1.y, xs0, acc[0][3]); \
    acc[1][0] = fma2(w0.x, xs1, acc[1][0]); acc[1][1] = fma2(w0.y, xs1, acc[1][1]); \
    acc[1][2] = fma2(w1.x, xs1, acc[1][2]); acc[1][3] = fma2(w1.y, xs1, acc[1][3]); \
    acc[2][0] = fma2(w0.x, xs2, acc[2][0]); acc[2][1] = fma2(w0.y, xs2, acc[2][1]); \
    acc[2][2] = fma2(w1.x, xs2, acc[2][2]); acc[2][3] = fma2(w1.y, xs2, acc[2][3]); \
    acc[3][0] = fma2(w0.x, xs3, acc[3][0]); acc[3][1] = fma2(w0.y, xs3, acc[3][1]); \
    acc[3][2] = fma2(w1.x, xs3, acc[3][2]); acc[3][3] = fma2(w1.y, xs3, acc[3][3]); \
    acc[4][0] = fma2(w0.x, xs4, acc[4][0]); acc[4][1] = fma2(w0.y, xs4, acc[4][1]); \
    acc[4][2] = fma2(w1.x, xs4, acc[4][2]); acc[4][3] = fma2(w1.y, xs4, acc[4][3]); \
    acc[5][0] = fma2(w0.x, xs5, acc[5][0]); acc[5][1] = fma2(w0.y, xs5, acc[5][1]); \
    acc[5][2] = fma2(w1.x, xs5, acc[5][2]); acc[5][3] = fma2(w1.y, xs5, acc[5][3]); \
    acc[6][0] = fma2(w0.x, xs6, acc[6][0]); acc[6][1] = fma2(w0.y, xs6, acc[6][1]); \
    acc[6][2] = fma2(w1.x, xs6, acc[6][2]); acc[6][3] = fma2(w1.y, xs6, acc[6][3]); \
    acc[7][0] = fma2(w0.x, xs7, acc[7][0]); acc[7][1] = fma2(w0.y, xs7, acc[7][1]); \
    acc[7][2] = fma2(w1.x, xs7, acc[7][2]); acc[7][3] = fma2(w1.y, xs7, acc[7][3]); \
} while (0)

extern "C" __global__ void __launch_bounds__(256, 1)
k_encoder(const float* __restrict__ obs, const float* __restrict__ ngb,
          const float* __restrict__ Wip, const float* __restrict__ bip,
          const float* __restrict__ Wih, const float* __restrict__ Whh,
          const float* __restrict__ bih, const float* __restrict__ bhh) {
    extern __shared__ char smb[];
    ulonglong2* WL = (ulonglong2*)smb;
    float4* b4 = (float4*)(smb + 98304);
    float* wip_s = (float*)(smb + 99328);
    float* bip_s = (float*)(smb + 99584);
    ull* Xemb = (ull*)(smb + 99712);
    ull* Hbuf = Xemb + 16 * 130;

    const int tid = threadIdx.x;
    const int m = tid & 31, wid = tid >> 5;

    for (int idx = tid; idx < 6144; idx += 256) {
        int mm = idx & 31, half = (idx >> 5) & 1, su = (idx >> 6) & 1, kp = idx >> 7;
        int u = 2 * mm + su, k0 = 2 * kp;
        float v[4];
#pragma unroll
        for (int q = 0; q < 4; q++) {
            int g = 2 * half + (q >> 1);
            int k = k0 + (q & 1);
            int grow = g * 64 + u;
            v[q] = (k < 32) ? Wih[grow * 32 + k] : Whh[grow * 64 + (k - 32)];
        }
        ulonglong2 e; e.x = pk2(v[0], v[1]); e.y = pk2(v[2], v[3]);
        WL[idx] = e;
    }
    if (tid < 64) {
        b4[tid] = make_float4(bih[tid] + bhh[tid], bih[64 + tid] + bhh[64 + tid],
                              bih[128 + tid] + bhh[128 + tid], bih[192 + tid] + bhh[192 + tid]);
        wip_s[tid] = Wip[tid];
    }
    if (tid < 32) bip_s[tid] = bip[tid];
    for (int idx = tid; idx < 4160; idx += 256) Hbuf[idx] = 0ull;
    __syncthreads();

    const int bx = blockIdx.x;
    const bool ego = (bx >= 288);
    const int row0 = ego ? (bx - 288) * 128 : bx * 128;
    const int nr = ego ? NN : PP;
    const float* src = ego ? obs : ngb;

    float creg[32];
#pragma unroll
    for (int q = 0; q < 32; q++) creg[q] = 0.f;

    int p = 0;
#pragma unroll 1
    for (int t = 0; t < T_OBS; t++) {
        if (tid < 128) {
            int row = row0 + tid;
            float x0 = 0.f, x1 = 0.f;
            if (row < nr) {
                const float* px = src + ((size_t)t * nr + row) * 2;
                x0 = px[0]; x1 = px[1];
            }
#pragma unroll
            for (int mm = 0; mm < 16; mm++) {
                float e0 = fmaf(wip_s[4 * mm + 0], x0, fmaf(wip_s[4 * mm + 1], x1, bip_s[2 * mm + 0]));
                float e1 = fmaf(wip_s[4 * mm + 2], x0, fmaf(wip_s[4 * mm + 3], x1, bip_s[2 * mm + 1]));
                Xemb[mm * 130 + tid] = pk2(lrelu(e0), lrelu(e1));
            }
        }
        __syncthreads();
        const ull* Hr = Hbuf + p * 4160;
        ull* Hw = Hbuf + (p ^ 1) * 4160;
#pragma unroll
        for (int i = 0; i < 2; i++) {
            const int r0 = (wid * 2 + i) * 8;
            float hlo[8];
#pragma unroll
            for (int su = 0; su < 2; su++) {
                ull acc[8][4];
#pragma unroll
                for (int rr = 0; rr < 8; rr++)
#pragma unroll
                    for (int q = 0; q < 4; q++) acc[rr][q] = 0ull;
#pragma unroll 8
                for (int kp = 0; kp < 16; kp++) {
                    const ull* xb = Xemb + kp * 130 + r0;
                    const ulonglong2* wb = WL + (kp * 2 + su) * 64 + m;
                    GEMM_KP(xb, wb);
                }
#pragma unroll 8
                for (int kp = 0; kp < 32; kp++) {
                    const ull* xb = Hr + kp * 130 + r0;
                    const ulonglong2* wb = WL + ((kp + 16) * 2 + su) * 64 + m;
                    GEMM_KP(xb, wb);
                }
                float4 bb = b4[2 * m + su];
#pragma unroll
                for (int rr = 0; rr < 8; rr++) {
                    float zi = psum(acc[rr][0]) + bb.x;
                    float zf = psum(acc[rr][1]) + bb.y;
                    float zg = psum(acc[rr][2]) + bb.z;
                    float zo = psum(acc[rr][3]) + bb.w;
                    int ci = (i * 2 + su) * 8 + rr;
                    float cn = fmaf(sigf(zf), creg[ci], sigf(zi) * tanha(zg));
                    creg[ci] = cn;
                    float h = sigf(zo) * tanha(cn);
                    if (su == 0) hlo[rr] = h;
                    else Hw[m * 130 + r0 + rr] = pk2(hlo[rr], h);
                }
            }
        }
        __syncthreads();
        p ^= 1;
    }
    {
        const ull* Hf = Hbuf + p * 4160;
        ull* gH = ego ? (ull*)g_Hs : (ull*)g_Hn;
        for (int idx = tid; idx < 4096; idx += 256) {
            int mm = idx & 31, r = idx >> 5;
            int row = row0 + r;
            if (row < nr) gH[(size_t)row * 32 + mm] = Hf[mm * 130 + r];
        }
    }
}

// ============================================================================
// K_prep: weight transposes.
//  Whh_d -> g_Whh4[k4][u*4+q][k&3]  (decoder lane order)
//  Wc1   -> g_W1t [uv][i2][64 o] packed pairs
//  Wc2   -> g_W2t [uv][i2][16 o] packed pairs
// ============================================================================
extern "C" __global__ void k_prep(const float* __restrict__ Whh_d,
                                  const float* __restrict__ Wc1,
                                  const float* __restrict__ Wc2) {
    int idx = blockIdx.x * 256 + threadIdx.x;
    if (idx < 65536) {
        int g = idx >> 7, k = idx & 127;
        int cg = g >> 7, uu = g & 127;
        int t = uu * 4 + cg;
        g_Whh4[(k >> 2) * 2048 + t * 4 + (k & 3)] = Whh_d[idx];
    } else if (idx < 102400) {
        int g2 = idx - 65536;
        int o = g2 / 576, rem = g2 - o * 576, i = rem / 9, uv = rem - i * 9;
        g_W1t[((uv * 32 + (i >> 1)) * 64 + o) * 2 + (i & 1)] = Wc1[g2];
    } else if (idx < 111616) {
        int g2 = idx - 102400;
        int o = g2 / 576, rem = g2 - o * 576, i = rem / 9, uv = rem - i * 9;
        g_W2t[((uv * 32 + (i >> 1)) * 16 + o) * 2 + (i & 1)] = Wc2[g2];
    }
}

// ============================================================================
// K2: social pipeline, lane = output-channel GEMM style.
// floats: S@0 [64][68] | A@4352 [36][68] | W1T@6800 | W2T@43664 | Bv@52880
// ============================================================================
#define SROW 68
#define K2_SMEM (53136 * 4)

extern "C" __global__ void __launch_bounds__(256, 1)
k_social(const int* __restrict__ masks_idxs, const int* __restrict__ obs_traj_idxs,
         const float* __restrict__ Wdyn, const float* __restrict__ bdyn,
         const float* __restrict__ bc1, const float* __restrict__ bc2) {
    extern __shared__ float sm[];
    float* S = sm;
    float* A = sm + 4352;
    float* W1T = sm + 6800;
    float* W2T = sm + 43664;
    float* Bv = sm + 52880;
    const int b = blockIdx.x, tid = threadIdx.x;
    const int lane = tid & 31, wrp = tid >> 5;

    {   // linear staged copies (pre-transposed in k_prep)
        const float4* s4 = (const float4*)g_W1t;
        float4* d4 = (float4*)W1T;
        for (int i = tid; i < 9216; i += 256) d4[i] = s4[i];
        const float4* s2 = (const float4*)g_W2t;
        float4* d2 = (float4*)W2T;
        for (int i = tid; i < 2304; i += 256) d2[i] = s2[i];
    }
    for (int idx = tid; idx < 4096; idx += 256) {
        int i = idx & 63, pos = idx >> 6, x = pos >> 3, y = pos & 7;
        int r = masks_idxs[b * 64 + y * 8 + x];
        S[pos * SROW + i] = g_Hn[(size_t)r * 64 + i];
    }
    __syncthreads();

    // conv1: warp w: o = (w>>2)*32 + lane; positions p_j = (w&3) + 4j, j=0..8
    {
        const int o = ((wrp >> 2) << 5) + lane;
        const int ws = wrp & 3;
        int xj[9], yj[9];
#pragma unroll
        for (int j = 0; j < 9; j++) {
            int pj = ws + 4 * j;
            xj[j] = pj / 6; yj[j] = pj - 6 * xj[j];
        }
        ull acc[9];
        float bb = __ldg(bc1 + o);
#pragma unroll
        for (int j = 0; j < 9; j++) acc[j] = pk2(bb, 0.f);
        const ull* W1u = (const ull*)W1T;
#pragma unroll 1
        for (int uv = 0; uv < 9; uv++) {
            int u = uv / 3, v = uv - 3 * u;
            int px[9];
#pragma unroll
            for (int j = 0; j < 9; j++) px[j] = (xj[j] + u) * 8 + (yj[j] + v);
#pragma unroll 1
            for (int c = 0; c < 4; c++) {
                ull wr[8];
#pragma unroll
                for (int kk = 0; kk < 8; kk++)
                    wr[kk] = W1u[(uv * 32 + c * 8 + kk) * 64 + o];
#pragma unroll
                for (int j = 0; j < 9; j++) {
                    const ulonglong2* sr = (const ulonglong2*)(S + px[j] * SROW) + c * 4;
#pragma unroll
                    for (int k2 = 0; k2 < 4; k2++) {
                        ulonglong2 sv = sr[k2];
                        acc[j] = fma2(wr[2 * k2 + 0], sv.x, acc[j]);
                        acc[j] = fma2(wr[2 * k2 + 1], sv.y, acc[j]);
                    }
                }
            }
        }
#pragma unroll
        for (int j = 0; j < 9; j++)
            A[(ws + 4 * j) * SROW + o] = lrelu(psum(acc[j]));
    }
    __syncthreads();

    // conv2: 128 threads: lane = o(16) x pg-half; each thread 2 positions
    if (tid < 128) {
        const int w2 = tid >> 5;
        const int o = lane & 15;
        const int pg = w2 * 2 + (lane >> 4);
        const int pp0 = pg * 2, pp1 = pg * 2 + 1;
        const int x0 = pp0 >> 2, y0 = pp0 & 3;
        const int x1 = pp1 >> 2, y1 = pp1 & 3;
        float bb = __ldg(bc2 + o);
        ull a0 = pk2(bb, 0.f), a1 = pk2(bb, 0.f);
        const ull* W2u = (const ull*)W2T;
#pragma unroll 1
        for (int uv = 0; uv < 9; uv++) {
            int u = uv / 3, v = uv - 3 * u;
            int pA0 = (x0 + u) * 6 + (y0 + v);
            int pA1 = (x1 + u) * 6 + (y1 + v);
#pragma unroll 1
            for (int c = 0; c < 4; c++) {
                ull wr[8];
#pragma unroll
                for (int kk = 0; kk < 8; kk++)
                    wr[kk] = W2u[(uv * 32 + c * 8 + kk) * 16 + o];
                const ulonglong2* r0 = (const ulonglong2*)(A + pA0 * SROW) + c * 4;
                const ulonglong2* r1 = (const ulonglong2*)(A + pA1 * SROW) + c * 4;
#pragma unroll
                for (int k2 = 0; k2 < 4; k2++) {
                    ulonglong2 v0 = r0[k2], v1 = r1[k2];
                    a0 = fma2(wr[2 * k2 + 0], v0.x, a0);
                    a0 = fma2(wr[2 * k2 + 1], v0.y, a0);
                    a1 = fma2(wr[2 * k2 + 0], v1.x, a1);
                    a1 = fma2(wr[2 * k2 + 1], v1.y, a1);
                }
            }
        }
        Bv[o * 16 + pp0] = lrelu(psum(a0));
        Bv[o * 16 + pp1] = lrelu(psum(a1));
    }
    __syncthreads();
    if (tid < 144) {  // 2x2 maxpool stride 1 -> [16][3][3]
        int o = tid / 9, pp = tid - o * 9, x = pp / 3, y = pp - x * 3;
        float m0 = fmaxf(Bv[o * 16 + x * 4 + y], Bv[o * 16 + x * 4 + y + 1]);
        float m1 = fmaxf(Bv[o * 16 + (x + 1) * 4 + y], Bv[o * 16 + (x + 1) * 4 + y + 1]);
        g_enc[b * ENCD + DYND + tid] = fmaxf(m0, m1);
    } else if (tid >= 160 && tid < 192) {  // traj_enc
        int d = tid - 160;
        int r = obs_traj_idxs[15 * NN + b];
        const float* hf = g_Hs + r * ENCH;
        float acc = bdyn[d];
#pragma unroll
        for (int k = 0; k < 64; k++) acc = fmaf(hf[k], Wdyn[d * 64 + k], acc);
        g_enc[b * ENCD + d] = lrelu(acc);
    }
}

// ============================================================================
// K3: decoder LSTM. 96 blocks x 2 rows, 512 threads.
// Thread = (unit u = tid>>2, gate q = tid&3); quad shfl exchange; ONE barrier
// per step; h double-buffered in smem; c in registers.
// ============================================================================
#define D_W 0        // 49152 floats (k4 0..23)
#define D_ENC 49152  // 352
#define D_H 49504    // 512: [buf][row][128]
#define D_WOP 50016  // 640
#define D_BOP 50656  // 8
#define K3_SMEM (50664 * 4)

extern "C" __global__ void __launch_bounds__(512, 1)
k_decoder(const float* __restrict__ Wih_d, const float* __restrict__ bih_d,
          const float* __restrict__ bhh_d,
          const float* __restrict__ Wop, const float* __restrict__ bop,
          float* __restrict__ out) {
    extern __shared__ float dsm[];
    float* enc_s = dsm + D_ENC;
    float* wop_s = dsm + D_WOP;
    float* bop_s = dsm + D_BOP;
    const int tid = threadIdx.x;
    const int b0 = blockIdx.x * 2;
    const int q = tid & 3, u = tid >> 2;
    const int g = q * 128 + u;   // weight row in torch order

    {
        const float4* src4 = (const float4*)g_Whh4;
        float4* dst4 = (float4*)(dsm + D_W);
        for (int i = tid; i < 12288; i += 512) dst4[i] = src4[i];
    }
    for (int idx = tid; idx < 2 * ENCD; idx += 512)
        enc_s[idx] = g_enc[b0 * ENCD + idx];
    for (int idx = tid; idx < 640; idx += 512) wop_s[idx] = Wop[idx];
    if (tid < 5) bop_s[tid] = bop[tid];
    if (tid < 256) dsm[D_H + tid] = 0.f;   // zero h buffer 0 (both rows)

    ulonglong2 wst[8];
#pragma unroll
    for (int k = 0; k < 8; k++)
        wst[k] = ((const ulonglong2*)g_Whh4)[(24 + k) * 512 + tid];
    __syncthreads();

    float ez0, ez1;
    {
        float bb = bih_d[g] + bhh_d[g];
        ez0 = bb; ez1 = bb;
        const float4* wr = (const float4*)(Wih_d + g * ENCD);
#pragma unroll 4
        for (int k4 = 0; k4 < 44; k4++) {
            float4 w = wr[k4];
            ez0 = fmaf(w.x, enc_s[4 * k4 + 0], fmaf(w.y, enc_s[4 * k4 + 1],
                  fmaf(w.z, enc_s[4 * k4 + 2], fmaf(w.w, enc_s[4 * k4 + 3], ez0))));
            ez1 = fmaf(w.x, enc_s[ENCD + 4 * k4 + 0], fmaf(w.y, enc_s[ENCD + 4 * k4 + 1],
                  fmaf(w.z, enc_s[ENCD + 4 * k4 + 2], fmaf(w.w, enc_s[ENCD + 4 * k4 + 3], ez1))));
        }
    }

    float c0 = 0.f, c1 = 0.f;
    const bool q0b = (q & 1), q1b = (q & 2);

#pragma unroll 1
    for (int t = 0; t < T_PRED; t++) {
        const float* hr = dsm + D_H + (t & 1) * 256;
        float* hw = dsm + D_H + ((t & 1) ^ 1) * 256;
        ull a0 = pk2(ez0, 0.f), a1 = pk2(ez1, 0.f);
        {
            const ulonglong2* wsm = (const ulonglong2*)(dsm + D_W) + tid;
            const ulonglong2* h0p = (const ulonglong2*)hr;
            const ulonglong2* h1p = (const ulonglong2*)(hr + DECH);
#pragma unroll
            for (int k4 = 0; k4 < 24; k4++) {
                ulonglong2 w = wsm[k4 * 512];
                ulonglong2 v0 = h0p[k4], v1 = h1p[k4];
                a0 = fma2(w.x, v0.x, a0); a0 = fma2(w.y, v0.y, a0);
                a1 = fma2(w.x, v1.x, a1); a1 = fma2(w.y, v1.y, a1);
            }
#pragma unroll
            for (int k = 0; k < 8; k++) {
                ulonglong2 w = wst[k];
                ulonglong2 v0 = h0p[24 + k], v1 = h1p[24 + k];
                a0 = fma2(w.x, v0.x, a0); a0 = fma2(w.y, v0.y, a0);
                a1 = fma2(w.x, v1.x, a1); a1 = fma2(w.y, v1.y, a1);
            }
        }
        float z0 = psum(a0), z1 = psum(a1);
        // quad exchange: gather all 4 gates per lane
        float xa0 = z0, xb0 = __shfl_xor_sync(0xffffffffu, z0, 1);
        float xc0 = __shfl_xor_sync(0xffffffffu, xa0, 2);
        float xd0 = __shfl_xor_sync(0xffffffffu, xb0, 2);
        float xa1 = z1, xb1 = __shfl_xor_sync(0xffffffffu, z1, 1);
        float xc1 = __shfl_xor_sync(0xffffffffu, xa1, 2);
        float xd1 = __shfl_xor_sync(0xffffffffu, xb1, 2);
        float zi0 = q1b ? (q0b ? xd0 : xc0) : (q0b ? xb0 : xa0);
        float zf0 = q1b ? (q0b ? xc0 : xd0) : (q0b ? xa0 : xb0);
        float zg0 = q1b ? (q0b ? xb0 : xa0) : (q0b ? xd0 : xc0);
        float zo0 = q1b ? (q0b ? xa0 : xb0) : (q0b ? xc0 : xd0);
        float zi1 = q1b ? (q0b ? xd1 : xc1) : (q0b ? xb1 : xa1);
        float zf1 = q1b ? (q0b ? xc1 : xd1) : (q0b ? xa1 : xb1);
        float zg1 = q1b ? (q0b ? xb1 : xa1) : (q0b ? xd1 : xc1);
        float zo1 = q1b ? (q0b ? xa1 : xb1) : (q0b ? xc1 : xd1);
        c0 = fmaf(sigf(zf0), c0, sigf(zi0) * tanha(zg0));
        c1 = fmaf(sigf(zf1), c1, sigf(zi1) * tanha(zg1));
        float h0 = sigf(zo0) * tanha(c0);
        float h1 = sigf(zo1) * tanha(c1);
        if (q == 0) { hw[u] = h0; hw[DECH + u] = h1; }
        __syncthreads();
        if (tid < 10) {
            int r = tid / 5, oi = tid - r * 5;
            float acc = bop_s[oi];
            const float* hh = hw + r * DECH;
#pragma unroll
            for (int k = 0; k < DECH; k++) acc = fmaf(hh[k], wop_s[oi * DECH + k], acc);
            float val = (oi < 2) ? acc : ((oi < 4) ? __expf(acc) : tanha(acc));
            out[((size_t)t * NN + (b0 + r)) * 5 + oi] = val;
        }
    }
}

extern "C" void kernel_launch(void* const* d_in, const int* in_sizes, int n_in,
                              void* d_out, int out_size) {
    const float* obs  = (const float*)d_in[0];
    const float* ngb  = (const float*)d_in[1];
    const int* masks_idxs    = (const int*)d_in[3];
    const int* obs_traj_idxs = (const int*)d_in[4];
    const float* Wip   = (const float*)d_in[7];
    const float* bip   = (const float*)d_in[8];
    const float* Wih_e = (const float*)d_in[9];
    const float* Whh_e = (const float*)d_in[10];
    const float* bih_e = (const float*)d_in[11];
    const float* bhh_e = (const float*)d_in[12];
    const float* Wdyn  = (const float*)d_in[13];
    const float* bdyn  = (const float*)d_in[14];
    const float* Wc1   = (const float*)d_in[15];
    const float* bc1   = (const float*)d_in[16];
    const float* Wc2   = (const float*)d_in[17];
    const float* bc2   = (const float*)d_in[18];
    const float* Wih_d = (const float*)d_in[19];
    const float* Whh_d = (const float*)d_in[20];
    const float* bih_d = (const float*)d_in[21];
    const float* bhh_d = (const float*)d_in[22];
    const float* Wop   = (const float*)d_in[23];
    const float* bop   = (const float*)d_in[24];

    cudaFuncSetAttribute(k_encoder, cudaFuncAttributeMaxDynamicSharedMemorySize, K1_SMEM);
    cudaFuncSetAttribute(k_social, cudaFuncAttributeMaxDynamicSharedMemorySize, K2_SMEM);
    cudaFuncSetAttribute(k_decoder, cudaFuncAttributeMaxDynamicSharedMemorySize, K3_SMEM);

    k_prep<<<437, 256>>>(Whh_d, Wc1, Wc2);
    k_encoder<<<290, 256, K1_SMEM>>>(obs, ngb, Wip, bip, Wih_e, Whh_e, bih_e, bhh_e);
    k_social<<<192, 256, K2_SMEM>>>(masks_idxs, obs_traj_idxs, Wdyn, bdyn, bc1, bc2);
    k_decoder<<<96, 512, K3_SMEM>>>(Wih_d, bih_d, bhh_d, Wop, bop, (float*)d_out);
}

// round 11
// speedup vs baseline: 5.9050x; 1.7499x over previous
#include <cuda_runtime.h>
#include <cuda_bf16.h>
#include <cstdint>

#define T_OBS 16
#define T_PRED 25
#define NN 192
#define PP 36864
#define ENCH 64
#define DECH 128
#define DYND 32
#define ENCD 176   // DYN + SOC

typedef unsigned long long ull;

__device__ float g_Hn[(size_t)PP * ENCH];
__device__ float g_Hs[NN * ENCH];
__device__ float g_enc[NN * ENCD];
__device__ float g_Whh4[32 * 512 * 4];   // [k4][u*4+q][4]
__device__ float g_W1t[36864];           // [uv][i2][64 o] ull-packed
__device__ float g_W2t[9216];            // [uv][i2][16 o] ull-packed

__device__ __forceinline__ float lrelu(float x) { return fmaxf(x, 0.1f * x); }
__device__ __forceinline__ float tanha(float x) {
    float y; asm("tanh.approx.f32 %0,%1;" : "=f"(y) : "f"(x)); return y;
}
__device__ __forceinline__ float sigf(float x) { return fmaf(tanha(0.5f * x), 0.5f, 0.5f); }

__device__ __forceinline__ ull pk2(float lo, float hi) {
    ull r; asm("mov.b64 %0,{%1,%2};" : "=l"(r) : "f"(lo), "f"(hi)); return r;
}
__device__ __forceinline__ ull fma2(ull a, ull b, ull c) {
    ull d; asm("fma.rn.f32x2 %0,%1,%2,%3;" : "=l"(d) : "l"(a), "l"(b), "l"(c)); return d;
}
__device__ __forceinline__ float psum(ull v) {
    float a, b; asm("mov.b64 {%0,%1},%2;" : "=f"(a), "=f"(b) : "l"(v)); return a + b;
}
__device__ __forceinline__ uint32_t s2u(const void* p) {
    uint32_t a;
    asm("{ .reg .u64 t; cvta.to.shared.u64 t, %1; cvt.u32.u64 %0, t; }" : "=r"(a) : "l"(p));
    return a;
}
__device__ __forceinline__ uint32_t lds32(uint32_t a) {
    uint32_t v; asm volatile("ld.shared.b32 %0,[%1];" : "=r"(v) : "r"(a)); return v;
}
__device__ __forceinline__ void sts32(uint32_t a, uint32_t v) {
    asm volatile("st.shared.b32 [%0],%1;" :: "r"(a), "r"(v) : "memory");
}

#define LDM4(r, adr) \
    asm volatile("ldmatrix.sync.aligned.m8n8.x4.shared.b16 {%0,%1,%2,%3}, [%4];" \
        : "=r"((r)[0]), "=r"((r)[1]), "=r"((r)[2]), "=r"((r)[3]) : "r"(adr))

#define MMA(c, a, b0, b1) \
    asm volatile("mma.sync.aligned.m16n8k16.row.col.f32.bf16.bf16.f32 " \
        "{%0,%1,%2,%3}, {%4,%5,%6,%7}, {%8,%9}, {%0,%1,%2,%3};" \
        : "+f"((c)[0]), "+f"((c)[1]), "+f"((c)[2]), "+f"((c)[3]) \
        : "r"((a)[0]), "r"((a)[1]), "r"((a)[2]), "r"((a)[3]), "r"(b0), "r"(b1))

// ============================================================================
// K1: encoder LSTM via mma.sync bf16 3-term split. 290 blocks x 128 rows.
// Warp w owns units [8w,8w+8) x all 4 gates -> thread-local activation,
// c in regs, A (emb|h) double-buffered, ONE barrier per step.
// smem: BH 53248 | BL 53248 | Abuf0 53248 (hi+lo) | Abuf1 53248 | bias/wip/bip
// ============================================================================
#define RS 208
#define BH_OFF 0
#define BL_OFF 53248
#define ABUF_OFF 106496
#define ABUF_SZ 53248
#define ALO 26624
#define BIAS_OFF 212992
#define WIP_OFF 214016
#define BIP_OFF 214272
#define K1_SMEM 214400

extern "C" __global__ void __launch_bounds__(256, 1)
k_encoder(const float* __restrict__ obs, const float* __restrict__ ngb,
          const float* __restrict__ Wip, const float* __restrict__ bip,
          const float* __restrict__ Wih, const float* __restrict__ Whh,
          const float* __restrict__ bih, const float* __restrict__ bhh) {
    extern __shared__ __align__(16) char smb[];
    const int tid = threadIdx.x, lane = tid & 31, w = tid >> 5;
    const uint32_t sb = s2u(smb);
    float4* bias4 = (float4*)(smb + BIAS_OFF);
    float* wip_s = (float*)(smb + WIP_OFF);
    float* bip_s = (float*)(smb + BIP_OFF);

    // stage B hi/lo (row n = gate*64+unit, col k = [emb32|h64])
    for (int idx = tid; idx < 24576; idx += 256) {
        int n = idx / 96, k = idx - n * 96;
        float wv = (k < 32) ? Wih[n * 32 + k] : Whh[n * 64 + (k - 32)];
        __nv_bfloat16 hh = __float2bfloat16(wv);
        __nv_bfloat16 ll = __float2bfloat16(wv - __bfloat162float(hh));
        *(__nv_bfloat16*)(smb + BH_OFF + n * RS + 2 * k) = hh;
        *(__nv_bfloat16*)(smb + BL_OFF + n * RS + 2 * k) = ll;
    }
    // zero A buf 0 (hi+lo)
    for (int i = tid; i < ABUF_SZ / 4; i += 256)
        *(uint32_t*)(smb + ABUF_OFF + 4 * i) = 0;
    if (tid < 64) {
        bias4[tid] = make_float4(bih[tid] + bhh[tid], bih[64 + tid] + bhh[64 + tid],
                                 bih[128 + tid] + bhh[128 + tid], bih[192 + tid] + bhh[192 + tid]);
        wip_s[tid] = Wip[tid];
    }
    if (tid < 32) bip_s[tid] = bip[tid];
    __syncthreads();

    const int bx = blockIdx.x;
    const bool ego = (bx >= 288);
    const int row0 = ego ? (bx - 288) * 128 : bx * 128;
    const int nr = ego ? NN : PP;
    const float* src = ego ? obs : ngb;
    float* gH = ego ? g_Hs : g_Hn;

    // emb t=0 into buf0
    if (tid < 128) {
        int row = row0 + tid;
        float x0 = 0.f, x1 = 0.f;
        if (row < nr) {
            const float* px = src + ((size_t)0 * nr + row) * 2;
            x0 = px[0]; x1 = px[1];
        }
        uint32_t base = sb + ABUF_OFF + (uint32_t)tid * RS;
#pragma unroll
        for (int m2 = 0; m2 < 16; m2++) {
            float e0 = lrelu(fmaf(wip_s[4 * m2 + 0], x0, fmaf(wip_s[4 * m2 + 1], x1, bip_s[2 * m2 + 0])));
            float e1 = lrelu(fmaf(wip_s[4 * m2 + 2], x0, fmaf(wip_s[4 * m2 + 3], x1, bip_s[2 * m2 + 1])));
            __nv_bfloat16 h0 = __float2bfloat16(e0), h1 = __float2bfloat16(e1);
            uint32_t hp = (uint32_t)__bfloat16_as_ushort(h0) | ((uint32_t)__bfloat16_as_ushort(h1) << 16);
            __nv_bfloat16 l0 = __float2bfloat16(e0 - __bfloat162float(h0));
            __nv_bfloat16 l1 = __float2bfloat16(e1 - __bfloat162float(h1));
            uint32_t lp = (uint32_t)__bfloat16_as_ushort(l0) | ((uint32_t)__bfloat16_as_ushort(l1) << 16);
            sts32(base + 4 * m2, hp);
            sts32(base + ALO + 4 * m2, lp);
        }
    }
    __syncthreads();

    const int gid = lane >> 2, tig = lane & 3;
    const int u0 = 8 * w + 2 * tig;
    const uint32_t ldmoff = (uint32_t)(((lane & 7) + ((lane >> 3) & 1) * 8) * RS + (lane >> 4) * 16);
    const float4 ba = bias4[u0], bb = bias4[u0 + 1];

    float c[8][2][2];
#pragma unroll
    for (int a = 0; a < 8; a++)
#pragma unroll
        for (int r = 0; r < 2; r++) { c[a][r][0] = 0.f; c[a][r][1] = 0.f; }

    int p = 0;
#pragma unroll 1
    for (int t = 0; t < T_OBS; t++) {
        const uint32_t Abase = sb + ABUF_OFF + (uint32_t)p * ABUF_SZ;
        const uint32_t Wbase = sb + ABUF_OFF + (uint32_t)(p ^ 1) * ABUF_SZ;
#pragma unroll
        for (int mh = 0; mh < 2; mh++) {
            float acc[4][4][4];
#pragma unroll
            for (int mt = 0; mt < 4; mt++)
#pragma unroll
                for (int q = 0; q < 4; q++)
#pragma unroll
                    for (int e = 0; e < 4; e++) acc[mt][q][e] = 0.f;
#pragma unroll
            for (int k = 0; k < 6; k++) {
                uint32_t ah[4][4], al[4][4];
#pragma unroll
                for (int mt = 0; mt < 4; mt++) {
                    uint32_t adr = Abase + (uint32_t)((mh * 64 + mt * 16) * RS + k * 32) + ldmoff;
                    LDM4(ah[mt], adr);
                    LDM4(al[mt], adr + ALO);
                }
#pragma unroll
                for (int q = 0; q < 4; q++) {
                    uint32_t baddr = sb + BH_OFF + (uint32_t)((q * 64 + 8 * w + gid) * RS + k * 32 + tig * 4);
                    uint32_t bh0 = lds32(baddr), bh1 = lds32(baddr + 16);
                    uint32_t bl0 = lds32(baddr + BL_OFF), bl1 = lds32(baddr + BL_OFF + 16);
#pragma unroll
                    for (int mt = 0; mt < 4; mt++) {
                        MMA(acc[mt][q], ah[mt], bh0, bh1);
                        MMA(acc[mt][q], ah[mt], bl0, bl1);
                        MMA(acc[mt][q], al[mt], bh0, bh1);
                    }
                }
            }
            // activation + h write
#pragma unroll
            for (int mt = 0; mt < 4; mt++)
#pragma unroll
            for (int rr = 0; rr < 2; rr++) {
                int row = mh * 64 + mt * 16 + gid + rr * 8;
                float hv[2];
#pragma unroll
                for (int cc = 0; cc < 2; cc++) {
                    int e = rr * 2 + cc;
                    float zi = acc[mt][0][e] + (cc ? bb.x : ba.x);
                    float zf = acc[mt][1][e] + (cc ? bb.y : ba.y);
                    float zg = acc[mt][2][e] + (cc ? bb.z : ba.z);
                    float zo = acc[mt][3][e] + (cc ? bb.w : ba.w);
                    int ci = mh * 4 + mt;
                    float cn = fmaf(sigf(zf), c[ci][rr][cc], sigf(zi) * tanha(zg));
                    c[ci][rr][cc] = cn;
                    hv[cc] = sigf(zo) * tanha(cn);
                }
                if (t < T_OBS - 1) {
                    __nv_bfloat16 h0 = __float2bfloat16(hv[0]), h1 = __float2bfloat16(hv[1]);
                    uint32_t hp = (uint32_t)__bfloat16_as_ushort(h0) | ((uint32_t)__bfloat16_as_ushort(h1) << 16);
                    __nv_bfloat16 l0 = __float2bfloat16(hv[0] - __bfloat162float(h0));
                    __nv_bfloat16 l1 = __float2bfloat16(hv[1] - __bfloat162float(h1));
                    uint32_t lp = (uint32_t)__bfloat16_as_ushort(l0) | ((uint32_t)__bfloat16_as_ushort(l1) << 16);
                    uint32_t ha = Wbase + (uint32_t)(row * RS + 64 + 2 * u0);
                    sts32(ha, hp);
                    sts32(ha + ALO, lp);
                } else {
                    int grow = row0 + row;
                    if (grow < nr) {
                        float2 v2; v2.x = hv[0]; v2.y = hv[1];
                        *(float2*)(gH + (size_t)grow * 64 + u0) = v2;
                    }
                }
            }
        }
        // emb for t+1 into buf p^1
        if (t < T_OBS - 1 && tid < 128) {
            int row = row0 + tid;
            float x0 = 0.f, x1 = 0.f;
            if (row < nr) {
                const float* px = src + ((size_t)(t + 1) * nr + row) * 2;
                x0 = px[0]; x1 = px[1];
            }
            uint32_t base = Wbase + (uint32_t)tid * RS;
#pragma unroll
            for (int m2 = 0; m2 < 16; m2++) {
                float e0 = lrelu(fmaf(wip_s[4 * m2 + 0], x0, fmaf(wip_s[4 * m2 + 1], x1, bip_s[2 * m2 + 0])));
                float e1 = lrelu(fmaf(wip_s[4 * m2 + 2], x0, fmaf(wip_s[4 * m2 + 3], x1, bip_s[2 * m2 + 1])));
                __nv_bfloat16 h0 = __float2bfloat16(e0), h1 = __float2bfloat16(e1);
                uint32_t hp = (uint32_t)__bfloat16_as_ushort(h0) | ((uint32_t)__bfloat16_as_ushort(h1) << 16);
                __nv_bfloat16 l0 = __float2bfloat16(e0 - __bfloat162float(h0));
                __nv_bfloat16 l1 = __float2bfloat16(e1 - __bfloat162float(h1));
                uint32_t lp = (uint32_t)__bfloat16_as_ushort(l0) | ((uint32_t)__bfloat16_as_ushort(l1) << 16);
                sts32(base + 4 * m2, hp);
                sts32(base + ALO + 4 * m2, lp);
            }
        }
        __syncthreads();
        p ^= 1;
    }
}

// ============================================================================
// K_prep: weight transposes (unchanged from R10).
// ============================================================================
extern "C" __global__ void k_prep(const float* __restrict__ Whh_d,
                                  const float* __restrict__ Wc1,
                                  const float* __restrict__ Wc2) {
    int idx = blockIdx.x * 256 + threadIdx.x;
    if (idx < 65536) {
        int g = idx >> 7, k = idx & 127;
        int cg = g >> 7, uu = g & 127;
        int t = uu * 4 + cg;
        g_Whh4[(k >> 2) * 2048 + t * 4 + (k & 3)] = Whh_d[idx];
    } else if (idx < 102400) {
        int g2 = idx - 65536;
        int o = g2 / 576, rem = g2 - o * 576, i = rem / 9, uv = rem - i * 9;
        g_W1t[((uv * 32 + (i >> 1)) * 64 + o) * 2 + (i & 1)] = Wc1[g2];
    } else if (idx < 111616) {
        int g2 = idx - 102400;
        int o = g2 / 576, rem = g2 - o * 576, i = rem / 9, uv = rem - i * 9;
        g_W2t[((uv * 32 + (i >> 1)) * 16 + o) * 2 + (i & 1)] = Wc2[g2];
    }
}

// ============================================================================
// K2: social pipeline (unchanged from R10).
// ============================================================================
#define SROW 68
#define K2_SMEM (53136 * 4)

extern "C" __global__ void __launch_bounds__(256, 1)
k_social(const int* __restrict__ masks_idxs, const int* __restrict__ obs_traj_idxs,
         const float* __restrict__ Wdyn, const float* __restrict__ bdyn,
         const float* __restrict__ bc1, const float* __restrict__ bc2) {
    extern __shared__ float sm[];
    float* S = sm;
    float* A = sm + 4352;
    float* W1T = sm + 6800;
    float* W2T = sm + 43664;
    float* Bv = sm + 52880;
    const int b = blockIdx.x, tid = threadIdx.x;
    const int lane = tid & 31, wrp = tid >> 5;

    {
        const float4* s4 = (const float4*)g_W1t;
        float4* d4 = (float4*)W1T;
        for (int i = tid; i < 9216; i += 256) d4[i] = s4[i];
        const float4* s2 = (const float4*)g_W2t;
        float4* d2 = (float4*)W2T;
        for (int i = tid; i < 2304; i += 256) d2[i] = s2[i];
    }
    for (int idx = tid; idx < 4096; idx += 256) {
        int i = idx & 63, pos = idx >> 6, x = pos >> 3, y = pos & 7;
        int r = masks_idxs[b * 64 + y * 8 + x];
        S[pos * SROW + i] = g_Hn[(size_t)r * 64 + i];
    }
    __syncthreads();

    {
        const int o = ((wrp >> 2) << 5) + lane;
        const int ws = wrp & 3;
        int xj[9], yj[9];
#pragma unroll
        for (int j = 0; j < 9; j++) {
            int pj = ws + 4 * j;
            xj[j] = pj / 6; yj[j] = pj - 6 * xj[j];
        }
        ull acc[9];
        float bbv = __ldg(bc1 + o);
#pragma unroll
        for (int j = 0; j < 9; j++) acc[j] = pk2(bbv, 0.f);
        const ull* W1u = (const ull*)W1T;
#pragma unroll 1
        for (int uv = 0; uv < 9; uv++) {
            int u = uv / 3, v = uv - 3 * u;
            int px[9];
#pragma unroll
            for (int j = 0; j < 9; j++) px[j] = (xj[j] + u) * 8 + (yj[j] + v);
#pragma unroll 1
            for (int cc = 0; cc < 4; cc++) {
                ull wr[8];
#pragma unroll
                for (int kk = 0; kk < 8; kk++)
                    wr[kk] = W1u[(uv * 32 + cc * 8 + kk) * 64 + o];
#pragma unroll
                for (int j = 0; j < 9; j++) {
                    const ulonglong2* sr = (const ulonglong2*)(S + px[j] * SROW) + cc * 4;
#pragma unroll
                    for (int k2 = 0; k2 < 4; k2++) {
                        ulonglong2 sv = sr[k2];
                        acc[j] = fma2(wr[2 * k2 + 0], sv.x, acc[j]);
                        acc[j] = fma2(wr[2 * k2 + 1], sv.y, acc[j]);
                    }
                }
            }
        }
#pragma unroll
        for (int j = 0; j < 9; j++)
            A[(ws + 4 * j) * SROW + o] = lrelu(psum(acc[j]));
    }
    __syncthreads();

    if (tid < 128) {
        const int w2 = tid >> 5;
        const int o = lane & 15;
        const int pg = w2 * 2 + (lane >> 4);
        const int pp0 = pg * 2, pp1 = pg * 2 + 1;
        const int x0 = pp0 >> 2, y0 = pp0 & 3;
        const int x1 = pp1 >> 2, y1 = pp1 & 3;
        float bbv = __ldg(bc2 + o);
        ull a0 = pk2(bbv, 0.f), a1 = pk2(bbv, 0.f);
        const ull* W2u = (const ull*)W2T;
#pragma unroll 1
        for (int uv = 0; uv < 9; uv++) {
            int u = uv / 3, v = uv - 3 * u;
            int pA0 = (x0 + u) * 6 + (y0 + v);
            int pA1 = (x1 + u) * 6 + (y1 + v);
#pragma unroll 1
            for (int cc = 0; cc < 4; cc++) {
                ull wr[8];
#pragma unroll
                for (int kk = 0; kk < 8; kk++)
                    wr[kk] = W2u[(uv * 32 + cc * 8 + kk) * 16 + o];
                const ulonglong2* r0 = (const ulonglong2*)(A + pA0 * SROW) + cc * 4;
                const ulonglong2* r1 = (const ulonglong2*)(A + pA1 * SROW) + cc * 4;
#pragma unroll
                for (int k2 = 0; k2 < 4; k2++) {
                    ulonglong2 v0 = r0[k2], v1 = r1[k2];
                    a0 = fma2(wr[2 * k2 + 0], v0.x, a0);
                    a0 = fma2(wr[2 * k2 + 1], v0.y, a0);
                    a1 = fma2(wr[2 * k2 + 0], v1.x, a1);
                    a1 = fma2(wr[2 * k2 + 1], v1.y, a1);
                }
            }
        }
        Bv[o * 16 + pp0] = lrelu(psum(a0));
        Bv[o * 16 + pp1] = lrelu(psum(a1));
    }
    __syncthreads();
    if (tid < 144) {
        int o = tid / 9, pp = tid - o * 9, x = pp / 3, y = pp - x * 3;
        float m0 = fmaxf(Bv[o * 16 + x * 4 + y], Bv[o * 16 + x * 4 + y + 1]);
        float m1 = fmaxf(Bv[o * 16 + (x + 1) * 4 + y], Bv[o * 16 + (x + 1) * 4 + y + 1]);
        g_enc[b * ENCD + DYND + tid] = fmaxf(m0, m1);
    } else if (tid >= 160 && tid < 192) {
        int d = tid - 160;
        int r = obs_traj_idxs[15 * NN + b];
        const float* hf = g_Hs + r * ENCH;
        float acc = bdyn[d];
#pragma unroll
        for (int k = 0; k < 64; k++) acc = fmaf(hf[k], Wdyn[d * 64 + k], acc);
        g_enc[b * ENCD + d] = lrelu(acc);
    }
}

// ============================================================================
// K3: decoder LSTM (unchanged from R10).
// ============================================================================
#define D_W 0
#define D_ENC 49152
#define D_H 49504
#define D_WOP 50016
#define D_BOP 50656
#define K3_SMEM (50664 * 4)

extern "C" __global__ void __launch_bounds__(512, 1)
k_decoder(const float* __restrict__ Wih_d, const float* __restrict__ bih_d,
          const float* __restrict__ bhh_d,
          const float* __restrict__ Wop, const float* __restrict__ bop,
          float* __restrict__ out) {
    extern __shared__ float dsm[];
    float* enc_s = dsm + D_ENC;
    float* wop_s = dsm + D_WOP;
    float* bop_s = dsm + D_BOP;
    const int tid = threadIdx.x;
    const int b0 = blockIdx.x * 2;
    const int q = tid & 3, u = tid >> 2;
    const int g = q * 128 + u;

    {
        const float4* src4 = (const float4*)g_Whh4;
        float4* dst4 = (float4*)(dsm + D_W);
        for (int i = tid; i < 12288; i += 512) dst4[i] = src4[i];
    }
    for (int idx = tid; idx < 2 * ENCD; idx += 512)
        enc_s[idx] = g_enc[b0 * ENCD + idx];
    for (int idx = tid; idx < 640; idx += 512) wop_s[idx] = Wop[idx];
    if (tid < 5) bop_s[tid] = bop[tid];
    if (tid < 256) dsm[D_H + tid] = 0.f;

    ulonglong2 wst[8];
#pragma unroll
    for (int k = 0; k < 8; k++)
        wst[k] = ((const ulonglong2*)g_Whh4)[(24 + k) * 512 + tid];
    __syncthreads();

    float ez0, ez1;
    {
        float bbv = bih_d[g] + bhh_d[g];
        ez0 = bbv; ez1 = bbv;
        const float4* wr = (const float4*)(Wih_d + g * ENCD);
#pragma unroll 4
        for (int k4 = 0; k4 < 44; k4++) {
            float4 wv = wr[k4];
            ez0 = fmaf(wv.x, enc_s[4 * k4 + 0], fmaf(wv.y, enc_s[4 * k4 + 1],
                  fmaf(wv.z, enc_s[4 * k4 + 2], fmaf(wv.w, enc_s[4 * k4 + 3], ez0))));
            ez1 = fmaf(wv.x, enc_s[ENCD + 4 * k4 + 0], fmaf(wv.y, enc_s[ENCD + 4 * k4 + 1],
                  fmaf(wv.z, enc_s[ENCD + 4 * k4 + 2], fmaf(wv.w, enc_s[ENCD + 4 * k4 + 3], ez1))));
        }
    }

    float c0 = 0.f, c1 = 0.f;
    const bool q0b = (q & 1), q1b = (q & 2);

#pragma unroll 1
    for (int t = 0; t < T_PRED; t++) {
        const float* hr = dsm + D_H + (t & 1) * 256;
        float* hw = dsm + D_H + ((t & 1) ^ 1) * 256;
        ull a0 = pk2(ez0, 0.f), a1 = pk2(ez1, 0.f);
        {
            const ulonglong2* wsm = (const ulonglong2*)(dsm + D_W) + tid;
            const ulonglong2* h0p = (const ulonglong2*)hr;
            const ulonglong2* h1p = (const ulonglong2*)(hr + DECH);
#pragma unroll
            for (int k4 = 0; k4 < 24; k4++) {
                ulonglong2 wv = wsm[k4 * 512];
                ulonglong2 v0 = h0p[k4], v1 = h1p[k4];
                a0 = fma2(wv.x, v0.x, a0); a0 = fma2(wv.y, v0.y, a0);
                a1 = fma2(wv.x, v1.x, a1); a1 = fma2(wv.y, v1.y, a1);
            }
#pragma unroll
            for (int k = 0; k < 8; k++) {
                ulonglong2 wv = wst[k];
                ulonglong2 v0 = h0p[24 + k], v1 = h1p[24 + k];
                a0 = fma2(wv.x, v0.x, a0); a0 = fma2(wv.y, v0.y, a0);
                a1 = fma2(wv.x, v1.x, a1); a1 = fma2(wv.y, v1.y, a1);
            }
        }
        float z0 = psum(a0), z1 = psum(a1);
        float xa0 = z0, xb0 = __shfl_xor_sync(0xffffffffu, z0, 1);
        float xc0 = __shfl_xor_sync(0xffffffffu, xa0, 2);
        float xd0 = __shfl_xor_sync(0xffffffffu, xb0, 2);
        float xa1 = z1, xb1 = __shfl_xor_sync(0xffffffffu, z1, 1);
        float xc1 = __shfl_xor_sync(0xffffffffu, xa1, 2);
        float xd1 = __shfl_xor_sync(0xffffffffu, xb1, 2);
        float zi0 = q1b ? (q0b ? xd0 : xc0) : (q0b ? xb0 : xa0);
        float zf0 = q1b ? (q0b ? xc0 : xd0) : (q0b ? xa0 : xb0);
        float zg0 = q1b ? (q0b ? xb0 : xa0) : (q0b ? xd0 : xc0);
        float zo0 = q1b ? (q0b ? xa0 : xb0) : (q0b ? xc0 : xd0);
        float zi1 = q1b ? (q0b ? xd1 : xc1) : (q0b ? xb1 : xa1);
        float zf1 = q1b ? (q0b ? xc1 : xd1) : (q0b ? xa1 : xb1);
        float zg1 = q1b ? (q0b ? xb1 : xa1) : (q0b ? xd1 : xc1);
        float zo1 = q1b ? (q0b ? xa1 : xb1) : (q0b ? xc1 : xd1);
        c0 = fmaf(sigf(zf0), c0, sigf(zi0) * tanha(zg0));
        c1 = fmaf(sigf(zf1), c1, sigf(zi1) * tanha(zg1));
        float h0 = sigf(zo0) * tanha(c0);
        float h1 = sigf(zo1) * tanha(c1);
        if (q == 0) { hw[u] = h0; hw[DECH + u] = h1; }
        __syncthreads();
        if (tid < 10) {
            int r = tid / 5, oi = tid - r * 5;
            float acc = bop_s[oi];
            const float* hh = hw + r * DECH;
#pragma unroll
            for (int k = 0; k < DECH; k++) acc = fmaf(hh[k], wop_s[oi * DECH + k], acc);
            float val = (oi < 2) ? acc : ((oi < 4) ? __expf(acc) : tanha(acc));
            out[((size_t)t * NN + (b0 + r)) * 5 + oi] = val;
        }
    }
}

extern "C" void kernel_launch(void* const* d_in, const int* in_sizes, int n_in,
                              void* d_out, int out_size) {
    const float* obs  = (const float*)d_in[0];
    const float* ngb  = (const float*)d_in[1];
    const int* masks_idxs    = (const int*)d_in[3];
    const int* obs_traj_idxs = (const int*)d_in[4];
    const float* Wip   = (const float*)d_in[7];
    const float* bip   = (const float*)d_in[8];
    const float* Wih_e = (const float*)d_in[9];
    const float* Whh_e = (const float*)d_in[10];
    const float* bih_e = (const float*)d_in[11];
    const float* bhh_e = (const float*)d_in[12];
    const float* Wdyn  = (const float*)d_in[13];
    const float* bdyn  = (const float*)d_in[14];
    const float* Wc1   = (const float*)d_in[15];
    const float* bc1   = (const float*)d_in[16];
    const float* Wc2   = (const float*)d_in[17];
    const float* bc2   = (const float*)d_in[18];
    const float* Wih_d = (const float*)d_in[19];
    const float* Whh_d = (const float*)d_in[20];
    const float* bih_d = (const float*)d_in[21];
    const float* bhh_d = (const float*)d_in[22];
    const float* Wop   = (const float*)d_in[23];
    const float* bop   = (const float*)d_in[24];

    cudaFuncSetAttribute(k_encoder, cudaFuncAttributeMaxDynamicSharedMemorySize, K1_SMEM);
    cudaFuncSetAttribute(k_social, cudaFuncAttributeMaxDynamicSharedMemorySize, K2_SMEM);
    cudaFuncSetAttribute(k_decoder, cudaFuncAttributeMaxDynamicSharedMemorySize, K3_SMEM);

    k_prep<<<437, 256>>>(Whh_d, Wc1, Wc2);
    k_encoder<<<290, 256, K1_SMEM>>>(obs, ngb, Wip, bip, Wih_e, Whh_e, bih_e, bhh_e);
    k_social<<<192, 256, K2_SMEM>>>(masks_idxs, obs_traj_idxs, Wdyn, bdyn, bc1, bc2);
    k_decoder<<<96, 512, K3_SMEM>>>(Wih_d, bih_d, bhh_d, Wop, bop, (float*)d_out);
}

// round 13
// speedup vs baseline: 7.2595x; 1.2294x over previous
#include <cuda_runtime.h>
#include <cuda_bf16.h>
#include <cuda_fp16.h>
#include <cstdint>

#define T_OBS 16
#define T_PRED 25
#define NN 192
#define PP 36864
#define ENCH 64
#define DECH 128
#define DYND 32
#define ENCD 176   // DYN + SOC

typedef unsigned long long ull;

__device__ float g_Hn[(size_t)PP * ENCH];
__device__ float g_Hs[NN * ENCH];
__device__ float g_enc[NN * ENCD];
__device__ float g_Whh4[32 * 512 * 4];   // [k4][u*4+q][4]
__device__ float g_W1t[36864];           // [uv][i2][64 o] ull-packed
__device__ float g_W2t[9216];            // [uv][i2][16 o] ull-packed

__device__ __forceinline__ float lrelu(float x) { return fmaxf(x, 0.1f * x); }
__device__ __forceinline__ float tanha(float x) {
    float y; asm("tanh.approx.f32 %0,%1;" : "=f"(y) : "f"(x)); return y;
}
__device__ __forceinline__ float sigf(float x) { return fmaf(tanha(0.5f * x), 0.5f, 0.5f); }

__device__ __forceinline__ ull pk2(float lo, float hi) {
    ull r; asm("mov.b64 %0,{%1,%2};" : "=l"(r) : "f"(lo), "f"(hi)); return r;
}
__device__ __forceinline__ ull fma2(ull a, ull b, ull c) {
    ull d; asm("fma.rn.f32x2 %0,%1,%2,%3;" : "=l"(d) : "l"(a), "l"(b), "l"(c)); return d;
}
__device__ __forceinline__ float psum(ull v) {
    float a, b; asm("mov.b64 {%0,%1},%2;" : "=f"(a), "=f"(b) : "l"(v)); return a + b;
}
__device__ __forceinline__ uint32_t s2u(const void* p) {
    uint32_t a;
    asm("{ .reg .u64 t; cvta.to.shared.u64 t, %1; cvt.u32.u64 %0, t; }" : "=r"(a) : "l"(p));
    return a;
}
__device__ __forceinline__ uint32_t lds32(uint32_t a) {
    uint32_t v; asm volatile("ld.shared.b32 %0,[%1];" : "=r"(v) : "r"(a)); return v;
}
__device__ __forceinline__ void sts32(uint32_t a, uint32_t v) {
    asm volatile("st.shared.b32 [%0],%1;" :: "r"(a), "r"(v) : "memory");
}
__device__ __forceinline__ uint32_t h2pack(float a, float b) {
    __half ha = __float2half_rn(a), hb = __float2half_rn(b);
    return (uint32_t)__half_as_ushort(ha) | ((uint32_t)__half_as_ushort(hb) << 16);
}

#define LDM4(r, adr) \
    asm volatile("ldmatrix.sync.aligned.m8n8.x4.shared.b16 {%0,%1,%2,%3}, [%4];" \
        : "=r"((r)[0]), "=r"((r)[1]), "=r"((r)[2]), "=r"((r)[3]) : "r"(adr))

#define MMA(c, a, b0, b1) \
    asm volatile("mma.sync.aligned.m16n8k16.row.col.f32.f16.f16.f32 " \
        "{%0,%1,%2,%3}, {%4,%5,%6,%7}, {%8,%9}, {%0,%1,%2,%3};" \
        : "+f"((c)[0]), "+f"((c)[1]), "+f"((c)[2]), "+f"((c)[3]) \
        : "r"((a)[0]), "r"((a)[1]), "r"((a)[2]), "r"((a)[3]), "r"(b0), "r"(b1))

// ============================================================================
// K1: encoder LSTM via mma.sync fp16, B split hi/lo (2 terms), A single fp16.
// 290 blocks x 128 rows. Warp w owns units [8w,8w+8) x all 4 gates.
// smem: BH 53248 | BL 53248 | Abuf0 26624 | Abuf1 26624 | bias/wip/bip
// ============================================================================
#define RS 208
#define BH_OFF 0
#define BL_OFF 53248
#define ABUF_OFF 106496
#define ABUF_SZ 26624
#define BIAS_OFF 159744
#define WIP_OFF 160768
#define BIP_OFF 161024
#define K1_SMEM 161280

extern "C" __global__ void __launch_bounds__(256, 1)
k_encoder(const float* __restrict__ obs, const float* __restrict__ ngb,
          const float* __restrict__ Wip, const float* __restrict__ bip,
          const float* __restrict__ Wih, const float* __restrict__ Whh,
          const float* __restrict__ bih, const float* __restrict__ bhh) {
    extern __shared__ __align__(16) char smb[];
    const int tid = threadIdx.x, lane = tid & 31, w = tid >> 5;
    const uint32_t sb = s2u(smb);
    float4* bias4 = (float4*)(smb + BIAS_OFF);
    float* wip_s = (float*)(smb + WIP_OFF);
    float* bip_s = (float*)(smb + BIP_OFF);

    // stage B hi/lo fp16 (row n = gate*64+unit, col k = [emb32|h64])
    for (int idx = tid; idx < 24576; idx += 256) {
        int n = idx / 96, k = idx - n * 96;
        float wv = (k < 32) ? Wih[n * 32 + k] : Whh[n * 64 + (k - 32)];
        __half hh = __float2half_rn(wv);
        __half ll = __float2half_rn(wv - __half2float(hh));
        *(__half*)(smb + BH_OFF + n * RS + 2 * k) = hh;
        *(__half*)(smb + BL_OFF + n * RS + 2 * k) = ll;
    }
    for (int i = tid; i < ABUF_SZ / 4; i += 256)
        *(uint32_t*)(smb + ABUF_OFF + 4 * i) = 0;
    if (tid < 64) {
        bias4[tid] = make_float4(bih[tid] + bhh[tid], bih[64 + tid] + bhh[64 + tid],
                                 bih[128 + tid] + bhh[128 + tid], bih[192 + tid] + bhh[192 + tid]);
        wip_s[tid] = Wip[tid];
    }
    if (tid < 32) bip_s[tid] = bip[tid];
    __syncthreads();

    const int bx = blockIdx.x;
    const bool ego = (bx >= 288);
    const int row0 = ego ? (bx - 288) * 128 : bx * 128;
    const int nr = ego ? NN : PP;
    const float* src = ego ? obs : ngb;
    float* gH = ego ? g_Hs : g_Hn;

    // emb t=0 into buf0
    if (tid < 128) {
        int row = row0 + tid;
        float x0 = 0.f, x1 = 0.f;
        if (row < nr) {
            const float* px = src + ((size_t)0 * nr + row) * 2;
            x0 = px[0]; x1 = px[1];
        }
        uint32_t base = sb + ABUF_OFF + (uint32_t)tid * RS;
#pragma unroll
        for (int m2 = 0; m2 < 16; m2++) {
            float e0 = lrelu(fmaf(wip_s[4 * m2 + 0], x0, fmaf(wip_s[4 * m2 + 1], x1, bip_s[2 * m2 + 0])));
            float e1 = lrelu(fmaf(wip_s[4 * m2 + 2], x0, fmaf(wip_s[4 * m2 + 3], x1, bip_s[2 * m2 + 1])));
            sts32(base + 4 * m2, h2pack(e0, e1));
        }
    }
    __syncthreads();

    const int gid = lane >> 2, tig = lane & 3;
    const int u0 = 8 * w + 2 * tig;
    const uint32_t ldmoff = (uint32_t)(((lane & 7) + ((lane >> 3) & 1) * 8) * RS + (lane >> 4) * 16);
    const float4 ba = bias4[u0], bb = bias4[u0 + 1];

    float c[8][2][2];
#pragma unroll
    for (int a = 0; a < 8; a++)
#pragma unroll
        for (int r = 0; r < 2; r++) { c[a][r][0] = 0.f; c[a][r][1] = 0.f; }

    int p = 0;
#pragma unroll 1
    for (int t = 0; t < T_OBS; t++) {
        const uint32_t Abase = sb + ABUF_OFF + (uint32_t)p * ABUF_SZ;
        const uint32_t Wbase = sb + ABUF_OFF + (uint32_t)(p ^ 1) * ABUF_SZ;
#pragma unroll
        for (int mh = 0; mh < 2; mh++) {
            float acc[4][4][4];
#pragma unroll
            for (int mt = 0; mt < 4; mt++)
#pragma unroll
                for (int q = 0; q < 4; q++)
#pragma unroll
                    for (int e = 0; e < 4; e++) acc[mt][q][e] = 0.f;
#pragma unroll
            for (int k = 0; k < 6; k++) {
                uint32_t ah[4][4];
#pragma unroll
                for (int mt = 0; mt < 4; mt++) {
                    uint32_t adr = Abase + (uint32_t)((mh * 64 + mt * 16) * RS + k * 32) + ldmoff;
                    LDM4(ah[mt], adr);
                }
#pragma unroll
                for (int q = 0; q < 4; q++) {
                    uint32_t baddr = sb + BH_OFF + (uint32_t)((q * 64 + 8 * w + gid) * RS + k * 32 + tig * 4);
                    uint32_t bh0 = lds32(baddr), bh1 = lds32(baddr + 16);
                    uint32_t bl0 = lds32(baddr + BL_OFF), bl1 = lds32(baddr + BL_OFF + 16);
#pragma unroll
                    for (int mt = 0; mt < 4; mt++) {
                        MMA(acc[mt][q], ah[mt], bh0, bh1);
                        MMA(acc[mt][q], ah[mt], bl0, bl1);
                    }
                }
            }
            // activation + h write
#pragma unroll
            for (int mt = 0; mt < 4; mt++)
#pragma unroll
            for (int rr = 0; rr < 2; rr++) {
                int row = mh * 64 + mt * 16 + gid + rr * 8;
                float hv[2];
#pragma unroll
                for (int cc = 0; cc < 2; cc++) {
                    int e = rr * 2 + cc;
                    float zi = acc[mt][0][e] + (cc ? bb.x : ba.x);
                    float zf = acc[mt][1][e] + (cc ? bb.y : ba.y);
                    float zg = acc[mt][2][e] + (cc ? bb.z : ba.z);
                    float zo = acc[mt][3][e] + (cc ? bb.w : ba.w);
                    int ci = mh * 4 + mt;
                    float cn = fmaf(sigf(zf), c[ci][rr][cc], sigf(zi) * tanha(zg));
                    c[ci][rr][cc] = cn;
                    hv[cc] = sigf(zo) * tanha(cn);
                }
                if (t < T_OBS - 1) {
                    uint32_t ha = Wbase + (uint32_t)(row * RS + 64 + 2 * u0);
                    sts32(ha, h2pack(hv[0], hv[1]));
                } else {
                    int grow = row0 + row;
                    if (grow < nr) {
                        float2 v2; v2.x = hv[0]; v2.y = hv[1];
                        *(float2*)(gH + (size_t)grow * 64 + u0) = v2;
                    }
                }
            }
        }
        // emb for t+1 into buf p^1
        if (t < T_OBS - 1 && tid < 128) {
            int row = row0 + tid;
            float x0 = 0.f, x1 = 0.f;
            if (row < nr) {
                const float* px = src + ((size_t)(t + 1) * nr + row) * 2;
                x0 = px[0]; x1 = px[1];
            }
            uint32_t base = Wbase + (uint32_t)tid * RS;
#pragma unroll
            for (int m2 = 0; m2 < 16; m2++) {
                float e0 = lrelu(fmaf(wip_s[4 * m2 + 0], x0, fmaf(wip_s[4 * m2 + 1], x1, bip_s[2 * m2 + 0])));
                float e1 = lrelu(fmaf(wip_s[4 * m2 + 2], x0, fmaf(wip_s[4 * m2 + 3], x1, bip_s[2 * m2 + 1])));
                sts32(base + 4 * m2, h2pack(e0, e1));
            }
        }
        __syncthreads();
        p ^= 1;
    }
}

// ============================================================================
// K_prep: weight transposes (unchanged).
// ============================================================================
extern "C" __global__ void k_prep(const float* __restrict__ Whh_d,
                                  const float* __restrict__ Wc1,
                                  const float* __restrict__ Wc2) {
    int idx = blockIdx.x * 256 + threadIdx.x;
    if (idx < 65536) {
        int g = idx >> 7, k = idx & 127;
        int cg = g >> 7, uu = g & 127;
        int t = uu * 4 + cg;
        g_Whh4[(k >> 2) * 2048 + t * 4 + (k & 3)] = Whh_d[idx];
    } else if (idx < 102400) {
        int g2 = idx - 65536;
        int o = g2 / 576, rem = g2 - o * 576, i = rem / 9, uv = rem - i * 9;
        g_W1t[((uv * 32 + (i >> 1)) * 64 + o) * 2 + (i & 1)] = Wc1[g2];
    } else if (idx < 111616) {
        int g2 = idx - 102400;
        int o = g2 / 576, rem = g2 - o * 576, i = rem / 9, uv = rem - i * 9;
        g_W2t[((uv * 32 + (i >> 1)) * 16 + o) * 2 + (i & 1)] = Wc2[g2];
    }
}

// ============================================================================
// K2: social pipeline (unchanged from R10/R11).
// ============================================================================
#define SROW 68
#define K2_SMEM (53136 * 4)

extern "C" __global__ void __launch_bounds__(256, 1)
k_social(const int* __restrict__ masks_idxs, const int* __restrict__ obs_traj_idxs,
         const float* __restrict__ Wdyn, const float* __restrict__ bdyn,
         const float* __restrict__ bc1, const float* __restrict__ bc2) {
    extern __shared__ float sm[];
    float* S = sm;
    float* A = sm + 4352;
    float* W1T = sm + 6800;
    float* W2T = sm + 43664;
    float* Bv = sm + 52880;
    const int b = blockIdx.x, tid = threadIdx.x;
    const int lane = tid & 31, wrp = tid >> 5;

    {
        const float4* s4 = (const float4*)g_W1t;
        float4* d4 = (float4*)W1T;
        for (int i = tid; i < 9216; i += 256) d4[i] = s4[i];
        const float4* s2 = (const float4*)g_W2t;
        float4* d2 = (float4*)W2T;
        for (int i = tid; i < 2304; i += 256) d2[i] = s2[i];
    }
    for (int idx = tid; idx < 4096; idx += 256) {
        int i = idx & 63, pos = idx >> 6, x = pos >> 3, y = pos & 7;
        int r = masks_idxs[b * 64 + y * 8 + x];
        S[pos * SROW + i] = g_Hn[(size_t)r * 64 + i];
    }
    __syncthreads();

    {
        const int o = ((wrp >> 2) << 5) + lane;
        const int ws = wrp & 3;
        int xj[9], yj[9];
#pragma unroll
        for (int j = 0; j < 9; j++) {
            int pj = ws + 4 * j;
            xj[j] = pj / 6; yj[j] = pj - 6 * xj[j];
        }
        ull acc[9];
        float bbv = __ldg(bc1 + o);
#pragma unroll
        for (int j = 0; j < 9; j++) acc[j] = pk2(bbv, 0.f);
        const ull* W1u = (const ull*)W1T;
#pragma unroll 1
        for (int uv = 0; uv < 9; uv++) {
            int u = uv / 3, v = uv - 3 * u;
            int px[9];
#pragma unroll
            for (int j = 0; j < 9; j++) px[j] = (xj[j] + u) * 8 + (yj[j] + v);
#pragma unroll 1
            for (int cc = 0; cc < 4; cc++) {
                ull wr[8];
#pragma unroll
                for (int kk = 0; kk < 8; kk++)
                    wr[kk] = W1u[(uv * 32 + cc * 8 + kk) * 64 + o];
#pragma unroll
                for (int j = 0; j < 9; j++) {
                    const ulonglong2* sr = (const ulonglong2*)(S + px[j] * SROW) + cc * 4;
#pragma unroll
                    for (int k2 = 0; k2 < 4; k2++) {
                        ulonglong2 sv = sr[k2];
                        acc[j] = fma2(wr[2 * k2 + 0], sv.x, acc[j]);
                        acc[j] = fma2(wr[2 * k2 + 1], sv.y, acc[j]);
                    }
                }
            }
        }
#pragma unroll
        for (int j = 0; j < 9; j++)
            A[(ws + 4 * j) * SROW + o] = lrelu(psum(acc[j]));
    }
    __syncthreads();

    if (tid < 128) {
        const int w2 = tid >> 5;
        const int o = lane & 15;
        const int pg = w2 * 2 + (lane >> 4);
        const int pp0 = pg * 2, pp1 = pg * 2 + 1;
        const int x0 = pp0 >> 2, y0 = pp0 & 3;
        const int x1 = pp1 >> 2, y1 = pp1 & 3;
        float bbv = __ldg(bc2 + o);
        ull a0 = pk2(bbv, 0.f), a1 = pk2(bbv, 0.f);
        const ull* W2u = (const ull*)W2T;
#pragma unroll 1
        for (int uv = 0; uv < 9; uv++) {
            int u = uv / 3, v = uv - 3 * u;
            int pA0 = (x0 + u) * 6 + (y0 + v);
            int pA1 = (x1 + u) * 6 + (y1 + v);
#pragma unroll 1
            for (int cc = 0; cc < 4; cc++) {
                ull wr[8];
#pragma unroll
                for (int kk = 0; kk < 8; kk++)
                    wr[kk] = W2u[(uv * 32 + cc * 8 + kk) * 16 + o];
                const ulonglong2* r0 = (const ulonglong2*)(A + pA0 * SROW) + cc * 4;
                const ulonglong2* r1 = (const ulonglong2*)(A + pA1 * SROW) + cc * 4;
#pragma unroll
                for (int k2 = 0; k2 < 4; k2++) {
                    ulonglong2 v0 = r0[k2], v1 = r1[k2];
                    a0 = fma2(wr[2 * k2 + 0], v0.x, a0);
                    a0 = fma2(wr[2 * k2 + 1], v0.y, a0);
                    a1 = fma2(wr[2 * k2 + 0], v1.x, a1);
                    a1 = fma2(wr[2 * k2 + 1], v1.y, a1);
                }
            }
        }
        Bv[o * 16 + pp0] = lrelu(psum(a0));
        Bv[o * 16 + pp1] = lrelu(psum(a1));
    }
    __syncthreads();
    if (tid < 144) {
        int o = tid / 9, pp = tid - o * 9, x = pp / 3, y = pp - x * 3;
        float m0 = fmaxf(Bv[o * 16 + x * 4 + y], Bv[o * 16 + x * 4 + y + 1]);
        float m1 = fmaxf(Bv[o * 16 + (x + 1) * 4 + y], Bv[o * 16 + (x + 1) * 4 + y + 1]);
        g_enc[b * ENCD + DYND + tid] = fmaxf(m0, m1);
    } else if (tid >= 160 && tid < 192) {
        int d = tid - 160;
        int r = obs_traj_idxs[15 * NN + b];
        const float* hf = g_Hs + r * ENCH;
        float acc = bdyn[d];
#pragma unroll
        for (int k = 0; k < 64; k++) acc = fmaf(hf[k], Wdyn[d * 64 + k], acc);
        g_enc[b * ENCD + d] = lrelu(acc);
    }
}

// ============================================================================
// K3: decoder LSTM. 96 blocks x 2 rows, 512 gemm threads + 1 output warp
// (computes step t-1's projection concurrently with step t's gemm).
// ============================================================================
#define D_W 0
#define D_ENC 49152
#define D_H 49504
#define D_WOP 50016
#define D_BOP 50656
#define K3_SMEM (50664 * 4)
#define K3_THREADS 544

extern "C" __global__ void __launch_bounds__(K3_THREADS, 1)
k_decoder(const float* __restrict__ Wih_d, const float* __restrict__ bih_d,
          const float* __restrict__ bhh_d,
          const float* __restrict__ Wop, const float* __restrict__ bop,
          float* __restrict__ out) {
    extern __shared__ float dsm[];
    float* enc_s = dsm + D_ENC;
    float* wop_s = dsm + D_WOP;
    float* bop_s = dsm + D_BOP;
    const int tid = threadIdx.x;
    const int b0 = blockIdx.x * 2;

    {
        const float4* src4 = (const float4*)g_Whh4;
        float4* dst4 = (float4*)(dsm + D_W);
        for (int i = tid; i < 12288; i += K3_THREADS) dst4[i] = src4[i];
    }
    for (int idx = tid; idx < 2 * ENCD; idx += K3_THREADS)
        enc_s[idx] = g_enc[b0 * ENCD + idx];
    for (int idx = tid; idx < 640; idx += K3_THREADS) wop_s[idx] = Wop[idx];
    if (tid < 5) bop_s[tid] = bop[tid];
    if (tid < 256) dsm[D_H + tid] = 0.f;

    const int q = tid & 3, u = tid >> 2;
    const int g = q * 128 + u;
    const bool gemm = (tid < 512);

    ulonglong2 wst[8];
    float ez0 = 0.f, ez1 = 0.f;
    if (gemm) {
#pragma unroll
        for (int k = 0; k < 8; k++)
            wst[k] = ((const ulonglong2*)g_Whh4)[(24 + k) * 512 + tid];
    }
    __syncthreads();
    if (gemm) {
        float bbv = bih_d[g] + bhh_d[g];
        ez0 = bbv; ez1 = bbv;
        const float4* wr = (const float4*)(Wih_d + g * ENCD);
#pragma unroll 4
        for (int k4 = 0; k4 < 44; k4++) {
            float4 wv = wr[k4];
            ez0 = fmaf(wv.x, enc_s[4 * k4 + 0], fmaf(wv.y, enc_s[4 * k4 + 1],
                  fmaf(wv.z, enc_s[4 * k4 + 2], fmaf(wv.w, enc_s[4 * k4 + 3], ez0))));
            ez1 = fmaf(wv.x, enc_s[ENCD + 4 * k4 + 0], fmaf(wv.y, enc_s[ENCD + 4 * k4 + 1],
                  fmaf(wv.z, enc_s[ENCD + 4 * k4 + 2], fmaf(wv.w, enc_s[ENCD + 4 * k4 + 3], ez1))));
        }
    }

    float c0 = 0.f, c1 = 0.f;
    const bool q0b = (q & 1), q1b = (q & 2);
    const int olane = tid - 512;

#pragma unroll 1
    for (int t = 0; t < T_PRED; t++) {
        const float* hr = dsm + D_H + (t & 1) * 256;
        float* hw = dsm + D_H + ((t & 1) ^ 1) * 256;
        if (gemm) {
            ull a0 = pk2(ez0, 0.f), a1 = pk2(ez1, 0.f);
            {
                const ulonglong2* wsm = (const ulonglong2*)(dsm + D_W) + tid;
                const ulonglong2* h0p = (const ulonglong2*)hr;
                const ulonglong2* h1p = (const ulonglong2*)(hr + DECH);
#pragma unroll
                for (int k4 = 0; k4 < 24; k4++) {
                    ulonglong2 wv = wsm[k4 * 512];
                    ulonglong2 v0 = h0p[k4], v1 = h1p[k4];
                    a0 = fma2(wv.x, v0.x, a0); a0 = fma2(wv.y, v0.y, a0);
                    a1 = fma2(wv.x, v1.x, a1); a1 = fma2(wv.y, v1.y, a1);
                }
#pragma unroll
                for (int k = 0; k < 8; k++) {
                    ulonglong2 wv = wst[k];
                    ulonglong2 v0 = h0p[24 + k], v1 = h1p[24 + k];
                    a0 = fma2(wv.x, v0.x, a0); a0 = fma2(wv.y, v0.y, a0);
                    a1 = fma2(wv.x, v1.x, a1); a1 = fma2(wv.y, v1.y, a1);
                }
            }
            float z0 = psum(a0), z1 = psum(a1);
            float xa0 = z0, xb0 = __shfl_xor_sync(0xffffffffu, z0, 1);
            float xc0 = __shfl_xor_sync(0xffffffffu, xa0, 2);
            float xd0 = __shfl_xor_sync(0xffffffffu, xb0, 2);
            float xa1 = z1, xb1 = __shfl_xor_sync(0xffffffffu, z1, 1);
            float xc1 = __shfl_xor_sync(0xffffffffu, xa1, 2);
            float xd1 = __shfl_xor_sync(0xffffffffu, xb1, 2);
            float zi0 = q1b ? (q0b ? xd0 : xc0) : (q0b ? xb0 : xa0);
            float zf0 = q1b ? (q0b ? xc0 : xd0) : (q0b ? xa0 : xb0);
            float zg0 = q1b ? (q0b ? xb0 : xa0) : (q0b ? xd0 : xc0);
            float zo0 = q1b ? (q0b ? xa0 : xb0) : (q0b ? xc0 : xd0);
            float zi1 = q1b ? (q0b ? xd1 : xc1) : (q0b ? xb1 : xa1);
            float zf1 = q1b ? (q0b ? xc1 : xd1) : (q0b ? xa1 : xb1);
            float zg1 = q1b ? (q0b ? xb1 : xa1) : (q0b ? xd1 : xc1);
            float zo1 = q1b ? (q0b ? xa1 : xb1) : (q0b ? xc1 : xd1);
            c0 = fmaf(sigf(zf0), c0, sigf(zi0) * tanha(zg0));
            c1 = fmaf(sigf(zf1), c1, sigf(zi1) * tanha(zg1));
            float h0 = sigf(zo0) * tanha(c0);
            float h1 = sigf(zo1) * tanha(c1);
            if (q == 0) { hw[u] = h0; hw[DECH + u] = h1; }
        } else if (t > 0 && olane < 20) {
            // output for step t-1 from hr (stable this step)
            int j = olane >> 1, half = olane & 1;
            int r = j / 5, oi = j - r * 5;
            float acc = half ? 0.f : bop_s[oi];
            const float* hh = hr + r * DECH + half * 64;
            const float* ww = wop_s + oi * DECH + half * 64;
#pragma unroll
            for (int k = 0; k < 64; k++) acc = fmaf(hh[k], ww[k], acc);
            acc += __shfl_xor_sync(0x000fffffu, acc, 1);
            if (!half) {
                float val = (oi < 2) ? acc : ((oi < 4) ? __expf(acc) : tanha(acc));
                out[((size_t)(t - 1) * NN + (b0 + r)) * 5 + oi] = val;
            }
        }
        __syncthreads();
    }
    // final step's output (h(T_PRED-1) is in buf[(T_PRED-1)&1 ^ 1] = buf[T_PRED&1])
    if (!gemm && olane < 20) {
        const float* hf = dsm + D_H + (T_PRED & 1) * 256;
        int j = olane >> 1, half = olane & 1;
        int r = j / 5, oi = j - r * 5;
        float acc = half ? 0.f : bop_s[oi];
        const float* hh = hf + r * DECH + half * 64;
        const float* ww = wop_s + oi * DECH + half * 64;
#pragma unroll
        for (int k = 0; k < 64; k++) acc = fmaf(hh[k], ww[k], acc);
        acc += __shfl_xor_sync(0x000fffffu, acc, 1);
        if (!half) {
            float val = (oi < 2) ? acc : ((oi < 4) ? __expf(acc) : tanha(acc));
            out[((size_t)(T_PRED - 1) * NN + (b0 + r)) * 5 + oi] = val;
        }
    }
}

extern "C" void kernel_launch(void* const* d_in, const int* in_sizes, int n_in,
                              void* d_out, int out_size) {
    const float* obs  = (const float*)d_in[0];
    const float* ngb  = (const float*)d_in[1];
    const int* masks_idxs    = (const int*)d_in[3];
    const int* obs_traj_idxs = (const int*)d_in[4];
    const float* Wip   = (const float*)d_in[7];
    const float* bip   = (const float*)d_in[8];
    const float* Wih_e = (const float*)d_in[9];
    const float* Whh_e = (const float*)d_in[10];
    const float* bih_e = (const float*)d_in[11];
    const float* bhh_e = (const float*)d_in[12];
    const float* Wdyn  = (const float*)d_in[13];
    const float* bdyn  = (const float*)d_in[14];
    const float* Wc1   = (const float*)d_in[15];
    const float* bc1   = (const float*)d_in[16];
    const float* Wc2   = (const float*)d_in[17];
    const float* bc2   = (const float*)d_in[18];
    const float* Wih_d = (const float*)d_in[19];
    const float* Whh_d = (const float*)d_in[20];
    const float* bih_d = (const float*)d_in[21];
    const float* bhh_d = (const float*)d_in[22];
    const float* Wop   = (const float*)d_in[23];
    const float* bop   = (const float*)d_in[24];

    cudaFuncSetAttribute(k_encoder, cudaFuncAttributeMaxDynamicSharedMemorySize, K1_SMEM);
    cudaFuncSetAttribute(k_social, cudaFuncAttributeMaxDynamicSharedMemorySize, K2_SMEM);
    cudaFuncSetAttribute(k_decoder, cudaFuncAttributeMaxDynamicSharedMemorySize, K3_SMEM);

    k_prep<<<437, 256>>>(Whh_d, Wc1, Wc2);
    k_encoder<<<290, 256, K1_SMEM>>>(obs, ngb, Wip, bip, Wih_e, Whh_e, bih_e, bhh_e);
    k_social<<<192, 256, K2_SMEM>>>(masks_idxs, obs_traj_idxs, Wdyn, bdyn, bc1, bc2);
    k_decoder<<<96, K3_THREADS, K3_SMEM>>>(Wih_d, bih_d, bhh_d, Wop, bop, (float*)d_out);
}

// round 14
// speedup vs baseline: 9.8433x; 1.3559x over previous
#include <cuda_runtime.h>
#include <cuda_bf16.h>
#include <cuda_fp16.h>
#include <cstdint>

#define T_OBS 16
#define T_PRED 25
#define NN 192
#define PP 36864
#define ENCH 64
#define DECH 128
#define DYND 32
#define ENCD 176   // DYN + SOC

typedef unsigned long long ull;

__device__ float g_Hn[(size_t)PP * ENCH];
__device__ float g_Hs[NN * ENCH];
__device__ float g_enc[NN * ENCD];
__device__ float g_Whh4[32 * 512 * 4];   // [k4][u*4+q][4]
__device__ float g_W1t[36864];           // [uv][i2][64 o] ull-packed
__device__ float g_W2t[9216];            // [uv][i2][16 o] ull-packed

__device__ __forceinline__ float lrelu(float x) { return fmaxf(x, 0.1f * x); }
__device__ __forceinline__ float tanha(float x) {
    float y; asm("tanh.approx.f32 %0,%1;" : "=f"(y) : "f"(x)); return y;
}
__device__ __forceinline__ float sigf(float x) { return fmaf(tanha(0.5f * x), 0.5f, 0.5f); }

__device__ __forceinline__ ull pk2(float lo, float hi) {
    ull r; asm("mov.b64 %0,{%1,%2};" : "=l"(r) : "f"(lo), "f"(hi)); return r;
}
__device__ __forceinline__ ull fma2(ull a, ull b, ull c) {
    ull d; asm("fma.rn.f32x2 %0,%1,%2,%3;" : "=l"(d) : "l"(a), "l"(b), "l"(c)); return d;
}
__device__ __forceinline__ float psum(ull v) {
    float a, b; asm("mov.b64 {%0,%1},%2;" : "=f"(a), "=f"(b) : "l"(v)); return a + b;
}
__device__ __forceinline__ uint32_t s2u(const void* p) {
    uint32_t a;
    asm("{ .reg .u64 t; cvta.to.shared.u64 t, %1; cvt.u32.u64 %0, t; }" : "=r"(a) : "l"(p));
    return a;
}
__device__ __forceinline__ uint32_t lds32(uint32_t a) {
    uint32_t v; asm volatile("ld.shared.b32 %0,[%1];" : "=r"(v) : "r"(a)); return v;
}
__device__ __forceinline__ void sts32(uint32_t a, uint32_t v) {
    asm volatile("st.shared.b32 [%0],%1;" :: "r"(a), "r"(v) : "memory");
}
__device__ __forceinline__ uint32_t h2pack(float a, float b) {
    __half ha = __float2half_rn(a), hb = __float2half_rn(b);
    return (uint32_t)__half_as_ushort(ha) | ((uint32_t)__half_as_ushort(hb) << 16);
}

#define LDM4(r, adr) \
    asm volatile("ldmatrix.sync.aligned.m8n8.x4.shared.b16 {%0,%1,%2,%3}, [%4];" \
        : "=r"((r)[0]), "=r"((r)[1]), "=r"((r)[2]), "=r"((r)[3]) : "r"(adr))

#define MMA(c, a, b0, b1) \
    asm volatile("mma.sync.aligned.m16n8k16.row.col.f32.f16.f16.f32 " \
        "{%0,%1,%2,%3}, {%4,%5,%6,%7}, {%8,%9}, {%0,%1,%2,%3};" \
        : "+f"((c)[0]), "+f"((c)[1]), "+f"((c)[2]), "+f"((c)[3]) \
        : "r"((a)[0]), "r"((a)[1]), "r"((a)[2]), "r"((a)[3]), "r"(b0), "r"(b1))

// ============================================================================
// K1: encoder LSTM via mma.sync fp16 single-term. 290 blocks x 128 rows,
// 2 CTAs/SM (one wave). Warp w owns units [8w,8w+8) x 4 gates.
// smem: BH 53248 | Abuf0 26624 | Abuf1 26624 | bias 1024 | wip 256 | bip 128
// ============================================================================
#define RS 208
#define BH_OFF 0
#define ABUF_OFF 53248
#define ABUF_SZ 26624
#define BIAS_OFF 106496
#define WIP_OFF 107520
#define BIP_OFF 107776
#define K1_SMEM 107904

extern "C" __global__ void __launch_bounds__(256, 2)
k_encoder(const float* __restrict__ obs, const float* __restrict__ ngb,
          const float* __restrict__ Wip, const float* __restrict__ bip,
          const float* __restrict__ Wih, const float* __restrict__ Whh,
          const float* __restrict__ bih, const float* __restrict__ bhh) {
    extern __shared__ __align__(16) char smb[];
    const int tid = threadIdx.x, lane = tid & 31, w = tid >> 5;
    const uint32_t sb = s2u(smb);
    float4* bias4 = (float4*)(smb + BIAS_OFF);
    float* wip_s = (float*)(smb + WIP_OFF);
    float* bip_s = (float*)(smb + BIP_OFF);

    // stage B fp16 (row n = gate*64+unit, col k = [emb32|h64])
    for (int idx = tid; idx < 24576; idx += 256) {
        int n = idx / 96, k = idx - n * 96;
        float wv = (k < 32) ? Wih[n * 32 + k] : Whh[n * 64 + (k - 32)];
        *(__half*)(smb + BH_OFF + n * RS + 2 * k) = __float2half_rn(wv);
    }
    for (int i = tid; i < ABUF_SZ / 4; i += 256)
        *(uint32_t*)(smb + ABUF_OFF + 4 * i) = 0;
    if (tid < 64) {
        bias4[tid] = make_float4(bih[tid] + bhh[tid], bih[64 + tid] + bhh[64 + tid],
                                 bih[128 + tid] + bhh[128 + tid], bih[192 + tid] + bhh[192 + tid]);
        wip_s[tid] = Wip[tid];
    }
    if (tid < 32) bip_s[tid] = bip[tid];
    __syncthreads();

    const int bx = blockIdx.x;
    const bool ego = (bx >= 288);
    const int row0 = ego ? (bx - 288) * 128 : bx * 128;
    const int nr = ego ? NN : PP;
    const float* src = ego ? obs : ngb;
    float* gH = ego ? g_Hs : g_Hn;

    // emb t=0 into buf0
    if (tid < 128) {
        int row = row0 + tid;
        float x0 = 0.f, x1 = 0.f;
        if (row < nr) {
            const float* px = src + ((size_t)0 * nr + row) * 2;
            x0 = px[0]; x1 = px[1];
        }
        uint32_t base = sb + ABUF_OFF + (uint32_t)tid * RS;
#pragma unroll
        for (int m2 = 0; m2 < 16; m2++) {
            float e0 = lrelu(fmaf(wip_s[4 * m2 + 0], x0, fmaf(wip_s[4 * m2 + 1], x1, bip_s[2 * m2 + 0])));
            float e1 = lrelu(fmaf(wip_s[4 * m2 + 2], x0, fmaf(wip_s[4 * m2 + 3], x1, bip_s[2 * m2 + 1])));
            sts32(base + 4 * m2, h2pack(e0, e1));
        }
    }
    __syncthreads();

    const int gid = lane >> 2, tig = lane & 3;
    const int u0 = 8 * w + 2 * tig;
    const uint32_t ldmoff = (uint32_t)(((lane & 7) + ((lane >> 3) & 1) * 8) * RS + (lane >> 4) * 16);
    const float4 ba = bias4[u0], bb = bias4[u0 + 1];

    float c[8][2][2];
#pragma unroll
    for (int a = 0; a < 8; a++)
#pragma unroll
        for (int r = 0; r < 2; r++) { c[a][r][0] = 0.f; c[a][r][1] = 0.f; }

    int p = 0;
#pragma unroll 1
    for (int t = 0; t < T_OBS; t++) {
        const uint32_t Abase = sb + ABUF_OFF + (uint32_t)p * ABUF_SZ;
        const uint32_t Wbase = sb + ABUF_OFF + (uint32_t)(p ^ 1) * ABUF_SZ;
#pragma unroll
        for (int mq = 0; mq < 4; mq++) {   // 32 rows per chunk (regs: acc 32)
            float acc[2][4][4];
#pragma unroll
            for (int mt = 0; mt < 2; mt++)
#pragma unroll
                for (int q = 0; q < 4; q++)
#pragma unroll
                    for (int e = 0; e < 4; e++) acc[mt][q][e] = 0.f;
#pragma unroll
            for (int k = 0; k < 6; k++) {
                uint32_t ah[2][4];
#pragma unroll
                for (int mt = 0; mt < 2; mt++) {
                    uint32_t adr = Abase + (uint32_t)((mq * 32 + mt * 16) * RS + k * 32) + ldmoff;
                    LDM4(ah[mt], adr);
                }
#pragma unroll
                for (int q = 0; q < 4; q++) {
                    uint32_t baddr = sb + BH_OFF + (uint32_t)((q * 64 + 8 * w + gid) * RS + k * 32 + tig * 4);
                    uint32_t bh0 = lds32(baddr), bh1 = lds32(baddr + 16);
                    MMA(acc[0][q], ah[0], bh0, bh1);
                    MMA(acc[1][q], ah[1], bh0, bh1);
                }
            }
            // activation + h write
#pragma unroll
            for (int mt = 0; mt < 2; mt++)
#pragma unroll
            for (int rr = 0; rr < 2; rr++) {
                int row = mq * 32 + mt * 16 + gid + rr * 8;
                float hv[2];
#pragma unroll
                for (int cc = 0; cc < 2; cc++) {
                    int e = rr * 2 + cc;
                    float zi = acc[mt][0][e] + (cc ? bb.x : ba.x);
                    float zf = acc[mt][1][e] + (cc ? bb.y : ba.y);
                    float zg = acc[mt][2][e] + (cc ? bb.z : ba.z);
                    float zo = acc[mt][3][e] + (cc ? bb.w : ba.w);
                    int ci = mq * 2 + mt;
                    float cn = fmaf(sigf(zf), c[ci][rr][cc], sigf(zi) * tanha(zg));
                    c[ci][rr][cc] = cn;
                    hv[cc] = sigf(zo) * tanha(cn);
                }
                if (t < T_OBS - 1) {
                    uint32_t ha = Wbase + (uint32_t)(row * RS + 64 + 2 * u0);
                    sts32(ha, h2pack(hv[0], hv[1]));
                } else {
                    int grow = row0 + row;
                    if (grow < nr) {
                        float2 v2; v2.x = hv[0]; v2.y = hv[1];
                        *(float2*)(gH + (size_t)grow * 64 + u0) = v2;
                    }
                }
            }
        }
        // emb for t+1 into buf p^1
        if (t < T_OBS - 1 && tid < 128) {
            int row = row0 + tid;
            float x0 = 0.f, x1 = 0.f;
            if (row < nr) {
                const float* px = src + ((size_t)(t + 1) * nr + row) * 2;
                x0 = px[0]; x1 = px[1];
            }
            uint32_t base = Wbase + (uint32_t)tid * RS;
#pragma unroll
            for (int m2 = 0; m2 < 16; m2++) {
                float e0 = lrelu(fmaf(wip_s[4 * m2 + 0], x0, fmaf(wip_s[4 * m2 + 1], x1, bip_s[2 * m2 + 0])));
                float e1 = lrelu(fmaf(wip_s[4 * m2 + 2], x0, fmaf(wip_s[4 * m2 + 3], x1, bip_s[2 * m2 + 1])));
                sts32(base + 4 * m2, h2pack(e0, e1));
            }
        }
        __syncthreads();
        p ^= 1;
    }
}

// ============================================================================
// K_prep: weight transposes (unchanged).
// ============================================================================
extern "C" __global__ void k_prep(const float* __restrict__ Whh_d,
                                  const float* __restrict__ Wc1,
                                  const float* __restrict__ Wc2) {
    int idx = blockIdx.x * 256 + threadIdx.x;
    if (idx < 65536) {
        int g = idx >> 7, k = idx & 127;
        int cg = g >> 7, uu = g & 127;
        int t = uu * 4 + cg;
        g_Whh4[(k >> 2) * 2048 + t * 4 + (k & 3)] = Whh_d[idx];
    } else if (idx < 102400) {
        int g2 = idx - 65536;
        int o = g2 / 576, rem = g2 - o * 576, i = rem / 9, uv = rem - i * 9;
        g_W1t[((uv * 32 + (i >> 1)) * 64 + o) * 2 + (i & 1)] = Wc1[g2];
    } else if (idx < 111616) {
        int g2 = idx - 102400;
        int o = g2 / 576, rem = g2 - o * 576, i = rem / 9, uv = rem - i * 9;
        g_W2t[((uv * 32 + (i >> 1)) * 16 + o) * 2 + (i & 1)] = Wc2[g2];
    }
}

// ============================================================================
// K2: social pipeline (unchanged).
// ============================================================================
#define SROW 68
#define K2_SMEM (53136 * 4)

extern "C" __global__ void __launch_bounds__(256, 1)
k_social(const int* __restrict__ masks_idxs, const int* __restrict__ obs_traj_idxs,
         const float* __restrict__ Wdyn, const float* __restrict__ bdyn,
         const float* __restrict__ bc1, const float* __restrict__ bc2) {
    extern __shared__ float sm[];
    float* S = sm;
    float* A = sm + 4352;
    float* W1T = sm + 6800;
    float* W2T = sm + 43664;
    float* Bv = sm + 52880;
    const int b = blockIdx.x, tid = threadIdx.x;
    const int lane = tid & 31, wrp = tid >> 5;

    {
        const float4* s4 = (const float4*)g_W1t;
        float4* d4 = (float4*)W1T;
        for (int i = tid; i < 9216; i += 256) d4[i] = s4[i];
        const float4* s2 = (const float4*)g_W2t;
        float4* d2 = (float4*)W2T;
        for (int i = tid; i < 2304; i += 256) d2[i] = s2[i];
    }
    for (int idx = tid; idx < 4096; idx += 256) {
        int i = idx & 63, pos = idx >> 6, x = pos >> 3, y = pos & 7;
        int r = masks_idxs[b * 64 + y * 8 + x];
        S[pos * SROW + i] = g_Hn[(size_t)r * 64 + i];
    }
    __syncthreads();

    {
        const int o = ((wrp >> 2) << 5) + lane;
        const int ws = wrp & 3;
        int xj[9], yj[9];
#pragma unroll
        for (int j = 0; j < 9; j++) {
            int pj = ws + 4 * j;
            xj[j] = pj / 6; yj[j] = pj - 6 * xj[j];
        }
        ull acc[9];
        float bbv = __ldg(bc1 + o);
#pragma unroll
        for (int j = 0; j < 9; j++) acc[j] = pk2(bbv, 0.f);
        const ull* W1u = (const ull*)W1T;
#pragma unroll 1
        for (int uv = 0; uv < 9; uv++) {
            int u = uv / 3, v = uv - 3 * u;
            int px[9];
#pragma unroll
            for (int j = 0; j < 9; j++) px[j] = (xj[j] + u) * 8 + (yj[j] + v);
#pragma unroll 1
            for (int cc = 0; cc < 4; cc++) {
                ull wr[8];
#pragma unroll
                for (int kk = 0; kk < 8; kk++)
                    wr[kk] = W1u[(uv * 32 + cc * 8 + kk) * 64 + o];
#pragma unroll
                for (int j = 0; j < 9; j++) {
                    const ulonglong2* sr = (const ulonglong2*)(S + px[j] * SROW) + cc * 4;
#pragma unroll
                    for (int k2 = 0; k2 < 4; k2++) {
                        ulonglong2 sv = sr[k2];
                        acc[j] = fma2(wr[2 * k2 + 0], sv.x, acc[j]);
                        acc[j] = fma2(wr[2 * k2 + 1], sv.y, acc[j]);
                    }
                }
            }
        }
#pragma unroll
        for (int j = 0; j < 9; j++)
            A[(ws + 4 * j) * SROW + o] = lrelu(psum(acc[j]));
    }
    __syncthreads();

    if (tid < 128) {
        const int w2 = tid >> 5;
        const int o = lane & 15;
        const int pg = w2 * 2 + (lane >> 4);
        const int pp0 = pg * 2, pp1 = pg * 2 + 1;
        const int x0 = pp0 >> 2, y0 = pp0 & 3;
        const int x1 = pp1 >> 2, y1 = pp1 & 3;
        float bbv = __ldg(bc2 + o);
        ull a0 = pk2(bbv, 0.f), a1 = pk2(bbv, 0.f);
        const ull* W2u = (const ull*)W2T;
#pragma unroll 1
        for (int uv = 0; uv < 9; uv++) {
            int u = uv / 3, v = uv - 3 * u;
            int pA0 = (x0 + u) * 6 + (y0 + v);
            int pA1 = (x1 + u) * 6 + (y1 + v);
#pragma unroll 1
            for (int cc = 0; cc < 4; cc++) {
                ull wr[8];
#pragma unroll
                for (int kk = 0; kk < 8; kk++)
                    wr[kk] = W2u[(uv * 32 + cc * 8 + kk) * 16 + o];
                const ulonglong2* r0 = (const ulonglong2*)(A + pA0 * SROW) + cc * 4;
                const ulonglong2* r1 = (const ulonglong2*)(A + pA1 * SROW) + cc * 4;
#pragma unroll
                for (int k2 = 0; k2 < 4; k2++) {
                    ulonglong2 v0 = r0[k2], v1 = r1[k2];
                    a0 = fma2(wr[2 * k2 + 0], v0.x, a0);
                    a0 = fma2(wr[2 * k2 + 1], v0.y, a0);
                    a1 = fma2(wr[2 * k2 + 0], v1.x, a1);
                    a1 = fma2(wr[2 * k2 + 1], v1.y, a1);
                }
            }
        }
        Bv[o * 16 + pp0] = lrelu(psum(a0));
        Bv[o * 16 + pp1] = lrelu(psum(a1));
    }
    __syncthreads();
    if (tid < 144) {
        int o = tid / 9, pp = tid - o * 9, x = pp / 3, y = pp - x * 3;
        float m0 = fmaxf(Bv[o * 16 + x * 4 + y], Bv[o * 16 + x * 4 + y + 1]);
        float m1 = fmaxf(Bv[o * 16 + (x + 1) * 4 + y], Bv[o * 16 + (x + 1) * 4 + y + 1]);
        g_enc[b * ENCD + DYND + tid] = fmaxf(m0, m1);
    } else if (tid >= 160 && tid < 192) {
        int d = tid - 160;
        int r = obs_traj_idxs[15 * NN + b];
        const float* hf = g_Hs + r * ENCH;
        float acc = bdyn[d];
#pragma unroll
        for (int k = 0; k < 64; k++) acc = fmaf(hf[k], Wdyn[d * 64 + k], acc);
        g_enc[b * ENCD + d] = lrelu(acc);
    }
}

// ============================================================================
// K3: decoder LSTM. 96 blocks x 2 rows, 512 threads.
// Weights: k4 0..15 in smem (131KB), k4 16..31 in registers (64 regs).
// shfl quad exchange, 1 barrier/step, h double-buffered.
// ============================================================================
#define D_W 0        // 32768 floats (16 k4)
#define D_ENC 32768  // 352
#define D_H 33120    // 512
#define D_WOP 33632  // 640
#define D_BOP 34272  // 8
#define K3_SMEM (34280 * 4)

extern "C" __global__ void __launch_bounds__(512, 1)
k_decoder(const float* __restrict__ Wih_d, const float* __restrict__ bih_d,
          const float* __restrict__ bhh_d,
          const float* __restrict__ Wop, const float* __restrict__ bop,
          float* __restrict__ out) {
    extern __shared__ float dsm[];
    float* enc_s = dsm + D_ENC;
    float* wop_s = dsm + D_WOP;
    float* bop_s = dsm + D_BOP;
    const int tid = threadIdx.x;
    const int b0 = blockIdx.x * 2;
    const int q = tid & 3, u = tid >> 2;
    const int g = q * 128 + u;

    {
        const float4* src4 = (const float4*)g_Whh4;
        float4* dst4 = (float4*)(dsm + D_W);
        for (int i = tid; i < 8192; i += 512) dst4[i] = src4[i];
    }
    for (int idx = tid; idx < 2 * ENCD; idx += 512)
        enc_s[idx] = g_enc[b0 * ENCD + idx];
    for (int idx = tid; idx < 640; idx += 512) wop_s[idx] = Wop[idx];
    if (tid < 5) bop_s[tid] = bop[tid];
    if (tid < 256) dsm[D_H + tid] = 0.f;

    ulonglong2 wreg[16];
#pragma unroll
    for (int k = 0; k < 16; k++)
        wreg[k] = ((const ulonglong2*)g_Whh4)[(16 + k) * 512 + tid];
    __syncthreads();

    float ez0, ez1;
    {
        float bbv = bih_d[g] + bhh_d[g];
        ez0 = bbv; ez1 = bbv;
        const float4* wr = (const float4*)(Wih_d + g * ENCD);
#pragma unroll 4
        for (int k4 = 0; k4 < 44; k4++) {
            float4 wv = wr[k4];
            ez0 = fmaf(wv.x, enc_s[4 * k4 + 0], fmaf(wv.y, enc_s[4 * k4 + 1],
                  fmaf(wv.z, enc_s[4 * k4 + 2], fmaf(wv.w, enc_s[4 * k4 + 3], ez0))));
            ez1 = fmaf(wv.x, enc_s[ENCD + 4 * k4 + 0], fmaf(wv.y, enc_s[ENCD + 4 * k4 + 1],
                  fmaf(wv.z, enc_s[ENCD + 4 * k4 + 2], fmaf(wv.w, enc_s[ENCD + 4 * k4 + 3], ez1))));
        }
    }

    float c0 = 0.f, c1 = 0.f;
    const bool q0b = (q & 1), q1b = (q & 2);

#pragma unroll 1
    for (int t = 0; t < T_PRED; t++) {
        const float* hr = dsm + D_H + (t & 1) * 256;
        float* hw = dsm + D_H + ((t & 1) ^ 1) * 256;
        ull a0 = pk2(ez0, 0.f), a1 = pk2(ez1, 0.f);
        {
            const ulonglong2* wsm = (const ulonglong2*)(dsm + D_W) + tid;
            const ulonglong2* h0p = (const ulonglong2*)hr;
            const ulonglong2* h1p = (const ulonglong2*)(hr + DECH);
#pragma unroll
            for (int k4 = 0; k4 < 16; k4++) {
                ulonglong2 wv = wsm[k4 * 512];
                ulonglong2 v0 = h0p[k4], v1 = h1p[k4];
                a0 = fma2(wv.x, v0.x, a0); a0 = fma2(wv.y, v0.y, a0);
                a1 = fma2(wv.x, v1.x, a1); a1 = fma2(wv.y, v1.y, a1);
            }
#pragma unroll
            for (int k = 0; k < 16; k++) {
                ulonglong2 wv = wreg[k];
                ulonglong2 v0 = h0p[16 + k], v1 = h1p[16 + k];
                a0 = fma2(wv.x, v0.x, a0); a0 = fma2(wv.y, v0.y, a0);
                a1 = fma2(wv.x, v1.x, a1); a1 = fma2(wv.y, v1.y, a1);
            }
        }
        float z0 = psum(a0), z1 = psum(a1);
        float xa0 = z0, xb0 = __shfl_xor_sync(0xffffffffu, z0, 1);
        float xc0 = __shfl_xor_sync(0xffffffffu, xa0, 2);
        float xd0 = __shfl_xor_sync(0xffffffffu, xb0, 2);
        float xa1 = z1, xb1 = __shfl_xor_sync(0xffffffffu, z1, 1);
        float xc1 = __shfl_xor_sync(0xffffffffu, xa1, 2);
        float xd1 = __shfl_xor_sync(0xffffffffu, xb1, 2);
        float zi0 = q1b ? (q0b ? xd0 : xc0) : (q0b ? xb0 : xa0);
        float zf0 = q1b ? (q0b ? xc0 : xd0) : (q0b ? xa0 : xb0);
        float zg0 = q1b ? (q0b ? xb0 : xa0) : (q0b ? xd0 : xc0);
        float zo0 = q1b ? (q0b ? xa0 : xb0) : (q0b ? xc0 : xd0);
        float zi1 = q1b ? (q0b ? xd1 : xc1) : (q0b ? xb1 : xa1);
        float zf1 = q1b ? (q0b ? xc1 : xd1) : (q0b ? xa1 : xb1);
        float zg1 = q1b ? (q0b ? xb1 : xa1) : (q0b ? xd1 : xc1);
        float zo1 = q1b ? (q0b ? xa1 : xb1) : (q0b ? xc1 : xd1);
        c0 = fmaf(sigf(zf0), c0, sigf(zi0) * tanha(zg0));
        c1 = fmaf(sigf(zf1), c1, sigf(zi1) * tanha(zg1));
        float h0 = sigf(zo0) * tanha(c0);
        float h1 = sigf(zo1) * tanha(c1);
        if (q == 0) { hw[u] = h0; hw[DECH + u] = h1; }
        __syncthreads();
        if (tid < 10) {
            int r = tid / 5, oi = tid - r * 5;
            float acc = bop_s[oi];
            const float* hh = hw + r * DECH;
#pragma unroll
            for (int k = 0; k < DECH; k++) acc = fmaf(hh[k], wop_s[oi * DECH + k], acc);
            float val = (oi < 2) ? acc : ((oi < 4) ? __expf(acc) : tanha(acc));
            out[((size_t)t * NN + (b0 + r)) * 5 + oi] = val;
        }
    }
}

extern "C" void kernel_launch(void* const* d_in, const int* in_sizes, int n_in,
                              void* d_out, int out_size) {
    const float* obs  = (const float*)d_in[0];
    const float* ngb  = (const float*)d_in[1];
    const int* masks_idxs    = (const int*)d_in[3];
    const int* obs_traj_idxs = (const int*)d_in[4];
    const float* Wip   = (const float*)d_in[7];
    const float* bip   = (const float*)d_in[8];
    const float* Wih_e = (const float*)d_in[9];
    const float* Whh_e = (const float*)d_in[10];
    const float* bih_e = (const float*)d_in[11];
    const float* bhh_e = (const float*)d_in[12];
    const float* Wdyn  = (const float*)d_in[13];
    const float* bdyn  = (const float*)d_in[14];
    const float* Wc1   = (const float*)d_in[15];
    const float* bc1   = (const float*)d_in[16];
    const float* Wc2   = (const float*)d_in[17];
    const float* bc2   = (const float*)d_in[18];
    const float* Wih_d = (const float*)d_in[19];
    const float* Whh_d = (const float*)d_in[20];
    const float* bih_d = (const float*)d_in[21];
    const float* bhh_d = (const float*)d_in[22];
    const float* Wop   = (const float*)d_in[23];
    const float* bop   = (const float*)d_in[24];

    cudaFuncSetAttribute(k_encoder, cudaFuncAttributeMaxDynamicSharedMemorySize, K1_SMEM);
    cudaFuncSetAttribute(k_social, cudaFuncAttributeMaxDynamicSharedMemorySize, K2_SMEM);
    cudaFuncSetAttribute(k_decoder, cudaFuncAttributeMaxDynamicSharedMemorySize, K3_SMEM);

    k_prep<<<437, 256>>>(Whh_d, Wc1, Wc2);
    k_encoder<<<290, 256, K1_SMEM>>>(obs, ngb, Wip, bip, Wih_e, Whh_e, bih_e, bhh_e);
    k_social<<<192, 256, K2_SMEM>>>(masks_idxs, obs_traj_idxs, Wdyn, bdyn, bc1, bc2);
    k_decoder<<<96, 512, K3_SMEM>>>(Wih_d, bih_d, bhh_d, Wop, bop, (float*)d_out);
}

// round 15
// speedup vs baseline: 10.3793x; 1.0545x over previous
#include <cuda_runtime.h>
#include <cuda_bf16.h>
#include <cuda_fp16.h>
#include <cstdint>

#define T_OBS 16
#define T_PRED 25
#define NN 192
#define PP 36864
#define ENCH 64
#define DECH 128
#define DYND 32
#define ENCD 176   // DYN + SOC

typedef unsigned long long ull;

__device__ float g_Hn[(size_t)PP * ENCH];
__device__ float g_Hs[NN * ENCH];
__device__ float g_enc[NN * ENCD];
__device__ float g_Whh4[32 * 512 * 4];   // [k4][u*4+q][4]
__device__ float g_W1t[36864];           // [uv][i2][64 o] ull-packed
__device__ float g_W2t[9216];            // [uv][i2][16 o] ull-packed

__device__ __forceinline__ float lrelu(float x) { return fmaxf(x, 0.1f * x); }
__device__ __forceinline__ float tanha(float x) {
    float y; asm("tanh.approx.f32 %0,%1;" : "=f"(y) : "f"(x)); return y;
}
__device__ __forceinline__ float sigf(float x) { return fmaf(tanha(0.5f * x), 0.5f, 0.5f); }

__device__ __forceinline__ ull pk2(float lo, float hi) {
    ull r; asm("mov.b64 %0,{%1,%2};" : "=l"(r) : "f"(lo), "f"(hi)); return r;
}
__device__ __forceinline__ ull fma2(ull a, ull b, ull c) {
    ull d; asm("fma.rn.f32x2 %0,%1,%2,%3;" : "=l"(d) : "l"(a), "l"(b), "l"(c)); return d;
}
__device__ __forceinline__ float psum(ull v) {
    float a, b; asm("mov.b64 {%0,%1},%2;" : "=f"(a), "=f"(b) : "l"(v)); return a + b;
}
__device__ __forceinline__ uint32_t s2u(const void* p) {
    uint32_t a;
    asm("{ .reg .u64 t; cvta.to.shared.u64 t, %1; cvt.u32.u64 %0, t; }" : "=r"(a) : "l"(p));
    return a;
}
__device__ __forceinline__ uint32_t lds32(uint32_t a) {
    uint32_t v; asm volatile("ld.shared.b32 %0,[%1];" : "=r"(v) : "r"(a)); return v;
}
__device__ __forceinline__ void sts32(uint32_t a, uint32_t v) {
    asm volatile("st.shared.b32 [%0],%1;" :: "r"(a), "r"(v) : "memory");
}
// pack 2 floats -> f16x2 (lo, hi)
__device__ __forceinline__ uint32_t pkh2(float lo, float hi) {
    uint32_t r; asm("cvt.rn.f16x2.f32 %0,%1,%2;" : "=r"(r) : "f"(hi), "f"(lo)); return r;
}
__device__ __forceinline__ uint32_t tanh2(uint32_t x) {
    uint32_t y; asm("tanh.approx.f16x2 %0,%1;" : "=r"(y) : "r"(x)); return y;
}
__device__ __forceinline__ uint32_t sig2fin(uint32_t t) {   // t*0.5 + 0.5
    const uint32_t H05 = 0x38003800u;
    uint32_t r; asm("fma.rn.f16x2 %0,%1,%2,%2;" : "=r"(r) : "r"(t), "r"(H05)); return r;
}
__device__ __forceinline__ uint32_t hmul2(uint32_t a, uint32_t b) {
    uint32_t r; asm("mul.rn.f16x2 %0,%1,%2;" : "=r"(r) : "r"(a), "r"(b)); return r;
}
__device__ __forceinline__ float2 uph2(uint32_t v) {
    float2 f;
    asm("{.reg .f16 l,h; mov.b32 {l,h},%2; cvt.f32.f16 %0,l; cvt.f32.f16 %1,h;}"
        : "=f"(f.x), "=f"(f.y) : "r"(v));
    return f;
}

#define LDM4(r, adr) \
    asm volatile("ldmatrix.sync.aligned.m8n8.x4.shared.b16 {%0,%1,%2,%3}, [%4];" \
        : "=r"((r)[0]), "=r"((r)[1]), "=r"((r)[2]), "=r"((r)[3]) : "r"(adr))

#define MMA(c, a, b0, b1) \
    asm volatile("mma.sync.aligned.m16n8k16.row.col.f32.f16.f16.f32 " \
        "{%0,%1,%2,%3}, {%4,%5,%6,%7}, {%8,%9}, {%0,%1,%2,%3};" \
        : "+f"((c)[0]), "+f"((c)[1]), "+f"((c)[2]), "+f"((c)[3]) \
        : "r"((a)[0]), "r"((a)[1]), "r"((a)[2]), "r"((a)[3]), "r"(b0), "r"(b1))

// ============================================================================
// K1: encoder LSTM, mma.sync fp16 single-term + f16x2 activations.
// Grid 296 (= one 2-CTA/SM wave): 0..287 neighbor, 288..289 ego,
// 290..295 weight-prep blocks (folded k_prep).
// ============================================================================
#define RS 208
#define BH_OFF 0
#define ABUF_OFF 53248
#define ABUF_SZ 26624
#define BIAS_OFF 106496
#define WIP_OFF 107520
#define BIP_OFF 107776
#define K1_SMEM 107904

extern "C" __global__ void __launch_bounds__(256, 2)
k_encoder(const float* __restrict__ obs, const float* __restrict__ ngb,
          const float* __restrict__ Wip, const float* __restrict__ bip,
          const float* __restrict__ Wih, const float* __restrict__ Whh,
          const float* __restrict__ bih, const float* __restrict__ bhh,
          const float* __restrict__ Whh_d, const float* __restrict__ Wc1,
          const float* __restrict__ Wc2) {
    const int tid = threadIdx.x;
    const int bx = blockIdx.x;

    if (bx >= 290) {   // prep blocks: weight transposes for K2/K3
        for (int idx = (bx - 290) * 256 + tid; idx < 111616; idx += 1536) {
            if (idx < 65536) {
                int g = idx >> 7, k = idx & 127;
                int cg = g >> 7, uu = g & 127;
                int t = uu * 4 + cg;
                g_Whh4[(k >> 2) * 2048 + t * 4 + (k & 3)] = Whh_d[idx];
            } else if (idx < 102400) {
                int g2 = idx - 65536;
                int o = g2 / 576, rem = g2 - o * 576, i = rem / 9, uv = rem - i * 9;
                g_W1t[((uv * 32 + (i >> 1)) * 64 + o) * 2 + (i & 1)] = Wc1[g2];
            } else {
                int g2 = idx - 102400;
                int o = g2 / 576, rem = g2 - o * 576, i = rem / 9, uv = rem - i * 9;
                g_W2t[((uv * 32 + (i >> 1)) * 16 + o) * 2 + (i & 1)] = Wc2[g2];
            }
        }
        return;
    }

    extern __shared__ __align__(16) char smb[];
    const int lane = tid & 31, w = tid >> 5;
    const uint32_t sb = s2u(smb);
    float4* bias4 = (float4*)(smb + BIAS_OFF);
    float* wip_s = (float*)(smb + WIP_OFF);
    float* bip_s = (float*)(smb + BIP_OFF);

    // stage B fp16 (row n = gate*64+unit, col k = [emb32|h64])
    for (int idx = tid; idx < 24576; idx += 256) {
        int n = idx / 96, k = idx - n * 96;
        float wv = (k < 32) ? Wih[n * 32 + k] : Whh[n * 64 + (k - 32)];
        *(__half*)(smb + BH_OFF + n * RS + 2 * k) = __float2half_rn(wv);
    }
    for (int i = tid; i < ABUF_SZ / 4; i += 256)
        *(uint32_t*)(smb + ABUF_OFF + 4 * i) = 0;
    if (tid < 64) {
        bias4[tid] = make_float4(bih[tid] + bhh[tid], bih[64 + tid] + bhh[64 + tid],
                                 bih[128 + tid] + bhh[128 + tid], bih[192 + tid] + bhh[192 + tid]);
        wip_s[tid] = Wip[tid];
    }
    if (tid < 32) bip_s[tid] = bip[tid];
    __syncthreads();

    const bool ego = (bx >= 288);
    const int row0 = ego ? (bx - 288) * 128 : bx * 128;
    const int nr = ego ? NN : PP;
    const float* src = ego ? obs : ngb;
    float* gH = ego ? g_Hs : g_Hn;

    // emb t=0 into buf0
    if (tid < 128) {
        int row = row0 + tid;
        float x0 = 0.f, x1 = 0.f;
        if (row < nr) {
            const float* px = src + ((size_t)0 * nr + row) * 2;
            x0 = px[0]; x1 = px[1];
        }
        uint32_t base = sb + ABUF_OFF + (uint32_t)tid * RS;
#pragma unroll
        for (int m2 = 0; m2 < 16; m2++) {
            float e0 = lrelu(fmaf(wip_s[4 * m2 + 0], x0, fmaf(wip_s[4 * m2 + 1], x1, bip_s[2 * m2 + 0])));
            float e1 = lrelu(fmaf(wip_s[4 * m2 + 2], x0, fmaf(wip_s[4 * m2 + 3], x1, bip_s[2 * m2 + 1])));
            sts32(base + 4 * m2, pkh2(e0, e1));
        }
    }
    __syncthreads();

    const int gid = lane >> 2, tig = lane & 3;
    const int u0 = 8 * w + 2 * tig;
    const uint32_t ldmoff = (uint32_t)(((lane & 7) + ((lane >> 3) & 1) * 8) * RS + (lane >> 4) * 16);
    const float4 ba = bias4[u0], bb = bias4[u0 + 1];
    // half-scaled biases for sigmoid gates (pack 0.5*(z+b))
    const float hbax = 0.5f * ba.x, hbbx = 0.5f * bb.x;
    const float hbay = 0.5f * ba.y, hbby = 0.5f * bb.y;
    const float hbaw = 0.5f * ba.w, hbbw = 0.5f * bb.w;

    float c[8][2][2];
#pragma unroll
    for (int a = 0; a < 8; a++)
#pragma unroll
        for (int r = 0; r < 2; r++) { c[a][r][0] = 0.f; c[a][r][1] = 0.f; }

    int p = 0;
#pragma unroll 1
    for (int t = 0; t < T_OBS; t++) {
        const uint32_t Abase = sb + ABUF_OFF + (uint32_t)p * ABUF_SZ;
        const uint32_t Wbase = sb + ABUF_OFF + (uint32_t)(p ^ 1) * ABUF_SZ;
#pragma unroll
        for (int mq = 0; mq < 4; mq++) {
            float acc[2][4][4];
#pragma unroll
            for (int mt = 0; mt < 2; mt++)
#pragma unroll
                for (int q = 0; q < 4; q++)
#pragma unroll
                    for (int e = 0; e < 4; e++) acc[mt][q][e] = 0.f;
#pragma unroll
            for (int k = 0; k < 6; k++) {
                uint32_t ah[2][4];
#pragma unroll
                for (int mt = 0; mt < 2; mt++) {
                    uint32_t adr = Abase + (uint32_t)((mq * 32 + mt * 16) * RS + k * 32) + ldmoff;
                    LDM4(ah[mt], adr);
                }
#pragma unroll
                for (int q = 0; q < 4; q++) {
                    uint32_t baddr = sb + BH_OFF + (uint32_t)((q * 64 + 8 * w + gid) * RS + k * 32 + tig * 4);
                    uint32_t bh0 = lds32(baddr), bh1 = lds32(baddr + 16);
                    MMA(acc[0][q], ah[0], bh0, bh1);
                    MMA(acc[1][q], ah[1], bh0, bh1);
                }
            }
            // f16x2 activation + h write
#pragma unroll
            for (int mt = 0; mt < 2; mt++)
#pragma unroll
            for (int rr = 0; rr < 2; rr++) {
                int row = mq * 32 + mt * 16 + gid + rr * 8;
                int e0 = rr * 2, e1 = rr * 2 + 1;
                int ci = mq * 2 + mt;
                uint32_t pi = pkh2(fmaf(0.5f, acc[mt][0][e0], hbax), fmaf(0.5f, acc[mt][0][e1], hbbx));
                uint32_t pf = pkh2(fmaf(0.5f, acc[mt][1][e0], hbay), fmaf(0.5f, acc[mt][1][e1], hbby));
                uint32_t pg = pkh2(acc[mt][2][e0] + ba.z, acc[mt][2][e1] + bb.z);
                uint32_t po = pkh2(fmaf(0.5f, acc[mt][3][e0], hbaw), fmaf(0.5f, acc[mt][3][e1], hbbw));
                uint32_t si = sig2fin(tanh2(pi));
                uint32_t sf = sig2fin(tanh2(pf));
                uint32_t tg = tanh2(pg);
                uint32_t so = sig2fin(tanh2(po));
                float2 fi = uph2(si), ff = uph2(sf), fg = uph2(tg);
                float cn0 = fmaf(ff.x, c[ci][rr][0], fi.x * fg.x);
                float cn1 = fmaf(ff.y, c[ci][rr][1], fi.y * fg.y);
                c[ci][rr][0] = cn0; c[ci][rr][1] = cn1;
                uint32_t hh = hmul2(so, tanh2(pkh2(cn0, cn1)));
                if (t < T_OBS - 1) {
                    uint32_t ha = Wbase + (uint32_t)(row * RS + 64 + 2 * u0);
                    sts32(ha, hh);
                } else {
                    int grow = row0 + row;
                    if (grow < nr) {
                        float2 hv = uph2(hh);
                        *(float2*)(gH + (size_t)grow * 64 + u0) = hv;
                    }
                }
            }
        }
        // emb for t+1 into buf p^1
        if (t < T_OBS - 1 && tid < 128) {
            int row = row0 + tid;
            float x0 = 0.f, x1 = 0.f;
            if (row < nr) {
                const float* px = src + ((size_t)(t + 1) * nr + row) * 2;
                x0 = px[0]; x1 = px[1];
            }
            uint32_t base = Wbase + (uint32_t)tid * RS;
#pragma unroll
            for (int m2 = 0; m2 < 16; m2++) {
                float e0 = lrelu(fmaf(wip_s[4 * m2 + 0], x0, fmaf(wip_s[4 * m2 + 1], x1, bip_s[2 * m2 + 0])));
                float e1 = lrelu(fmaf(wip_s[4 * m2 + 2], x0, fmaf(wip_s[4 * m2 + 3], x1, bip_s[2 * m2 + 1])));
                sts32(base + 4 * m2, pkh2(e0, e1));
            }
        }
        __syncthreads();
        p ^= 1;
    }
}

// ============================================================================
// K2: social pipeline (unchanged).
// ============================================================================
#define SROW 68
#define K2_SMEM (53136 * 4)

extern "C" __global__ void __launch_bounds__(256, 1)
k_social(const int* __restrict__ masks_idxs, const int* __restrict__ obs_traj_idxs,
         const float* __restrict__ Wdyn, const float* __restrict__ bdyn,
         const float* __restrict__ bc1, const float* __restrict__ bc2) {
    extern __shared__ float sm[];
    float* S = sm;
    float* A = sm + 4352;
    float* W1T = sm + 6800;
    float* W2T = sm + 43664;
    float* Bv = sm + 52880;
    const int b = blockIdx.x, tid = threadIdx.x;
    const int lane = tid & 31, wrp = tid >> 5;

    {
        const float4* s4 = (const float4*)g_W1t;
        float4* d4 = (float4*)W1T;
        for (int i = tid; i < 9216; i += 256) d4[i] = s4[i];
        const float4* s2 = (const float4*)g_W2t;
        float4* d2 = (float4*)W2T;
        for (int i = tid; i < 2304; i += 256) d2[i] = s2[i];
    }
    for (int idx = tid; idx < 4096; idx += 256) {
        int i = idx & 63, pos = idx >> 6, x = pos >> 3, y = pos & 7;
        int r = masks_idxs[b * 64 + y * 8 + x];
        S[pos * SROW + i] = g_Hn[(size_t)r * 64 + i];
    }
    __syncthreads();

    {
        const int o = ((wrp >> 2) << 5) + lane;
        const int ws = wrp & 3;
        int xj[9], yj[9];
#pragma unroll
        for (int j = 0; j < 9; j++) {
            int pj = ws + 4 * j;
            xj[j] = pj / 6; yj[j] = pj - 6 * xj[j];
        }
        ull acc[9];
        float bbv = __ldg(bc1 + o);
#pragma unroll
        for (int j = 0; j < 9; j++) acc[j] = pk2(bbv, 0.f);
        const ull* W1u = (const ull*)W1T;
#pragma unroll 1
        for (int uv = 0; uv < 9; uv++) {
            int u = uv / 3, v = uv - 3 * u;
            int px[9];
#pragma unroll
            for (int j = 0; j < 9; j++) px[j] = (xj[j] + u) * 8 + (yj[j] + v);
#pragma unroll 1
            for (int cc = 0; cc < 4; cc++) {
                ull wr[8];
#pragma unroll
                for (int kk = 0; kk < 8; kk++)
                    wr[kk] = W1u[(uv * 32 + cc * 8 + kk) * 64 + o];
#pragma unroll
                for (int j = 0; j < 9; j++) {
                    const ulonglong2* sr = (const ulonglong2*)(S + px[j] * SROW) + cc * 4;
#pragma unroll
                    for (int k2 = 0; k2 < 4; k2++) {
                        ulonglong2 sv = sr[k2];
                        acc[j] = fma2(wr[2 * k2 + 0], sv.x, acc[j]);
                        acc[j] = fma2(wr[2 * k2 + 1], sv.y, acc[j]);
                    }
                }
            }
        }
#pragma unroll
        for (int j = 0; j < 9; j++)
            A[(ws + 4 * j) * SROW + o] = lrelu(psum(acc[j]));
    }
    __syncthreads();

    if (tid < 128) {
        const int w2 = tid >> 5;
        const int o = lane & 15;
        const int pg = w2 * 2 + (lane >> 4);
        const int pp0 = pg * 2, pp1 = pg * 2 + 1;
        const int x0 = pp0 >> 2, y0 = pp0 & 3;
        const int x1 = pp1 >> 2, y1 = pp1 & 3;
        float bbv = __ldg(bc2 + o);
        ull a0 = pk2(bbv, 0.f), a1 = pk2(bbv, 0.f);
        const ull* W2u = (const ull*)W2T;
#pragma unroll 1
        for (int uv = 0; uv < 9; uv++) {
            int u = uv / 3, v = uv - 3 * u;
            int pA0 = (x0 + u) * 6 + (y0 + v);
            int pA1 = (x1 + u) * 6 + (y1 + v);
#pragma unroll 1
            for (int cc = 0; cc < 4; cc++) {
                ull wr[8];
#pragma unroll
                for (int kk = 0; kk < 8; kk++)
                    wr[kk] = W2u[(uv * 32 + cc * 8 + kk) * 16 + o];
                const ulonglong2* r0 = (const ulonglong2*)(A + pA0 * SROW) + cc * 4;
                const ulonglong2* r1 = (const ulonglong2*)(A + pA1 * SROW) + cc * 4;
#pragma unroll
                for (int k2 = 0; k2 < 4; k2++) {
                    ulonglong2 v0 = r0[k2], v1 = r1[k2];
                    a0 = fma2(wr[2 * k2 + 0], v0.x, a0);
                    a0 = fma2(wr[2 * k2 + 1], v0.y, a0);
                    a1 = fma2(wr[2 * k2 + 0], v1.x, a1);
                    a1 = fma2(wr[2 * k2 + 1], v1.y, a1);
                }
            }
        }
        Bv[o * 16 + pp0] = lrelu(psum(a0));
        Bv[o * 16 + pp1] = lrelu(psum(a1));
    }
    __syncthreads();
    if (tid < 144) {
        int o = tid / 9, pp = tid - o * 9, x = pp / 3, y = pp - x * 3;
        float m0 = fmaxf(Bv[o * 16 + x * 4 + y], Bv[o * 16 + x * 4 + y + 1]);
        float m1 = fmaxf(Bv[o * 16 + (x + 1) * 4 + y], Bv[o * 16 + (x + 1) * 4 + y + 1]);
        g_enc[b * ENCD + DYND + tid] = fmaxf(m0, m1);
    } else if (tid >= 160 && tid < 192) {
        int d = tid - 160;
        int r = obs_traj_idxs[15 * NN + b];
        const float* hf = g_Hs + r * ENCH;
        float acc = bdyn[d];
#pragma unroll
        for (int k = 0; k < 64; k++) acc = fmaf(hf[k], Wdyn[d * 64 + k], acc);
        g_enc[b * ENCD + d] = lrelu(acc);
    }
}

// ============================================================================
// K3: decoder LSTM (unchanged from R14 — 73us).
// ============================================================================
#define D_W 0
#define D_ENC 32768
#define D_H 33120
#define D_WOP 33632
#define D_BOP 34272
#define K3_SMEM (34280 * 4)

extern "C" __global__ void __launch_bounds__(512, 1)
k_decoder(const float* __restrict__ Wih_d, const float* __restrict__ bih_d,
          const float* __restrict__ bhh_d,
          const float* __restrict__ Wop, const float* __restrict__ bop,
          float* __restrict__ out) {
    extern __shared__ float dsm[];
    float* enc_s = dsm + D_ENC;
    float* wop_s = dsm + D_WOP;
    float* bop_s = dsm + D_BOP;
    const int tid = threadIdx.x;
    const int b0 = blockIdx.x * 2;
    const int q = tid & 3, u = tid >> 2;
    const int g = q * 128 + u;

    {
        const float4* src4 = (const float4*)g_Whh4;
        float4* dst4 = (float4*)(dsm + D_W);
        for (int i = tid; i < 8192; i += 512) dst4[i] = src4[i];
    }
    for (int idx = tid; idx < 2 * ENCD; idx += 512)
        enc_s[idx] = g_enc[b0 * ENCD + idx];
    for (int idx = tid; idx < 640; idx += 512) wop_s[idx] = Wop[idx];
    if (tid < 5) bop_s[tid] = bop[tid];
    if (tid < 256) dsm[D_H + tid] = 0.f;

    ulonglong2 wreg[16];
#pragma unroll
    for (int k = 0; k < 16; k++)
        wreg[k] = ((const ulonglong2*)g_Whh4)[(16 + k) * 512 + tid];
    __syncthreads();

    float ez0, ez1;
    {
        float bbv = bih_d[g] + bhh_d[g];
        ez0 = bbv; ez1 = bbv;
        const float4* wr = (const float4*)(Wih_d + g * ENCD);
#pragma unroll 4
        for (int k4 = 0; k4 < 44; k4++) {
            float4 wv = wr[k4];
            ez0 = fmaf(wv.x, enc_s[4 * k4 + 0], fmaf(wv.y, enc_s[4 * k4 + 1],
                  fmaf(wv.z, enc_s[4 * k4 + 2], fmaf(wv.w, enc_s[4 * k4 + 3], ez0))));
            ez1 = fmaf(wv.x, enc_s[ENCD + 4 * k4 + 0], fmaf(wv.y, enc_s[ENCD + 4 * k4 + 1],
                  fmaf(wv.z, enc_s[ENCD + 4 * k4 + 2], fmaf(wv.w, enc_s[ENCD + 4 * k4 + 3], ez1))));
        }
    }

    float c0 = 0.f, c1 = 0.f;
    const bool q0b = (q & 1), q1b = (q & 2);

#pragma unroll 1
    for (int t = 0; t < T_PRED; t++) {
        const float* hr = dsm + D_H + (t & 1) * 256;
        float* hw = dsm + D_H + ((t & 1) ^ 1) * 256;
        ull a0 = pk2(ez0, 0.f), a1 = pk2(ez1, 0.f);
        {
            const ulonglong2* wsm = (const ulonglong2*)(dsm + D_W) + tid;
            const ulonglong2* h0p = (const ulonglong2*)hr;
            const ulonglong2* h1p = (const ulonglong2*)(hr + DECH);
#pragma unroll
            for (int k4 = 0; k4 < 16; k4++) {
                ulonglong2 wv = wsm[k4 * 512];
                ulonglong2 v0 = h0p[k4], v1 = h1p[k4];
                a0 = fma2(wv.x, v0.x, a0); a0 = fma2(wv.y, v0.y, a0);
                a1 = fma2(wv.x, v1.x, a1); a1 = fma2(wv.y, v1.y, a1);
            }
#pragma unroll
            for (int k = 0; k < 16; k++) {
                ulonglong2 wv = wreg[k];
                ulonglong2 v0 = h0p[16 + k], v1 = h1p[16 + k];
                a0 = fma2(wv.x, v0.x, a0); a0 = fma2(wv.y, v0.y, a0);
                a1 = fma2(wv.x, v1.x, a1); a1 = fma2(wv.y, v1.y, a1);
            }
        }
        float z0 = psum(a0), z1 = psum(a1);
        float xa0 = z0, xb0 = __shfl_xor_sync(0xffffffffu, z0, 1);
        float xc0 = __shfl_xor_sync(0xffffffffu, xa0, 2);
        float xd0 = __shfl_xor_sync(0xffffffffu, xb0, 2);
        float xa1 = z1, xb1 = __shfl_xor_sync(0xffffffffu, z1, 1);
        float xc1 = __shfl_xor_sync(0xffffffffu, xa1, 2);
        float xd1 = __shfl_xor_sync(0xffffffffu, xb1, 2);
        float zi0 = q1b ? (q0b ? xd0 : xc0) : (q0b ? xb0 : xa0);
        float zf0 = q1b ? (q0b ? xc0 : xd0) : (q0b ? xa0 : xb0);
        float zg0 = q1b ? (q0b ? xb0 : xa0) : (q0b ? xd0 : xc0);
        float zo0 = q1b ? (q0b ? xa0 : xb0) : (q0b ? xc0 : xd0);
        float zi1 = q1b ? (q0b ? xd1 : xc1) : (q0b ? xb1 : xa1);
        float zf1 = q1b ? (q0b ? xc1 : xd1) : (q0b ? xa1 : xb1);
        float zg1 = q1b ? (q0b ? xb1 : xa1) : (q0b ? xd1 : xc1);
        float zo1 = q1b ? (q0b ? xa1 : xb1) : (q0b ? xc1 : xd1);
        c0 = fmaf(sigf(zf0), c0, sigf(zi0) * tanha(zg0));
        c1 = fmaf(sigf(zf1), c1, sigf(zi1) * tanha(zg1));
        float h0 = sigf(zo0) * tanha(c0);
        float h1 = sigf(zo1) * tanha(c1);
        if (q == 0) { hw[u] = h0; hw[DECH + u] = h1; }
        __syncthreads();
        if (tid < 10) {
            int r = tid / 5, oi = tid - r * 5;
            float acc = bop_s[oi];
            const float* hh = hw + r * DECH;
#pragma unroll
            for (int k = 0; k < DECH; k++) acc = fmaf(hh[k], wop_s[oi * DECH + k], acc);
            float val = (oi < 2) ? acc : ((oi < 4) ? __expf(acc) : tanha(acc));
            out[((size_t)t * NN + (b0 + r)) * 5 + oi] = val;
        }
    }
}

extern "C" void kernel_launch(void* const* d_in, const int* in_sizes, int n_in,
                              void* d_out, int out_size) {
    const float* obs  = (const float*)d_in[0];
    const float* ngb  = (const float*)d_in[1];
    const int* masks_idxs    = (const int*)d_in[3];
    const int* obs_traj_idxs = (const int*)d_in[4];
    const float* Wip   = (const float*)d_in[7];
    const float* bip   = (const float*)d_in[8];
    const float* Wih_e = (const float*)d_in[9];
    const float* Whh_e = (const float*)d_in[10];
    const float* bih_e = (const float*)d_in[11];
    const float* bhh_e = (const float*)d_in[12];
    const float* Wdyn  = (const float*)d_in[13];
    const float* bdyn  = (const float*)d_in[14];
    const float* Wc1   = (const float*)d_in[15];
    const float* bc1   = (const float*)d_in[16];
    const float* Wc2   = (const float*)d_in[17];
    const float* bc2   = (const float*)d_in[18];
    const float* Wih_d = (const float*)d_in[19];
    const float* Whh_d = (const float*)d_in[20];
    const float* bih_d = (const float*)d_in[21];
    const float* bhh_d = (const float*)d_in[22];
    const float* Wop   = (const float*)d_in[23];
    const float* bop   = (const float*)d_in[24];

    cudaFuncSetAttribute(k_encoder, cudaFuncAttributeMaxDynamicSharedMemorySize, K1_SMEM);
    cudaFuncSetAttribute(k_social, cudaFuncAttributeMaxDynamicSharedMemorySize, K2_SMEM);
    cudaFuncSetAttribute(k_decoder, cudaFuncAttributeMaxDynamicSharedMemorySize, K3_SMEM);

    k_encoder<<<296, 256, K1_SMEM>>>(obs, ngb, Wip, bip, Wih_e, Whh_e, bih_e, bhh_e,
                                     Whh_d, Wc1, Wc2);
    k_social<<<192, 256, K2_SMEM>>>(masks_idxs, obs_traj_idxs, Wdyn, bdyn, bc1, bc2);
    k_decoder<<<96, 512, K3_SMEM>>>(Wih_d, bih_d, bhh_d, Wop, bop, (float*)d_out);
}

// round 16
// speedup vs baseline: 10.5037x; 1.0120x over previous
#include <cuda_runtime.h>
#include <cuda_bf16.h>
#include <cuda_fp16.h>
#include <cstdint>

#define T_OBS 16
#define T_PRED 25
#define NN 192
#define PP 36864
#define ENCH 64
#define DECH 128
#define DYND 32
#define ENCD 176   // DYN + SOC

typedef unsigned long long ull;

__device__ float g_Hn[(size_t)PP * ENCH];
__device__ float g_Hs[NN * ENCH];
__device__ float g_enc[NN * ENCD];
__device__ float g_Whh4[32 * 512 * 4];   // [k4][u*4+q][4]
__device__ float g_W1t[36864];           // [uv][i2][64 o] ull-packed
__device__ float g_W2t[9216];            // [uv][i2][16 o] ull-packed

__device__ __forceinline__ float lrelu(float x) { return fmaxf(x, 0.1f * x); }
__device__ __forceinline__ float tanha(float x) {
    float y; asm("tanh.approx.f32 %0,%1;" : "=f"(y) : "f"(x)); return y;
}
__device__ __forceinline__ float sigf(float x) { return fmaf(tanha(0.5f * x), 0.5f, 0.5f); }

__device__ __forceinline__ ull pk2(float lo, float hi) {
    ull r; asm("mov.b64 %0,{%1,%2};" : "=l"(r) : "f"(lo), "f"(hi)); return r;
}
__device__ __forceinline__ ull fma2(ull a, ull b, ull c) {
    ull d; asm("fma.rn.f32x2 %0,%1,%2,%3;" : "=l"(d) : "l"(a), "l"(b), "l"(c)); return d;
}
__device__ __forceinline__ float psum(ull v) {
    float a, b; asm("mov.b64 {%0,%1},%2;" : "=f"(a), "=f"(b) : "l"(v)); return a + b;
}
__device__ __forceinline__ uint32_t s2u(const void* p) {
    uint32_t a;
    asm("{ .reg .u64 t; cvta.to.shared.u64 t, %1; cvt.u32.u64 %0, t; }" : "=r"(a) : "l"(p));
    return a;
}
__device__ __forceinline__ void sts32(uint32_t a, uint32_t v) {
    asm volatile("st.shared.b32 [%0],%1;" :: "r"(a), "r"(v) : "memory");
}
// non-volatile paired load (B is immutable after init barrier -> hoistable)
__device__ __forceinline__ uint2 lds64nv(uint32_t a) {
    uint2 v; asm("ld.shared.v2.b32 {%0,%1},[%2];" : "=r"(v.x), "=r"(v.y) : "r"(a));
    return v;
}
__device__ __forceinline__ uint32_t pkh2(float lo, float hi) {
    uint32_t r; asm("cvt.rn.f16x2.f32 %0,%1,%2;" : "=r"(r) : "f"(hi), "f"(lo)); return r;
}
__device__ __forceinline__ uint32_t tanh2(uint32_t x) {
    uint32_t y; asm("tanh.approx.f16x2 %0,%1;" : "=r"(y) : "r"(x)); return y;
}
__device__ __forceinline__ uint32_t sig2fin(uint32_t t) {
    const uint32_t H05 = 0x38003800u;
    uint32_t r; asm("fma.rn.f16x2 %0,%1,%2,%2;" : "=r"(r) : "r"(t), "r"(H05)); return r;
}
__device__ __forceinline__ uint32_t hmul2(uint32_t a, uint32_t b) {
    uint32_t r; asm("mul.rn.f16x2 %0,%1,%2;" : "=r"(r) : "r"(a), "r"(b)); return r;
}
__device__ __forceinline__ float2 uph2(uint32_t v) {
    float2 f;
    asm("{.reg .f16 l,h; mov.b32 {l,h},%2; cvt.f32.f16 %0,l; cvt.f32.f16 %1,h;}"
        : "=f"(f.x), "=f"(f.y) : "r"(v));
    return f;
}

#define LDM4(r, adr) \
    asm volatile("ldmatrix.sync.aligned.m8n8.x4.shared.b16 {%0,%1,%2,%3}, [%4];" \
        : "=r"((r)[0]), "=r"((r)[1]), "=r"((r)[2]), "=r"((r)[3]) : "r"(adr))

#define MMA(c, a, b0, b1) \
    asm volatile("mma.sync.aligned.m16n8k16.row.col.f32.f16.f16.f32 " \
        "{%0,%1,%2,%3}, {%4,%5,%6,%7}, {%8,%9}, {%0,%1,%2,%3};" \
        : "+f"((c)[0]), "+f"((c)[1]), "+f"((c)[2]), "+f"((c)[3]) \
        : "r"((a)[0]), "r"((a)[1]), "r"((a)[2]), "r"((a)[3]), "r"(b0), "r"(b1))

// ============================================================================
// K1: encoder LSTM, mma.sync fp16 + f16x2 activations.
// B stored pre-paired: BP[k][n][tig] (8B = mma b-frag pair) -> 1 lds64/frag,
// warp-contiguous 256B spans (2 wf, conflict-free), non-volatile (hoistable).
// Grid 296: 0..287 neighbor, 288..289 ego, 290..295 folded weight-prep.
// ============================================================================
#define RS 208
#define BP_OFF 0          // 6*256*32 = 49152
#define ABUF_OFF 49152
#define ABUF_SZ 26624
#define BIAS_OFF 102400
#define WIP_OFF 103424
#define BIP_OFF 103680
#define K1_SMEM 103808

extern "C" __global__ void __launch_bounds__(256, 2)
k_encoder(const float* __restrict__ obs, const float* __restrict__ ngb,
          const float* __restrict__ Wip, const float* __restrict__ bip,
          const float* __restrict__ Wih, const float* __restrict__ Whh,
          const float* __restrict__ bih, const float* __restrict__ bhh,
          const float* __restrict__ Whh_d, const float* __restrict__ Wc1,
          const float* __restrict__ Wc2) {
    const int tid = threadIdx.x;
    const int bx = blockIdx.x;

    if (bx >= 290) {   // folded prep: weight transposes for K2/K3
        for (int idx = (bx - 290) * 256 + tid; idx < 111616; idx += 1536) {
            if (idx < 65536) {
                int g = idx >> 7, k = idx & 127;
                int cg = g >> 7, uu = g & 127;
                int t = uu * 4 + cg;
                g_Whh4[(k >> 2) * 2048 + t * 4 + (k & 3)] = Whh_d[idx];
            } else if (idx < 102400) {
                int g2 = idx - 65536;
                int o = g2 / 576, rem = g2 - o * 576, i = rem / 9, uv = rem - i * 9;
                g_W1t[((uv * 32 + (i >> 1)) * 64 + o) * 2 + (i & 1)] = Wc1[g2];
            } else {
                int g2 = idx - 102400;
                int o = g2 / 576, rem = g2 - o * 576, i = rem / 9, uv = rem - i * 9;
                g_W2t[((uv * 32 + (i >> 1)) * 16 + o) * 2 + (i & 1)] = Wc2[g2];
            }
        }
        return;
    }

    extern __shared__ __align__(16) char smb[];
    const int lane = tid & 31, w = tid >> 5;
    const uint32_t sb = s2u(smb);
    float4* bias4 = (float4*)(smb + BIAS_OFF);
    float* wip_s = (float*)(smb + WIP_OFF);
    float* bip_s = (float*)(smb + BIP_OFF);

    // stage B pre-paired: n = gate*64+unit, k in [0,96); chunk=k>>4, ki=k&15
    // tig=(ki&7)>>1, slot=(ki>>3)*2+(ki&1); addr=chunk*8192 + n*32 + tig*8 + slot*2
    for (int idx = tid; idx < 24576; idx += 256) {
        int n = idx / 96, k = idx - n * 96;
        float wv = (k < 32) ? Wih[n * 32 + k] : Whh[n * 64 + (k - 32)];
        int chunk = k >> 4, ki = k & 15;
        int tg = (ki & 7) >> 1, slot = ((ki >> 3) << 1) + (ki & 1);
        *(__half*)(smb + BP_OFF + chunk * 8192 + n * 32 + tg * 8 + slot * 2) = __float2half_rn(wv);
    }
    for (int i = tid; i < ABUF_SZ / 4; i += 256)
        *(uint32_t*)(smb + ABUF_OFF + 4 * i) = 0;
    if (tid < 64) {
        bias4[tid] = make_float4(bih[tid] + bhh[tid], bih[64 + tid] + bhh[64 + tid],
                                 bih[128 + tid] + bhh[128 + tid], bih[192 + tid] + bhh[192 + tid]);
        wip_s[tid] = Wip[tid];
    }
    if (tid < 32) bip_s[tid] = bip[tid];
    __syncthreads();

    const bool ego = (bx >= 288);
    const int row0 = ego ? (bx - 288) * 128 : bx * 128;
    const int nr = ego ? NN : PP;
    const float* src = ego ? obs : ngb;
    float* gH = ego ? g_Hs : g_Hn;

    if (tid < 128) {   // emb t=0
        int row = row0 + tid;
        float x0 = 0.f, x1 = 0.f;
        if (row < nr) {
            const float* px = src + ((size_t)0 * nr + row) * 2;
            x0 = px[0]; x1 = px[1];
        }
        uint32_t base = sb + ABUF_OFF + (uint32_t)tid * RS;
#pragma unroll
        for (int m2 = 0; m2 < 16; m2++) {
            float e0 = lrelu(fmaf(wip_s[4 * m2 + 0], x0, fmaf(wip_s[4 * m2 + 1], x1, bip_s[2 * m2 + 0])));
            float e1 = lrelu(fmaf(wip_s[4 * m2 + 2], x0, fmaf(wip_s[4 * m2 + 3], x1, bip_s[2 * m2 + 1])));
            sts32(base + 4 * m2, pkh2(e0, e1));
        }
    }
    __syncthreads();

    const int gid = lane >> 2, tig = lane & 3;
    const int u0 = 8 * w + 2 * tig;
    const uint32_t ldmoff = (uint32_t)(((lane & 7) + ((lane >> 3) & 1) * 8) * RS + (lane >> 4) * 16);
    // per-(k,q) B address base for this thread
    const uint32_t bbase = sb + BP_OFF + (uint32_t)((8 * w + gid) * 32 + tig * 8);
    const float4 ba = bias4[u0], bb = bias4[u0 + 1];
    const float hbax = 0.5f * ba.x, hbbx = 0.5f * bb.x;
    const float hbay = 0.5f * ba.y, hbby = 0.5f * bb.y;
    const float hbaw = 0.5f * ba.w, hbbw = 0.5f * bb.w;

    float c[8][2][2];
#pragma unroll
    for (int a = 0; a < 8; a++)
#pragma unroll
        for (int r = 0; r < 2; r++) { c[a][r][0] = 0.f; c[a][r][1] = 0.f; }

    int p = 0;
#pragma unroll 1
    for (int t = 0; t < T_OBS; t++) {
        const uint32_t Abase = sb + ABUF_OFF + (uint32_t)p * ABUF_SZ;
        const uint32_t Wbase = sb + ABUF_OFF + (uint32_t)(p ^ 1) * ABUF_SZ;
#pragma unroll
        for (int mq = 0; mq < 4; mq++) {
            float acc[2][4][4];
#pragma unroll
            for (int mt = 0; mt < 2; mt++)
#pragma unroll
                for (int q = 0; q < 4; q++)
#pragma unroll
                    for (int e = 0; e < 4; e++) acc[mt][q][e] = 0.f;
#pragma unroll
            for (int k = 0; k < 6; k++) {
                uint32_t ah[2][4];
#pragma unroll
                for (int mt = 0; mt < 2; mt++) {
                    uint32_t adr = Abase + (uint32_t)((mq * 32 + mt * 16) * RS + k * 32) + ldmoff;
                    LDM4(ah[mt], adr);
                }
#pragma unroll
                for (int q = 0; q < 4; q++) {
                    uint2 bp = lds64nv(bbase + (uint32_t)(k * 8192 + q * 2048));
                    MMA(acc[0][q], ah[0], bp.x, bp.y);
                    MMA(acc[1][q], ah[1], bp.x, bp.y);
                }
            }
#pragma unroll
            for (int mt = 0; mt < 2; mt++)
#pragma unroll
            for (int rr = 0; rr < 2; rr++) {
                int row = mq * 32 + mt * 16 + gid + rr * 8;
                int e0 = rr * 2, e1 = rr * 2 + 1;
                int ci = mq * 2 + mt;
                uint32_t pi = pkh2(fmaf(0.5f, acc[mt][0][e0], hbax), fmaf(0.5f, acc[mt][0][e1], hbbx));
                uint32_t pf = pkh2(fmaf(0.5f, acc[mt][1][e0], hbay), fmaf(0.5f, acc[mt][1][e1], hbby));
                uint32_t pg = pkh2(acc[mt][2][e0] + ba.z, acc[mt][2][e1] + bb.z);
                uint32_t po = pkh2(fmaf(0.5f, acc[mt][3][e0], hbaw), fmaf(0.5f, acc[mt][3][e1], hbbw));
                uint32_t si = sig2fin(tanh2(pi));
                uint32_t sf = sig2fin(tanh2(pf));
                uint32_t tg2 = tanh2(pg);
                uint32_t so = sig2fin(tanh2(po));
                float2 fi = uph2(si), ff = uph2(sf), fg = uph2(tg2);
                float cn0 = fmaf(ff.x, c[ci][rr][0], fi.x * fg.x);
                float cn1 = fmaf(ff.y, c[ci][rr][1], fi.y * fg.y);
                c[ci][rr][0] = cn0; c[ci][rr][1] = cn1;
                uint32_t hh = hmul2(so, tanh2(pkh2(cn0, cn1)));
                if (t < T_OBS - 1) {
                    sts32(Wbase + (uint32_t)(row * RS + 64 + 2 * u0), hh);
                } else {
                    int grow = row0 + row;
                    if (grow < nr) {
                        float2 hv = uph2(hh);
                        *(float2*)(gH + (size_t)grow * 64 + u0) = hv;
                    }
                }
            }
        }
        if (t < T_OBS - 1 && tid < 128) {   // emb t+1
            int row = row0 + tid;
            float x0 = 0.f, x1 = 0.f;
            if (row < nr) {
                const float* px = src + ((size_t)(t + 1) * nr + row) * 2;
                x0 = px[0]; x1 = px[1];
            }
            uint32_t base = Wbase + (uint32_t)tid * RS;
#pragma unroll
            for (int m2 = 0; m2 < 16; m2++) {
                float e0 = lrelu(fmaf(wip_s[4 * m2 + 0], x0, fmaf(wip_s[4 * m2 + 1], x1, bip_s[2 * m2 + 0])));
                float e1 = lrelu(fmaf(wip_s[4 * m2 + 2], x0, fmaf(wip_s[4 * m2 + 3], x1, bip_s[2 * m2 + 1])));
                sts32(base + 4 * m2, pkh2(e0, e1));
            }
        }
        __syncthreads();
        p ^= 1;
    }
}

// ============================================================================
// K2: social pipeline (unchanged).
// ============================================================================
#define SROW 68
#define K2_SMEM (53136 * 4)

extern "C" __global__ void __launch_bounds__(256, 1)
k_social(const int* __restrict__ masks_idxs, const int* __restrict__ obs_traj_idxs,
         const float* __restrict__ Wdyn, const float* __restrict__ bdyn,
         const float* __restrict__ bc1, const float* __restrict__ bc2) {
    extern __shared__ float sm[];
    float* S = sm;
    float* A = sm + 4352;
    float* W1T = sm + 6800;
    float* W2T = sm + 43664;
    float* Bv = sm + 52880;
    const int b = blockIdx.x, tid = threadIdx.x;
    const int lane = tid & 31, wrp = tid >> 5;

    {
        const float4* s4 = (const float4*)g_W1t;
        float4* d4 = (float4*)W1T;
        for (int i = tid; i < 9216; i += 256) d4[i] = s4[i];
        const float4* s2 = (const float4*)g_W2t;
        float4* d2 = (float4*)W2T;
        for (int i = tid; i < 2304; i += 256) d2[i] = s2[i];
    }
    for (int idx = tid; idx < 4096; idx += 256) {
        int i = idx & 63, pos = idx >> 6, x = pos >> 3, y = pos & 7;
        int r = masks_idxs[b * 64 + y * 8 + x];
        S[pos * SROW + i] = g_Hn[(size_t)r * 64 + i];
    }
    __syncthreads();

    {
        const int o = ((wrp >> 2) << 5) + lane;
        const int ws = wrp & 3;
        int xj[9], yj[9];
#pragma unroll
        for (int j = 0; j < 9; j++) {
            int pj = ws + 4 * j;
            xj[j] = pj / 6; yj[j] = pj - 6 * xj[j];
        }
        ull acc[9];
        float bbv = __ldg(bc1 + o);
#pragma unroll
        for (int j = 0; j < 9; j++) acc[j] = pk2(bbv, 0.f);
        const ull* W1u = (const ull*)W1T;
#pragma unroll 1
        for (int uv = 0; uv < 9; uv++) {
            int u = uv / 3, v = uv - 3 * u;
            int px[9];
#pragma unroll
            for (int j = 0; j < 9; j++) px[j] = (xj[j] + u) * 8 + (yj[j] + v);
#pragma unroll 1
            for (int cc = 0; cc < 4; cc++) {
                ull wr[8];
#pragma unroll
                for (int kk = 0; kk < 8; kk++)
                    wr[kk] = W1u[(uv * 32 + cc * 8 + kk) * 64 + o];
#pragma unroll
                for (int j = 0; j < 9; j++) {
                    const ulonglong2* sr = (const ulonglong2*)(S + px[j] * SROW) + cc * 4;
#pragma unroll
                    for (int k2 = 0; k2 < 4; k2++) {
                        ulonglong2 sv = sr[k2];
                        acc[j] = fma2(wr[2 * k2 + 0], sv.x, acc[j]);
                        acc[j] = fma2(wr[2 * k2 + 1], sv.y, acc[j]);
                    }
                }
            }
        }
#pragma unroll
        for (int j = 0; j < 9; j++)
            A[(ws + 4 * j) * SROW + o] = lrelu(psum(acc[j]));
    }
    __syncthreads();

    if (tid < 128) {
        const int w2 = tid >> 5;
        const int o = lane & 15;
        const int pg = w2 * 2 + (lane >> 4);
        const int pp0 = pg * 2, pp1 = pg * 2 + 1;
        const int x0 = pp0 >> 2, y0 = pp0 & 3;
        const int x1 = pp1 >> 2, y1 = pp1 & 3;
        float bbv = __ldg(bc2 + o);
        ull a0 = pk2(bbv, 0.f), a1 = pk2(bbv, 0.f);
        const ull* W2u = (const ull*)W2T;
#pragma unroll 1
        for (int uv = 0; uv < 9; uv++) {
            int u = uv / 3, v = uv - 3 * u;
            int pA0 = (x0 + u) * 6 + (y0 + v);
            int pA1 = (x1 + u) * 6 + (y1 + v);
#pragma unroll 1
            for (int cc = 0; cc < 4; cc++) {
                ull wr[8];
#pragma unroll
                for (int kk = 0; kk < 8; kk++)
                    wr[kk] = W2u[(uv * 32 + cc * 8 + kk) * 16 + o];
                const ulonglong2* r0 = (const ulonglong2*)(A + pA0 * SROW) + cc * 4;
                const ulonglong2* r1 = (const ulonglong2*)(A + pA1 * SROW) + cc * 4;
#pragma unroll
                for (int k2 = 0; k2 < 4; k2++) {
                    ulonglong2 v0 = r0[k2], v1 = r1[k2];
                    a0 = fma2(wr[2 * k2 + 0], v0.x, a0);
                    a0 = fma2(wr[2 * k2 + 1], v0.y, a0);
                    a1 = fma2(wr[2 * k2 + 0], v1.x, a1);
                    a1 = fma2(wr[2 * k2 + 1], v1.y, a1);
                }
            }
        }
        Bv[o * 16 + pp0] = lrelu(psum(a0));
        Bv[o * 16 + pp1] = lrelu(psum(a1));
    }
    __syncthreads();
    if (tid < 144) {
        int o = tid / 9, pp = tid - o * 9, x = pp / 3, y = pp - x * 3;
        float m0 = fmaxf(Bv[o * 16 + x * 4 + y], Bv[o * 16 + x * 4 + y + 1]);
        float m1 = fmaxf(Bv[o * 16 + (x + 1) * 4 + y], Bv[o * 16 + (x + 1) * 4 + y + 1]);
        g_enc[b * ENCD + DYND + tid] = fmaxf(m0, m1);
    } else if (tid >= 160 && tid < 192) {
        int d = tid - 160;
        int r = obs_traj_idxs[15 * NN + b];
        const float* hf = g_Hs + r * ENCH;
        float acc = bdyn[d];
#pragma unroll
        for (int k = 0; k < 64; k++) acc = fmaf(hf[k], Wdyn[d * 64 + k], acc);
        g_enc[b * ENCD + d] = lrelu(acc);
    }
}

// ============================================================================
// K3: decoder LSTM. 96 blocks x 2 rows, 512 threads.
// h history in smem; ALL output projections post-loop (no per-step tail).
// ============================================================================
#define D_W 0        // 32768 floats
#define D_ENC 32768  // 352
#define D_H 33120    // 512
#define D_WOP 33632  // 640
#define D_BOP 34272  // 8
#define D_HIST 34280 // 25*256 = 6400
#define K3_SMEM (40680 * 4)

extern "C" __global__ void __launch_bounds__(512, 1)
k_decoder(const float* __restrict__ Wih_d, const float* __restrict__ bih_d,
          const float* __restrict__ bhh_d,
          const float* __restrict__ Wop, const float* __restrict__ bop,
          float* __restrict__ out) {
    extern __shared__ float dsm[];
    float* enc_s = dsm + D_ENC;
    float* wop_s = dsm + D_WOP;
    float* bop_s = dsm + D_BOP;
    float* hist = dsm + D_HIST;
    const int tid = threadIdx.x;
    const int b0 = blockIdx.x * 2;
    const int q = tid & 3, u = tid >> 2;
    const int g = q * 128 + u;

    {
        const float4* src4 = (const float4*)g_Whh4;
        float4* dst4 = (float4*)(dsm + D_W);
        for (int i = tid; i < 8192; i += 512) dst4[i] = src4[i];
    }
    for (int idx = tid; idx < 2 * ENCD; idx += 512)
        enc_s[idx] = g_enc[b0 * ENCD + idx];
    for (int idx = tid; idx < 640; idx += 512) wop_s[idx] = Wop[idx];
    if (tid < 5) bop_s[tid] = bop[tid];
    if (tid < 256) dsm[D_H + tid] = 0.f;

    ulonglong2 wreg[16];
#pragma unroll
    for (int k = 0; k < 16; k++)
        wreg[k] = ((const ulonglong2*)g_Whh4)[(16 + k) * 512 + tid];
    __syncthreads();

    float ez0, ez1;
    {
        float bbv = bih_d[g] + bhh_d[g];
        ez0 = bbv; ez1 = bbv;
        const float4* wr = (const float4*)(Wih_d + g * ENCD);
#pragma unroll 4
        for (int k4 = 0; k4 < 44; k4++) {
            float4 wv = wr[k4];
            ez0 = fmaf(wv.x, enc_s[4 * k4 + 0], fmaf(wv.y, enc_s[4 * k4 + 1],
                  fmaf(wv.z, enc_s[4 * k4 + 2], fmaf(wv.w, enc_s[4 * k4 + 3], ez0))));
            ez1 = fmaf(wv.x, enc_s[ENCD + 4 * k4 + 0], fmaf(wv.y, enc_s[ENCD + 4 * k4 + 1],
                  fmaf(wv.z, enc_s[ENCD + 4 * k4 + 2], fmaf(wv.w, enc_s[ENCD + 4 * k4 + 3], ez1))));
        }
    }

    float c0 = 0.f, c1 = 0.f;
    const bool q0b = (q & 1), q1b = (q & 2);

#pragma unroll 1
    for (int t = 0; t < T_PRED; t++) {
        const float* hr = dsm + D_H + (t & 1) * 256;
        float* hw = dsm + D_H + ((t & 1) ^ 1) * 256;
        ull a0 = pk2(ez0, 0.f), a1 = pk2(ez1, 0.f);
        {
            const ulonglong2* wsm = (const ulonglong2*)(dsm + D_W) + tid;
            const ulonglong2* h0p = (const ulonglong2*)hr;
            const ulonglong2* h1p = (const ulonglong2*)(hr + DECH);
#pragma unroll
            for (int k4 = 0; k4 < 16; k4++) {
                ulonglong2 wv = wsm[k4 * 512];
                ulonglong2 v0 = h0p[k4], v1 = h1p[k4];
                a0 = fma2(wv.x, v0.x, a0); a0 = fma2(wv.y, v0.y, a0);
                a1 = fma2(wv.x, v1.x, a1); a1 = fma2(wv.y, v1.y, a1);
            }
#pragma unroll
            for (int k = 0; k < 16; k++) {
                ulonglong2 wv = wreg[k];
                ulonglong2 v0 = h0p[16 + k], v1 = h1p[16 + k];
                a0 = fma2(wv.x, v0.x, a0); a0 = fma2(wv.y, v0.y, a0);
                a1 = fma2(wv.x, v1.x, a1); a1 = fma2(wv.y, v1.y, a1);
            }
        }
        float z0 = psum(a0), z1 = psum(a1);
        float xa0 = z0, xb0 = __shfl_xor_sync(0xffffffffu, z0, 1);
        float xc0 = __shfl_xor_sync(0xffffffffu, xa0, 2);
        float xd0 = __shfl_xor_sync(0xffffffffu, xb0, 2);
        float xa1 = z1, xb1 = __shfl_xor_sync(0xffffffffu, z1, 1);
        float xc1 = __shfl_xor_sync(0xffffffffu, xa1, 2);
        float xd1 = __shfl_xor_sync(0xffffffffu, xb1, 2);
        float zi0 = q1b ? (q0b ? xd0 : xc0) : (q0b ? xb0 : xa0);
        float zf0 = q1b ? (q0b ? xc0 : xd0) : (q0b ? xa0 : xb0);
        float zg0 = q1b ? (q0b ? xb0 : xa0) : (q0b ? xd0 : xc0);
        float zo0 = q1b ? (q0b ? xa0 : xb0) : (q0b ? xc0 : xd0);
        float zi1 = q1b ? (q0b ? xd1 : xc1) : (q0b ? xb1 : xa1);
        float zf1 = q1b ? (q0b ? xc1 : xd1) : (q0b ? xa1 : xb1);
        float zg1 = q1b ? (q0b ? xb1 : xa1) : (q0b ? xd1 : xc1);
        float zo1 = q1b ? (q0b ? xa1 : xb1) : (q0b ? xc1 : xd1);
        c0 = fmaf(sigf(zf0), c0, sigf(zi0) * tanha(zg0));
        c1 = fmaf(sigf(zf1), c1, sigf(zi1) * tanha(zg1));
        float h0 = sigf(zo0) * tanha(c0);
        float h1 = sigf(zo1) * tanha(c1);
        if (q == 0) {
            hw[u] = h0; hw[DECH + u] = h1;
            hist[t * 256 + u] = h0; hist[t * 256 + DECH + u] = h1;
        }
        __syncthreads();
    }
    // all 250 output projections in parallel
    if (tid < 250) {
        int t = tid / 10, j = tid - t * 10;
        int r = j / 5, oi = j - r * 5;
        float acc = bop_s[oi];
        const float* hh = hist + t * 256 + r * DECH;
        const float* ww = wop_s + oi * DECH;
#pragma unroll 4
        for (int k = 0; k < DECH; k++) acc = fmaf(hh[k], ww[k], acc);
        float val = (oi < 2) ? acc : ((oi < 4) ? __expf(acc) : tanha(acc));
        out[((size_t)t * NN + (b0 + r)) * 5 + oi] = val;
    }
    if (tid >= 250 && tid < 500) {
        int task = tid - 250 + 250;   // tasks 250..499 -> t 25.. none (guard)
        (void)task;
    }
}

extern "C" void kernel_launch(void* const* d_in, const int* in_sizes, int n_in,
                              void* d_out, int out_size) {
    const float* obs  = (const float*)d_in[0];
    const float* ngb  = (const float*)d_in[1];
    const int* masks_idxs    = (const int*)d_in[3];
    const int* obs_traj_idxs = (const int*)d_in[4];
    const float* Wip   = (const float*)d_in[7];
    const float* bip   = (const float*)d_in[8];
    const float* Wih_e = (const float*)d_in[9];
    const float* Whh_e = (const float*)d_in[10];
    const float* bih_e = (const float*)d_in[11];
    const float* bhh_e = (const float*)d_in[12];
    const float* Wdyn  = (const float*)d_in[13];
    const float* bdyn  = (const float*)d_in[14];
    const float* Wc1   = (const float*)d_in[15];
    const float* bc1   = (const float*)d_in[16];
    const float* Wc2   = (const float*)d_in[17];
    const float* bc2   = (const float*)d_in[18];
    const float* Wih_d = (const float*)d_in[19];
    const float* Whh_d = (const float*)d_in[20];
    const float* bih_d = (const float*)d_in[21];
    const float* bhh_d = (const float*)d_in[22];
    const float* Wop   = (const float*)d_in[23];
    const float* bop   = (const float*)d_in[24];

    cudaFuncSetAttribute(k_encoder, cudaFuncAttributeMaxDynamicSharedMemorySize, K1_SMEM);
    cudaFuncSetAttribute(k_social, cudaFuncAttributeMaxDynamicSharedMemorySize, K2_SMEM);
    cudaFuncSetAttribute(k_decoder, cudaFuncAttributeMaxDynamicSharedMemorySize, K3_SMEM);

    k_encoder<<<296, 256, K1_SMEM>>>(obs, ngb, Wip, bip, Wih_e, Whh_e, bih_e, bhh_e,
                                     Whh_d, Wc1, Wc2);
    k_social<<<192, 256, K2_SMEM>>>(masks_idxs, obs_traj_idxs, Wdyn, bdyn, bc1, bc2);
    k_decoder<<<96, 512, K3_SMEM>>>(Wih_d, bih_d, bhh_d, Wop, bop, (float*)d_out);
}